// round 6
// baseline (speedup 1.0000x reference)
#include <cuda_runtime.h>
#include <cuda_bf16.h>
#include <math.h>
#include <stdint.h>

// ---------------------------------------------------------------------------
// Problem constants
// ---------------------------------------------------------------------------
#define CC     768
#define C3     2304
#define NH     12
#define HD     64
#define HIDDEN 3072
#define TT     8
#define HW     196
#define BB     4
#define NTOK   1569
#define MT     6272
#define MS     6304
#define MX     6276
#define SL     197
#define SB     32
#define ZB     (SB*NH)
#define SL2    (SL*SL)

// ---------------------------------------------------------------------------
// Static device scratch
// ---------------------------------------------------------------------------
__device__ float g_qkv [(size_t)MS * C3];
__device__ float g_xt  [(size_t)MT * CC];
__device__ float g_sc  [(size_t)ZB * SL2];
__device__ float g_proj[(size_t)MS * CC];

__device__ __nv_bfloat16 g_ln_h[(size_t)MS * CC];
__device__ __nv_bfloat16 g_ln_l[(size_t)MS * CC];
__device__ __nv_bfloat16 g_at_h[(size_t)MS * CC];
__device__ __nv_bfloat16 g_at_l[(size_t)MS * CC];
__device__ __nv_bfloat16 g_pj_h[(size_t)MT * CC];
__device__ __nv_bfloat16 g_pj_l[(size_t)MT * CC];
__device__ __nv_bfloat16 g_f1_h[(size_t)MX * HIDDEN];
__device__ __nv_bfloat16 g_f1_l[(size_t)MX * HIDDEN];

__device__ __nv_bfloat16 g_wtq_h[(size_t)C3 * CC],     g_wtq_l[(size_t)C3 * CC];
__device__ __nv_bfloat16 g_wtp_h[(size_t)CC * CC],     g_wtp_l[(size_t)CC * CC];
__device__ __nv_bfloat16 g_wtf_h[(size_t)CC * CC],     g_wtf_l[(size_t)CC * CC];
__device__ __nv_bfloat16 g_wsq_h[(size_t)C3 * CC],     g_wsq_l[(size_t)C3 * CC];
__device__ __nv_bfloat16 g_wsp_h[(size_t)CC * CC],     g_wsp_l[(size_t)CC * CC];
__device__ __nv_bfloat16 g_wf1_h[(size_t)HIDDEN * CC], g_wf1_l[(size_t)HIDDEN * CC];
__device__ __nv_bfloat16 g_wf2_h[(size_t)CC * HIDDEN], g_wf2_l[(size_t)CC * HIDDEN];

// ---------------------------------------------------------------------------
// Helpers
// ---------------------------------------------------------------------------
__device__ __forceinline__ float gelu_exact(float v) {
    return 0.5f * v * (1.0f + erff(v * 0.7071067811865475f));
}

__device__ __forceinline__ void f2hl(float x, __nv_bfloat16& h, __nv_bfloat16& l) {
    h = __float2bfloat16(x);
    l = __float2bfloat16(x - __bfloat162float(h));
}

__device__ __forceinline__ uint32_t smem_u32(const void* p) {
    uint32_t a;
    asm("{ .reg .u64 t; cvta.to.shared.u64 t, %1; cvt.u32.u64 %0, t; }" : "=r"(a) : "l"(p));
    return a;
}

__device__ __forceinline__ void cpasync16(uint32_t dst, const void* src) {
    asm volatile("cp.async.cg.shared.global [%0], [%1], 16;" :: "r"(dst), "l"(src));
}
#define CP_COMMIT() asm volatile("cp.async.commit_group;" ::: "memory")
#define CP_WAIT0()  asm volatile("cp.async.wait_group 0;" ::: "memory")

__device__ __forceinline__ void ldm4(uint32_t* r, uint32_t addr) {
    asm volatile("ldmatrix.sync.aligned.m8n8.x4.shared.b16 {%0,%1,%2,%3}, [%4];"
                 : "=r"(r[0]), "=r"(r[1]), "=r"(r[2]), "=r"(r[3]) : "r"(addr));
}

__device__ __forceinline__ void mma16816(float* d, const uint32_t* a, const uint32_t* b) {
    asm volatile(
        "mma.sync.aligned.m16n8k16.row.col.f32.bf16.bf16.f32 "
        "{%0,%1,%2,%3}, {%4,%5,%6,%7}, {%8,%9}, {%0,%1,%2,%3};"
        : "+f"(d[0]), "+f"(d[1]), "+f"(d[2]), "+f"(d[3])
        : "r"(a[0]), "r"(a[1]), "r"(a[2]), "r"(a[3]), "r"(b[0]), "r"(b[1]));
}

// ---------------------------------------------------------------------------
// Split-bf16 HMMA NT GEMM, CTA tile 128(M) x 256(N), k-step 32, 8 warps,
// warp tile 64x64, double-buffered cp.async.
//   C[M,N] = A[M,K]*B[N,K]^T + bias (+epilogue); 3 chains Ah*Bh+Ah*Bl+Al*Bh.
// Requirements: N % 256 == 0, K % 32 == 0.
//   EPI 0: +bias   1: gelu(+bias)   2: +bias+resid(skip-cls)   3: +bias+C
//   OUT 0: fp32 C  1: hi/lo bf16 arrays (Ch, Cl)
// smem/stage: Ah,Al 128x80B; Bh,Bl 256x80B = 61440 B; x2 stages = 122880 B.
// ---------------------------------------------------------------------------
#define STG    61440u
#define OFF_AH 0u
#define OFF_AL 10240u
#define OFF_BH 20480u
#define OFF_BL 40960u
#define GEMM_SMEM (2 * STG)

template<int EPI, int OUT>
__global__ void __launch_bounds__(256)
gemm_mma(const __nv_bfloat16* __restrict__ Ahg, const __nv_bfloat16* __restrict__ Alg,
         const __nv_bfloat16* __restrict__ Bhg, const __nv_bfloat16* __restrict__ Blg,
         const float* __restrict__ bias,
         float* __restrict__ C,
         __nv_bfloat16* __restrict__ Ch, __nv_bfloat16* __restrict__ Cl,
         const float* __restrict__ resid,
         int M, int N, int K)
{
    extern __shared__ char smem[];
    const uint32_t sb = smem_u32(smem);

    const int tid  = threadIdx.x;
    const int wid  = tid >> 5;
    const int lane = tid & 31;
    const int row0 = blockIdx.y * 128;
    const int col0 = blockIdx.x * 256;
    const int KT   = K >> 5;

    float acc[4][8][4];
    #pragma unroll
    for (int a = 0; a < 4; a++)
        #pragma unroll
        for (int b = 0; b < 8; b++)
            #pragma unroll
            for (int c = 0; c < 4; c++) acc[a][b][c] = 0.0f;

    auto load_stage = [&](int kt, int buf) {
        const int kw = kt * 32;
        const uint32_t dstb = sb + buf * STG;
        // A: 128 rows x 64B, hi+lo = 1024 16B-chunks
        #pragma unroll
        for (int q = 0; q < 4; q++) {
            int cid = q * 256 + tid;
            int arr = cid >> 9;
            int idx = cid & 511;
            int row = idx >> 2, ch = idx & 3;
            int ar  = min(row0 + row, M - 1);
            const __nv_bfloat16* src = (arr ? Alg : Ahg) + (size_t)ar * K + kw + ch * 8;
            cpasync16(dstb + (arr ? OFF_AL : OFF_AH) + row * 80u + ch * 16u, src);
        }
        // B: 256 rows x 64B, hi+lo = 2048 16B-chunks
        #pragma unroll
        for (int q = 0; q < 8; q++) {
            int cid = q * 256 + tid;
            int arr = cid >> 10;
            int idx = cid & 1023;
            int row = idx >> 2, ch = idx & 3;
            const __nv_bfloat16* src = (arr ? Blg : Bhg) + (size_t)(col0 + row) * K + kw + ch * 8;
            cpasync16(dstb + (arr ? OFF_BL : OFF_BH) + row * 80u + ch * 16u, src);
        }
        CP_COMMIT();
    };

    load_stage(0, 0);
    CP_WAIT0();
    __syncthreads();

    const int m0w = (wid & 1) * 64;   // 2 warps along M
    const int n0w = (wid >> 1) * 64;  // 4 warps along N
    const uint32_t a_off = (uint32_t)(m0w + (lane & 15)) * 80u + (uint32_t)((lane >> 4) << 4);
    const uint32_t b_off = (uint32_t)(n0w + (lane & 7) + ((lane >> 4) << 3)) * 80u
                         + (uint32_t)(((lane >> 3) & 1) << 4);

    for (int kt = 0; kt < KT; kt++) {
        const int buf = kt & 1;
        if (kt + 1 < KT) load_stage(kt + 1, buf ^ 1);

        const uint32_t bb = sb + buf * STG;
        #pragma unroll
        for (int s = 0; s < 2; s++) {
            uint32_t ah[4][4], al[4][4], bh[8][2], bl[8][2];
            #pragma unroll
            for (int mi = 0; mi < 4; mi++) {
                ldm4(ah[mi], bb + OFF_AH + a_off + mi * 1280u + s * 32u);
                ldm4(al[mi], bb + OFF_AL + a_off + mi * 1280u + s * 32u);
            }
            #pragma unroll
            for (int nj = 0; nj < 4; nj++) {
                uint32_t t[4];
                ldm4(t, bb + OFF_BH + b_off + nj * 1280u + s * 32u);
                bh[nj*2][0] = t[0]; bh[nj*2][1] = t[1];
                bh[nj*2+1][0] = t[2]; bh[nj*2+1][1] = t[3];
                ldm4(t, bb + OFF_BL + b_off + nj * 1280u + s * 32u);
                bl[nj*2][0] = t[0]; bl[nj*2][1] = t[1];
                bl[nj*2+1][0] = t[2]; bl[nj*2+1][1] = t[3];
            }
            #pragma unroll
            for (int mi = 0; mi < 4; mi++)
                #pragma unroll
                for (int nj = 0; nj < 8; nj++) {
                    mma16816(acc[mi][nj], ah[mi], bh[nj]);
                    mma16816(acc[mi][nj], ah[mi], bl[nj]);
                    mma16816(acc[mi][nj], al[mi], bh[nj]);
                }
        }
        CP_WAIT0();
        __syncthreads();
    }

    #pragma unroll
    for (int mi = 0; mi < 4; mi++) {
        const int rbase = row0 + m0w + mi * 16 + (lane >> 2);
        #pragma unroll
        for (int half = 0; half < 2; half++) {
            const int m = rbase + half * 8;
            if (m >= M) continue;
            #pragma unroll
            for (int nj = 0; nj < 8; nj++) {
                const int n = col0 + n0w + nj * 8 + (lane & 3) * 2;
                float v0 = acc[mi][nj][half * 2 + 0] + bias[n];
                float v1 = acc[mi][nj][half * 2 + 1] + bias[n + 1];
                if (EPI == 1) { v0 = gelu_exact(v0); v1 = gelu_exact(v1); }
                if (EPI == 2) {
                    const float* rs = resid + (size_t)(m + m / 1568 + 1) * CC + n;
                    v0 += rs[0]; v1 += rs[1];
                }
                if (OUT == 0) {
                    float* cp = C + (size_t)m * N + n;
                    if (EPI == 3) {
                        float2 old = *(const float2*)cp;
                        v0 += old.x; v1 += old.y;
                    }
                    float2 o = {v0, v1};
                    *(float2*)cp = o;
                } else {
                    __nv_bfloat16 h0, l0, h1, l1;
                    f2hl(v0, h0, l0);
                    f2hl(v1, h1, l1);
                    *(__nv_bfloat162*)(Ch + (size_t)m * N + n) = __halves2bfloat162(h0, h1);
                    *(__nv_bfloat162*)(Cl + (size_t)m * N + n) = __halves2bfloat162(l0, l1);
                }
            }
        }
    }
}

// ---------------------------------------------------------------------------
// Fused weight conversion: all 7 weights -> hi/lo bf16 in one launch.
// ---------------------------------------------------------------------------
struct WSegs {
    const float4*   src[7];
    __nv_bfloat162* dh[7];
    __nv_bfloat162* dl[7];
    int             n4[7];
};

__global__ void conv_all(WSegs w, int total4)
{
    int i = blockIdx.x * blockDim.x + threadIdx.x;
    if (i >= total4) return;
    int rem = i;
    #pragma unroll
    for (int s = 0; s < 7; s++) {
        if (rem < w.n4[s]) {
            float4 v = w.src[s][rem];
            __nv_bfloat16 h0, l0, h1, l1, h2, l2, h3, l3;
            f2hl(v.x, h0, l0); f2hl(v.y, h1, l1);
            f2hl(v.z, h2, l2); f2hl(v.w, h3, l3);
            w.dh[s][rem * 2 + 0] = __halves2bfloat162(h0, h1);
            w.dh[s][rem * 2 + 1] = __halves2bfloat162(h2, h3);
            w.dl[s][rem * 2 + 0] = __halves2bfloat162(l0, l1);
            w.dl[s][rem * 2 + 1] = __halves2bfloat162(l2, l3);
            return;
        }
        rem -= w.n4[s];
    }
}

// ---------------------------------------------------------------------------
// LayerNorm over 768 (=256*3). One block/row. Writes hi/lo bf16.
// ---------------------------------------------------------------------------
__global__ void ln_kernel(const float* __restrict__ src0,
                          const float* __restrict__ xt,
                          const float* __restrict__ g,
                          const float* __restrict__ bta,
                          __nv_bfloat16* __restrict__ oh,
                          __nv_bfloat16* __restrict__ ol, int mode)
{
    int m = blockIdx.x;
    const float* src;
    if (mode == 0) {
        src = src0 + (size_t)(m + m / 1568 + 1) * CC;
    } else if (mode == 1) {
        int sb = m / SL, p = m % SL;
        int b = sb >> 3, t = sb & 7;
        if (p == 0) src = src0 + (size_t)b * NTOK * CC;
        else        src = xt + ((size_t)(b * HW + (p - 1)) * TT + t) * CC;
    } else {
        src = src0 + (size_t)m * CC;
    }
    int tid = threadIdx.x;
    float v0 = src[tid], v1 = src[tid + 256], v2 = src[tid + 512];
    float s = v0 + v1 + v2;
    __shared__ float sh[32];
    int lane = tid & 31, wid = tid >> 5;
    #pragma unroll
    for (int o = 16; o; o >>= 1) s += __shfl_xor_sync(0xffffffffu, s, o);
    if (lane == 0) sh[wid] = s;
    __syncthreads();
    if (wid == 0) {
        float t2 = (lane < 8) ? sh[lane] : 0.0f;
        #pragma unroll
        for (int o = 4; o; o >>= 1) t2 += __shfl_xor_sync(0xffffffffu, t2, o);
        if (lane == 0) sh[0] = t2;
    }
    __syncthreads();
    float mean = sh[0] * (1.0f / 768.0f);
    __syncthreads();
    float d0 = v0 - mean, d1 = v1 - mean, d2 = v2 - mean;
    float s2 = d0 * d0 + d1 * d1 + d2 * d2;
    #pragma unroll
    for (int o = 16; o; o >>= 1) s2 += __shfl_xor_sync(0xffffffffu, s2, o);
    if (lane == 0) sh[wid] = s2;
    __syncthreads();
    if (wid == 0) {
        float t2 = (lane < 8) ? sh[lane] : 0.0f;
        #pragma unroll
        for (int o = 4; o; o >>= 1) t2 += __shfl_xor_sync(0xffffffffu, t2, o);
        if (lane == 0) sh[0] = t2;
    }
    __syncthreads();
    float inv = rsqrtf(sh[0] * (1.0f / 768.0f) + 1e-5f);
    size_t ob = (size_t)m * CC;
    #pragma unroll
    for (int p = 0; p < 3; p++) {
        float d = (p == 0) ? d0 : (p == 1) ? d1 : d2;
        int c = tid + p * 256;
        float v = d * inv * g[c] + bta[c];
        __nv_bfloat16 h, l;
        f2hl(v, h, l);
        oh[ob + c] = h;
        ol[ob + c] = l;
    }
}

// ---------------------------------------------------------------------------
// Temporal attention: fused per (seq, head). Padded smem (conflict-free).
// ---------------------------------------------------------------------------
__global__ void temporal_attn(const float* __restrict__ qkv,
                              __nv_bfloat16* __restrict__ oh,
                              __nv_bfloat16* __restrict__ ol)
{
    int seq = blockIdx.x, h = blockIdx.y;
    __shared__ float q[TT][HD + 1], k[TT][HD + 1], v[TT][HD + 1], p[TT][TT];
    int tid = threadIdx.x;
    size_t base = (size_t)(seq * TT) * C3 + h * HD;
    #pragma unroll
    for (int t = 0; t < TT; t++) {
        q[t][tid] = qkv[base + (size_t)t * C3 + tid];
        k[t][tid] = qkv[base + (size_t)t * C3 + CC + tid];
        v[t][tid] = qkv[base + (size_t)t * C3 + 2 * CC + tid];
    }
    __syncthreads();
    int i = tid >> 3, j = tid & 7;
    float s = 0.0f;
    #pragma unroll
    for (int d = 0; d < HD; d++) s = fmaf(q[i][d], k[j][d], s);
    p[i][j] = s * 0.125f;
    __syncthreads();
    if (tid < TT) {
        float mx = -1e30f;
        #pragma unroll
        for (int jj = 0; jj < TT; jj++) mx = fmaxf(mx, p[tid][jj]);
        float sum = 0.0f;
        #pragma unroll
        for (int jj = 0; jj < TT; jj++) {
            float e = expf(p[tid][jj] - mx);
            p[tid][jj] = e; sum += e;
        }
        float invs = 1.0f / sum;
        #pragma unroll
        for (int jj = 0; jj < TT; jj++) p[tid][jj] *= invs;
    }
    __syncthreads();
    #pragma unroll
    for (int t = 0; t < TT; t++) {
        float o = 0.0f;
        #pragma unroll
        for (int jj = 0; jj < TT; jj++) o = fmaf(p[t][jj], v[jj][tid], o);
        __nv_bfloat16 hh, ll;
        f2hl(o, hh, ll);
        size_t oi = (size_t)(seq * TT + t) * CC + h * HD + tid;
        oh[oi] = hh;
        ol[oi] = ll;
    }
}

// ---------------------------------------------------------------------------
// Spatial scores: per z=(s,h): S = Q * K^T, 197x197x64.
// Tile 64x64x16, 256 threads, 4x4 microtile, float4 LDS.
// ---------------------------------------------------------------------------
__global__ void spatial_scores(const float* __restrict__ qkv, float* __restrict__ sc)
{
    int z = blockIdx.z, s = z / NH, h = z % NH;
    const float* Q  = qkv + (size_t)s * SL * C3 + h * HD;
    const float* Kp = Q + CC;
    float* S = sc + (size_t)z * SL2;
    __shared__ float Qs[16][68], Ks[16][68];
    int tid = threadIdx.x;
    int tx = tid & 15, ty = tid >> 4;
    int row0 = blockIdx.y * 64, col0 = blockIdx.x * 64;
    float acc[4][4] = {};
    int lr = tid >> 2;
    int lc = (tid & 3) << 2;
    #pragma unroll
    for (int k0 = 0; k0 < HD; k0 += 16) {
        #pragma unroll
        for (int u = 0; u < 4; u++) {
            int gr = row0 + lr;
            Qs[lc + u][lr] = (gr < SL) ? Q[(size_t)gr * C3 + k0 + lc + u] : 0.0f;
            int gc = col0 + lr;
            Ks[lc + u][lr] = (gc < SL) ? Kp[(size_t)gc * C3 + k0 + lc + u] : 0.0f;
        }
        __syncthreads();
        #pragma unroll
        for (int kk = 0; kk < 16; kk++) {
            float4 a4 = *(const float4*)&Qs[kk][ty * 4];
            float4 b4 = *(const float4*)&Ks[kk][tx * 4];
            float a[4] = {a4.x, a4.y, a4.z, a4.w};
            float b[4] = {b4.x, b4.y, b4.z, b4.w};
            #pragma unroll
            for (int i = 0; i < 4; i++)
                #pragma unroll
                for (int j = 0; j < 4; j++)
                    acc[i][j] = fmaf(a[i], b[j], acc[i][j]);
        }
        __syncthreads();
    }
    #pragma unroll
    for (int i = 0; i < 4; i++) {
        int m = row0 + ty * 4 + i;
        if (m >= SL) continue;
        #pragma unroll
        for (int j = 0; j < 4; j++) {
            int n = col0 + tx * 4 + j;
            if (n < SL) S[(size_t)m * SL + n] = acc[i][j];
        }
    }
}

// ---------------------------------------------------------------------------
// Softmax over rows of length 197 (1/8 scale folded in).
// ---------------------------------------------------------------------------
__global__ void softmax197(float* __restrict__ sc, int nrows)
{
    int row = blockIdx.x * 8 + (threadIdx.x >> 5);
    if (row >= nrows) return;
    int lane = threadIdx.x & 31;
    float* r = sc + (size_t)row * SL;
    float mx = -1e30f;
    for (int j = lane; j < SL; j += 32) mx = fmaxf(mx, r[j] * 0.125f);
    #pragma unroll
    for (int o = 16; o; o >>= 1) mx = fmaxf(mx, __shfl_xor_sync(0xffffffffu, mx, o));
    float sum = 0.0f;
    for (int j = lane; j < SL; j += 32) {
        float e = expf(r[j] * 0.125f - mx);
        r[j] = e; sum += e;
    }
    #pragma unroll
    for (int o = 16; o; o >>= 1) sum += __shfl_xor_sync(0xffffffffu, sum, o);
    float inv = 1.0f / sum;
    for (int j = lane; j < SL; j += 32) r[j] *= inv;
}

// ---------------------------------------------------------------------------
// Spatial P*V: per z: O = P(197x197) * V(197x64). Writes hi/lo bf16.
// ---------------------------------------------------------------------------
__global__ void spatial_pv(const float* __restrict__ sc, const float* __restrict__ qkv,
                           __nv_bfloat16* __restrict__ oh, __nv_bfloat16* __restrict__ ol)
{
    int z = blockIdx.z, s = z / NH, h = z % NH;
    const float* P = sc + (size_t)z * SL2;
    const float* V = qkv + (size_t)s * SL * C3 + 2 * CC + h * HD;
    size_t obase = (size_t)s * SL * CC + h * HD;
    __shared__ float Ps[16][68], Vs[16][68];
    int tid = threadIdx.x;
    int tx = tid & 15, ty = tid >> 4;
    int row0 = blockIdx.y * 64;
    float acc[4][4] = {};
    int lrp = tid >> 2, lcp = (tid & 3) << 2;
    int lrv = tid >> 4, lcv = (tid & 15) << 2;
    for (int k0 = 0; k0 < SL; k0 += 16) {
        #pragma unroll
        for (int u = 0; u < 4; u++) {
            int gm = row0 + lrp, gk = k0 + lcp + u;
            Ps[lcp + u][lrp] = (gm < SL && gk < SL) ? P[(size_t)gm * SL + gk] : 0.0f;
        }
        {
            int gk = k0 + lrv;
            #pragma unroll
            for (int u = 0; u < 4; u++)
                Vs[lrv][lcv + u] = (gk < SL) ? V[(size_t)gk * C3 + lcv + u] : 0.0f;
        }
        __syncthreads();
        #pragma unroll
        for (int kk = 0; kk < 16; kk++) {
            float4 a4 = *(const float4*)&Ps[kk][ty * 4];
            float4 b4 = *(const float4*)&Vs[kk][tx * 4];
            float a[4] = {a4.x, a4.y, a4.z, a4.w};
            float b[4] = {b4.x, b4.y, b4.z, b4.w};
            #pragma unroll
            for (int i = 0; i < 4; i++)
                #pragma unroll
                for (int j = 0; j < 4; j++)
                    acc[i][j] = fmaf(a[i], b[j], acc[i][j]);
        }
        __syncthreads();
    }
    #pragma unroll
    for (int i = 0; i < 4; i++) {
        int m = row0 + ty * 4 + i;
        if (m >= SL) continue;
        #pragma unroll
        for (int j = 0; j < 4; j++) {
            __nv_bfloat16 hh, ll;
            f2hl(acc[i][j], hh, ll);
            size_t oi = obase + (size_t)m * CC + tx * 4 + j;
            oh[oi] = hh;
            ol[oi] = ll;
        }
    }
}

// ---------------------------------------------------------------------------
// Assemble x_new into d_out
// ---------------------------------------------------------------------------
__global__ void assemble(const float* __restrict__ x, const float* __restrict__ xt,
                         const float* __restrict__ ps, float* __restrict__ out)
{
    int row = blockIdx.x;
    int b = row / NTOK, n = row % NTOK;
    size_t orow = (size_t)row * CC;
    if (n == 0) {
        for (int c = threadIdx.x; c < CC; c += 256) {
            float acc = 0.0f;
            #pragma unroll
            for (int t = 0; t < TT; t++)
                acc += ps[((size_t)(b * TT + t) * SL) * CC + c];
            out[orow + c] = x[orow + c] + acc * 0.125f;
        }
    } else {
        int r = n - 1, hw = r >> 3, t = r & 7;
        size_t xtrow = ((size_t)b * 1568 + r) * CC;
        size_t psrow = ((size_t)((b * TT + t) * SL + 1 + hw)) * CC;
        for (int c = threadIdx.x; c < CC; c += 256)
            out[orow + c] = xt[xtrow + c] + ps[psrow + c];
    }
}

// ---------------------------------------------------------------------------
// Host launch
// ---------------------------------------------------------------------------
extern "C" void kernel_launch(void* const* d_in, const int* in_sizes, int n_in,
                              void* d_out, int out_size)
{
    const float* x        = (const float*)d_in[0];
    const float* ln_t_g   = (const float*)d_in[1];
    const float* ln_t_b   = (const float*)d_in[2];
    const float* t_qkv_w  = (const float*)d_in[3];
    const float* t_qkv_b  = (const float*)d_in[4];
    const float* t_proj_w = (const float*)d_in[5];
    const float* t_proj_b = (const float*)d_in[6];
    const float* t_fc_w   = (const float*)d_in[7];
    const float* t_fc_b   = (const float*)d_in[8];
    const float* ln1_g    = (const float*)d_in[9];
    const float* ln1_b    = (const float*)d_in[10];
    const float* s_qkv_w  = (const float*)d_in[11];
    const float* s_qkv_b  = (const float*)d_in[12];
    const float* s_proj_w = (const float*)d_in[13];
    const float* s_proj_b = (const float*)d_in[14];
    const float* ln2_g    = (const float*)d_in[15];
    const float* ln2_b    = (const float*)d_in[16];
    const float* fc1_w    = (const float*)d_in[17];
    const float* fc1_b    = (const float*)d_in[18];
    const float* fc2_w    = (const float*)d_in[19];
    const float* fc2_b    = (const float*)d_in[20];
    float* out = (float*)d_out;

    float *qkv, *xt, *sc, *proj;
    __nv_bfloat16 *lnh, *lnl, *ath, *atl, *pjh, *pjl, *f1h, *f1l;
    cudaGetSymbolAddress((void**)&qkv,  g_qkv);
    cudaGetSymbolAddress((void**)&xt,   g_xt);
    cudaGetSymbolAddress((void**)&sc,   g_sc);
    cudaGetSymbolAddress((void**)&proj, g_proj);
    cudaGetSymbolAddress((void**)&lnh,  g_ln_h);
    cudaGetSymbolAddress((void**)&lnl,  g_ln_l);
    cudaGetSymbolAddress((void**)&ath,  g_at_h);
    cudaGetSymbolAddress((void**)&atl,  g_at_l);
    cudaGetSymbolAddress((void**)&pjh,  g_pj_h);
    cudaGetSymbolAddress((void**)&pjl,  g_pj_l);
    cudaGetSymbolAddress((void**)&f1h,  g_f1_h);
    cudaGetSymbolAddress((void**)&f1l,  g_f1_l);

    __nv_bfloat16 *wtq_h, *wtq_l, *wtp_h, *wtp_l, *wtf_h, *wtf_l;
    __nv_bfloat16 *wsq_h, *wsq_l, *wsp_h, *wsp_l, *wf1_h, *wf1_l, *wf2_h, *wf2_l;
    cudaGetSymbolAddress((void**)&wtq_h, g_wtq_h); cudaGetSymbolAddress((void**)&wtq_l, g_wtq_l);
    cudaGetSymbolAddress((void**)&wtp_h, g_wtp_h); cudaGetSymbolAddress((void**)&wtp_l, g_wtp_l);
    cudaGetSymbolAddress((void**)&wtf_h, g_wtf_h); cudaGetSymbolAddress((void**)&wtf_l, g_wtf_l);
    cudaGetSymbolAddress((void**)&wsq_h, g_wsq_h); cudaGetSymbolAddress((void**)&wsq_l, g_wsq_l);
    cudaGetSymbolAddress((void**)&wsp_h, g_wsp_h); cudaGetSymbolAddress((void**)&wsp_l, g_wsp_l);
    cudaGetSymbolAddress((void**)&wf1_h, g_wf1_h); cudaGetSymbolAddress((void**)&wf1_l, g_wf1_l);
    cudaGetSymbolAddress((void**)&wf2_h, g_wf2_h); cudaGetSymbolAddress((void**)&wf2_l, g_wf2_l);

    cudaFuncSetAttribute(gemm_mma<0,0>, cudaFuncAttributeMaxDynamicSharedMemorySize, GEMM_SMEM);
    cudaFuncSetAttribute(gemm_mma<0,1>, cudaFuncAttributeMaxDynamicSharedMemorySize, GEMM_SMEM);
    cudaFuncSetAttribute(gemm_mma<1,1>, cudaFuncAttributeMaxDynamicSharedMemorySize, GEMM_SMEM);
    cudaFuncSetAttribute(gemm_mma<2,0>, cudaFuncAttributeMaxDynamicSharedMemorySize, GEMM_SMEM);
    cudaFuncSetAttribute(gemm_mma<3,0>, cudaFuncAttributeMaxDynamicSharedMemorySize, GEMM_SMEM);

    // 0. convert all weights in one launch
    {
        WSegs w;
        w.src[0] = (const float4*)t_qkv_w;  w.dh[0] = (__nv_bfloat162*)wtq_h; w.dl[0] = (__nv_bfloat162*)wtq_l; w.n4[0] = C3 * CC / 4;
        w.src[1] = (const float4*)t_proj_w; w.dh[1] = (__nv_bfloat162*)wtp_h; w.dl[1] = (__nv_bfloat162*)wtp_l; w.n4[1] = CC * CC / 4;
        w.src[2] = (const float4*)t_fc_w;   w.dh[2] = (__nv_bfloat162*)wtf_h; w.dl[2] = (__nv_bfloat162*)wtf_l; w.n4[2] = CC * CC / 4;
        w.src[3] = (const float4*)s_qkv_w;  w.dh[3] = (__nv_bfloat162*)wsq_h; w.dl[3] = (__nv_bfloat162*)wsq_l; w.n4[3] = C3 * CC / 4;
        w.src[4] = (const float4*)s_proj_w; w.dh[4] = (__nv_bfloat162*)wsp_h; w.dl[4] = (__nv_bfloat162*)wsp_l; w.n4[4] = CC * CC / 4;
        w.src[5] = (const float4*)fc1_w;    w.dh[5] = (__nv_bfloat162*)wf1_h; w.dl[5] = (__nv_bfloat162*)wf1_l; w.n4[5] = HIDDEN * CC / 4;
        w.src[6] = (const float4*)fc2_w;    w.dh[6] = (__nv_bfloat162*)wf2_h; w.dl[6] = (__nv_bfloat162*)wf2_l; w.n4[6] = CC * HIDDEN / 4;
        int total4 = 0;
        for (int i = 0; i < 7; i++) total4 += w.n4[i];
        conv_all<<<(total4 + 255) / 256, 256>>>(w, total4);
    }

    // 1. temporal LN (skip cls) -> hi/lo
    ln_kernel<<<MT, 256>>>(x, nullptr, ln_t_g, ln_t_b, lnh, lnl, 0);

    // 2. temporal qkv -> fp32
    gemm_mma<0,0><<<dim3(C3/256, (MT+127)/128), 256, GEMM_SMEM>>>(
        lnh, lnl, wtq_h, wtq_l, t_qkv_b, qkv, nullptr, nullptr, nullptr, MT, C3, CC);

    // 3. temporal attention -> hi/lo
    temporal_attn<<<dim3(BB * HW, NH), 64>>>(qkv, ath, atl);

    // 4. temporal proj -> hi/lo
    gemm_mma<0,1><<<dim3(CC/256, (MT+127)/128), 256, GEMM_SMEM>>>(
        ath, atl, wtp_h, wtp_l, t_proj_b, nullptr, pjh, pjl, nullptr, MT, CC, CC);

    // 5. t_fc + residual from x (skip-cls) -> fp32 xt
    gemm_mma<2,0><<<dim3(CC/256, (MT+127)/128), 256, GEMM_SMEM>>>(
        pjh, pjl, wtf_h, wtf_l, t_fc_b, xt, nullptr, nullptr, x, MT, CC, CC);

    // 6. spatial gather + LN1 -> hi/lo
    ln_kernel<<<MS, 256>>>(x, xt, ln1_g, ln1_b, lnh, lnl, 1);

    // 7. spatial qkv -> fp32
    gemm_mma<0,0><<<dim3(C3/256, (MS+127)/128), 256, GEMM_SMEM>>>(
        lnh, lnl, wsq_h, wsq_l, s_qkv_b, qkv, nullptr, nullptr, nullptr, MS, C3, CC);

    // 8-10. spatial attention -> hi/lo
    spatial_scores<<<dim3(4, 4, ZB), 256>>>(qkv, sc);
    softmax197<<<(ZB * SL + 7) / 8, 256>>>(sc, ZB * SL);
    spatial_pv<<<dim3(1, 4, ZB), 256>>>(sc, qkv, ath, atl);

    // 11. spatial proj -> fp32
    gemm_mma<0,0><<<dim3(CC/256, (MS+127)/128), 256, GEMM_SMEM>>>(
        ath, atl, wsp_h, wsp_l, s_proj_b, proj, nullptr, nullptr, nullptr, MS, CC, CC);

    // 12. assemble x_new into d_out
    assemble<<<MX, 256>>>(x, xt, proj, out);

    // 13. LN2 -> hi/lo
    ln_kernel<<<MX, 256>>>(out, nullptr, ln2_g, ln2_b, lnh, lnl, 2);

    // 14. fc1 + gelu -> hi/lo
    gemm_mma<1,1><<<dim3(HIDDEN/256, (MX+127)/128), 256, GEMM_SMEM>>>(
        lnh, lnl, wf1_h, wf1_l, fc1_b, nullptr, f1h, f1l, nullptr, MX, HIDDEN, CC);

    // 15. fc2 + in-place residual on d_out
    gemm_mma<3,0><<<dim3(CC/256, (MX+127)/128), 256, GEMM_SMEM>>>(
        f1h, f1l, wf2_h, wf2_l, fc2_b, out, nullptr, nullptr, nullptr, MX, CC, HIDDEN);
}

// round 7
// speedup vs baseline: 1.3321x; 1.3321x over previous
#include <cuda_runtime.h>
#include <cuda_fp16.h>
#include <math.h>
#include <stdint.h>

// ---------------------------------------------------------------------------
// Problem constants
// ---------------------------------------------------------------------------
#define CC     768
#define C3     2304
#define NH     12
#define HD     64
#define HIDDEN 3072
#define TT     8
#define HW     196
#define BB     4
#define NTOK   1569
#define MT     6272
#define MS     6304
#define MX     6276
#define SL     197
#define SB     32
#define ZB     (SB*NH)
#define SL2    (SL*SL)

// ---------------------------------------------------------------------------
// Static device scratch
// ---------------------------------------------------------------------------
__device__ float g_qkv [(size_t)MS * C3];
__device__ float g_xt  [(size_t)MT * CC];
__device__ float g_sc  [(size_t)ZB * SL2];
__device__ float g_proj[(size_t)MS * CC];

// activation hi/lo fp16
__device__ __half g_ln_h[(size_t)MS * CC];
__device__ __half g_ln_l[(size_t)MS * CC];
__device__ __half g_at_h[(size_t)MS * CC];
__device__ __half g_at_l[(size_t)MS * CC];
__device__ __half g_pj_h[(size_t)MT * CC];
__device__ __half g_pj_l[(size_t)MT * CC];
__device__ __half g_f1_h[(size_t)MX * HIDDEN];
__device__ __half g_f1_l[(size_t)MX * HIDDEN];

// weights: single fp16
__device__ __half g_wtq[(size_t)C3 * CC];
__device__ __half g_wtp[(size_t)CC * CC];
__device__ __half g_wtf[(size_t)CC * CC];
__device__ __half g_wsq[(size_t)C3 * CC];
__device__ __half g_wsp[(size_t)CC * CC];
__device__ __half g_wf1[(size_t)HIDDEN * CC];
__device__ __half g_wf2[(size_t)CC * HIDDEN];

// ---------------------------------------------------------------------------
// Helpers
// ---------------------------------------------------------------------------
__device__ __forceinline__ float gelu_exact(float v) {
    return 0.5f * v * (1.0f + erff(v * 0.7071067811865475f));
}

__device__ __forceinline__ void f2hl(float x, __half& h, __half& l) {
    h = __float2half_rn(x);
    l = __float2half_rn(x - __half2float(h));
}

__device__ __forceinline__ uint32_t smem_u32(const void* p) {
    uint32_t a;
    asm("{ .reg .u64 t; cvta.to.shared.u64 t, %1; cvt.u32.u64 %0, t; }" : "=r"(a) : "l"(p));
    return a;
}

__device__ __forceinline__ void cpasync16(uint32_t dst, const void* src) {
    asm volatile("cp.async.cg.shared.global [%0], [%1], 16;" :: "r"(dst), "l"(src));
}
#define CP_COMMIT() asm volatile("cp.async.commit_group;" ::: "memory")
#define CP_WAIT0()  asm volatile("cp.async.wait_group 0;" ::: "memory")

__device__ __forceinline__ void ldm4(uint32_t* r, uint32_t addr) {
    asm volatile("ldmatrix.sync.aligned.m8n8.x4.shared.b16 {%0,%1,%2,%3}, [%4];"
                 : "=r"(r[0]), "=r"(r[1]), "=r"(r[2]), "=r"(r[3]) : "r"(addr));
}

__device__ __forceinline__ void mma16816(float* d, const uint32_t* a, const uint32_t* b) {
    asm volatile(
        "mma.sync.aligned.m16n8k16.row.col.f32.f16.f16.f32 "
        "{%0,%1,%2,%3}, {%4,%5,%6,%7}, {%8,%9}, {%0,%1,%2,%3};"
        : "+f"(d[0]), "+f"(d[1]), "+f"(d[2]), "+f"(d[3])
        : "r"(a[0]), "r"(a[1]), "r"(a[2]), "r"(a[3]), "r"(b[0]), "r"(b[1]));
}

// ---------------------------------------------------------------------------
// Split-fp16 HMMA NT GEMM, CTA tile 128x128, k-step 32, 8 warps (64Mx32N),
// double-buffered cp.async. 2 chains: (Ah + Al) * B, fp32 accum.
//   A: hi/lo fp16 activations; B: single fp16 weights (K-major, NT).
// Requirements: N % 128 == 0, K % 32 == 0.
//   EPI 0: +bias   1: gelu(+bias)   2: +bias+resid(skip-cls)   3: +bias+C
//   OUT 0: fp32 C  1: hi/lo fp16 arrays (Ch, Cl)
// smem/stage: Ah, Al, B = 3 x (128 rows x 80B) = 30720 B; x2 = 61440 B.
// ---------------------------------------------------------------------------
#define STG    30720u
#define OFF_AH 0u
#define OFF_AL 10240u
#define OFF_B  20480u
#define GEMM_SMEM (2 * STG)

template<int EPI, int OUT>
__global__ void __launch_bounds__(256)
gemm_mma(const __half* __restrict__ Ahg, const __half* __restrict__ Alg,
         const __half* __restrict__ Bg,
         const float* __restrict__ bias,
         float* __restrict__ C,
         __half* __restrict__ Ch, __half* __restrict__ Cl,
         const float* __restrict__ resid,
         int M, int N, int K)
{
    extern __shared__ char smem[];
    const uint32_t sb = smem_u32(smem);

    const int tid  = threadIdx.x;
    const int wid  = tid >> 5;
    const int lane = tid & 31;
    const int row0 = blockIdx.y * 128;
    const int col0 = blockIdx.x * 128;
    const int KT   = K >> 5;

    float acc[4][4][4];
    #pragma unroll
    for (int a = 0; a < 4; a++)
        #pragma unroll
        for (int b = 0; b < 4; b++)
            #pragma unroll
            for (int c = 0; c < 4; c++) acc[a][b][c] = 0.0f;

    auto load_stage = [&](int kt, int buf) {
        const int kw = kt * 32;
        const uint32_t dstb = sb + buf * STG;
        // A hi+lo: 1024 16B-chunks (128 rows x 4 chunks x 2 arrays)
        #pragma unroll
        for (int q = 0; q < 4; q++) {
            int cid = q * 256 + tid;
            int arr = cid >> 9;
            int idx = cid & 511;
            int row = idx >> 2, ch = idx & 3;
            int ar  = min(row0 + row, M - 1);
            const __half* src = (arr ? Alg : Ahg) + (size_t)ar * K + kw + ch * 8;
            cpasync16(dstb + (arr ? OFF_AL : OFF_AH) + row * 80u + ch * 16u, src);
        }
        // B: 512 16B-chunks (128 rows x 4 chunks)
        #pragma unroll
        for (int q = 0; q < 2; q++) {
            int cid = q * 256 + tid;
            int row = cid >> 2, ch = cid & 3;
            const __half* src = Bg + (size_t)(col0 + row) * K + kw + ch * 8;
            cpasync16(dstb + OFF_B + row * 80u + ch * 16u, src);
        }
        CP_COMMIT();
    };

    load_stage(0, 0);
    CP_WAIT0();
    __syncthreads();

    const int m0w = (wid & 1) * 64;
    const int n0w = (wid >> 1) * 32;
    const uint32_t a_off = (uint32_t)(m0w + (lane & 15)) * 80u + (uint32_t)((lane >> 4) << 4);
    const uint32_t b_off = (uint32_t)(n0w + (lane & 7) + ((lane >> 4) << 3)) * 80u
                         + (uint32_t)(((lane >> 3) & 1) << 4);

    for (int kt = 0; kt < KT; kt++) {
        const int buf = kt & 1;
        if (kt + 1 < KT) load_stage(kt + 1, buf ^ 1);

        const uint32_t bb = sb + buf * STG;
        #pragma unroll
        for (int s = 0; s < 2; s++) {
            uint32_t ah[4][4], al[4][4], bh[4][2];
            #pragma unroll
            for (int mi = 0; mi < 4; mi++) {
                ldm4(ah[mi], bb + OFF_AH + a_off + mi * 1280u + s * 32u);
                ldm4(al[mi], bb + OFF_AL + a_off + mi * 1280u + s * 32u);
            }
            #pragma unroll
            for (int nj = 0; nj < 2; nj++) {
                uint32_t t[4];
                ldm4(t, bb + OFF_B + b_off + nj * 1280u + s * 32u);
                bh[nj*2][0] = t[0]; bh[nj*2][1] = t[1];
                bh[nj*2+1][0] = t[2]; bh[nj*2+1][1] = t[3];
            }
            #pragma unroll
            for (int mi = 0; mi < 4; mi++)
                #pragma unroll
                for (int nj = 0; nj < 4; nj++) {
                    mma16816(acc[mi][nj], ah[mi], bh[nj]);
                    mma16816(acc[mi][nj], al[mi], bh[nj]);
                }
        }
        CP_WAIT0();
        __syncthreads();
    }

    #pragma unroll
    for (int mi = 0; mi < 4; mi++) {
        const int rbase = row0 + m0w + mi * 16 + (lane >> 2);
        #pragma unroll
        for (int half = 0; half < 2; half++) {
            const int m = rbase + half * 8;
            if (m >= M) continue;
            #pragma unroll
            for (int nj = 0; nj < 4; nj++) {
                const int n = col0 + n0w + nj * 8 + (lane & 3) * 2;
                float v0 = acc[mi][nj][half * 2 + 0] + bias[n];
                float v1 = acc[mi][nj][half * 2 + 1] + bias[n + 1];
                if (EPI == 1) { v0 = gelu_exact(v0); v1 = gelu_exact(v1); }
                if (EPI == 2) {
                    const float* rs = resid + (size_t)(m + m / 1568 + 1) * CC + n;
                    v0 += rs[0]; v1 += rs[1];
                }
                if (OUT == 0) {
                    float* cp = C + (size_t)m * N + n;
                    if (EPI == 3) {
                        float2 old = *(const float2*)cp;
                        v0 += old.x; v1 += old.y;
                    }
                    float2 o = {v0, v1};
                    *(float2*)cp = o;
                } else {
                    __half h0, l0, h1, l1;
                    f2hl(v0, h0, l0);
                    f2hl(v1, h1, l1);
                    *(__half2*)(Ch + (size_t)m * N + n) = __halves2half2(h0, h1);
                    *(__half2*)(Cl + (size_t)m * N + n) = __halves2half2(l0, l1);
                }
            }
        }
    }
}

// ---------------------------------------------------------------------------
// Fused weight conversion: all 7 weights -> single fp16, one launch.
// ---------------------------------------------------------------------------
struct WSegs {
    const float4* src[7];
    __half2*      dh[7];
    int           n4[7];
};

__global__ void conv_all(WSegs w, int total4)
{
    int i = blockIdx.x * blockDim.x + threadIdx.x;
    if (i >= total4) return;
    int rem = i;
    #pragma unroll
    for (int s = 0; s < 7; s++) {
        if (rem < w.n4[s]) {
            float4 v = w.src[s][rem];
            w.dh[s][rem * 2 + 0] = __halves2half2(__float2half_rn(v.x), __float2half_rn(v.y));
            w.dh[s][rem * 2 + 1] = __halves2half2(__float2half_rn(v.z), __float2half_rn(v.w));
            return;
        }
        rem -= w.n4[s];
    }
}

// ---------------------------------------------------------------------------
// LayerNorm over 768 (=256*3). One block/row. Writes hi/lo fp16.
// ---------------------------------------------------------------------------
__global__ void ln_kernel(const float* __restrict__ src0,
                          const float* __restrict__ xt,
                          const float* __restrict__ g,
                          const float* __restrict__ bta,
                          __half* __restrict__ oh,
                          __half* __restrict__ ol, int mode)
{
    int m = blockIdx.x;
    const float* src;
    if (mode == 0) {
        src = src0 + (size_t)(m + m / 1568 + 1) * CC;
    } else if (mode == 1) {
        int sb = m / SL, p = m % SL;
        int b = sb >> 3, t = sb & 7;
        if (p == 0) src = src0 + (size_t)b * NTOK * CC;
        else        src = xt + ((size_t)(b * HW + (p - 1)) * TT + t) * CC;
    } else {
        src = src0 + (size_t)m * CC;
    }
    int tid = threadIdx.x;
    float v0 = src[tid], v1 = src[tid + 256], v2 = src[tid + 512];
    float s = v0 + v1 + v2;
    __shared__ float sh[32];
    int lane = tid & 31, wid = tid >> 5;
    #pragma unroll
    for (int o = 16; o; o >>= 1) s += __shfl_xor_sync(0xffffffffu, s, o);
    if (lane == 0) sh[wid] = s;
    __syncthreads();
    if (wid == 0) {
        float t2 = (lane < 8) ? sh[lane] : 0.0f;
        #pragma unroll
        for (int o = 4; o; o >>= 1) t2 += __shfl_xor_sync(0xffffffffu, t2, o);
        if (lane == 0) sh[0] = t2;
    }
    __syncthreads();
    float mean = sh[0] * (1.0f / 768.0f);
    __syncthreads();
    float d0 = v0 - mean, d1 = v1 - mean, d2 = v2 - mean;
    float s2 = d0 * d0 + d1 * d1 + d2 * d2;
    #pragma unroll
    for (int o = 16; o; o >>= 1) s2 += __shfl_xor_sync(0xffffffffu, s2, o);
    if (lane == 0) sh[wid] = s2;
    __syncthreads();
    if (wid == 0) {
        float t2 = (lane < 8) ? sh[lane] : 0.0f;
        #pragma unroll
        for (int o = 4; o; o >>= 1) t2 += __shfl_xor_sync(0xffffffffu, t2, o);
        if (lane == 0) sh[0] = t2;
    }
    __syncthreads();
    float inv = rsqrtf(sh[0] * (1.0f / 768.0f) + 1e-5f);
    size_t ob = (size_t)m * CC;
    #pragma unroll
    for (int p = 0; p < 3; p++) {
        float d = (p == 0) ? d0 : (p == 1) ? d1 : d2;
        int c = tid + p * 256;
        float v = d * inv * g[c] + bta[c];
        __half h, l;
        f2hl(v, h, l);
        oh[ob + c] = h;
        ol[ob + c] = l;
    }
}

// ---------------------------------------------------------------------------
// Temporal attention: fused per (seq, head). Padded smem (conflict-free).
// ---------------------------------------------------------------------------
__global__ void temporal_attn(const float* __restrict__ qkv,
                              __half* __restrict__ oh,
                              __half* __restrict__ ol)
{
    int seq = blockIdx.x, h = blockIdx.y;
    __shared__ float q[TT][HD + 1], k[TT][HD + 1], v[TT][HD + 1], p[TT][TT];
    int tid = threadIdx.x;
    size_t base = (size_t)(seq * TT) * C3 + h * HD;
    #pragma unroll
    for (int t = 0; t < TT; t++) {
        q[t][tid] = qkv[base + (size_t)t * C3 + tid];
        k[t][tid] = qkv[base + (size_t)t * C3 + CC + tid];
        v[t][tid] = qkv[base + (size_t)t * C3 + 2 * CC + tid];
    }
    __syncthreads();
    int i = tid >> 3, j = tid & 7;
    float s = 0.0f;
    #pragma unroll
    for (int d = 0; d < HD; d++) s = fmaf(q[i][d], k[j][d], s);
    p[i][j] = s * 0.125f;
    __syncthreads();
    if (tid < TT) {
        float mx = -1e30f;
        #pragma unroll
        for (int jj = 0; jj < TT; jj++) mx = fmaxf(mx, p[tid][jj]);
        float sum = 0.0f;
        #pragma unroll
        for (int jj = 0; jj < TT; jj++) {
            float e = expf(p[tid][jj] - mx);
            p[tid][jj] = e; sum += e;
        }
        float invs = 1.0f / sum;
        #pragma unroll
        for (int jj = 0; jj < TT; jj++) p[tid][jj] *= invs;
    }
    __syncthreads();
    #pragma unroll
    for (int t = 0; t < TT; t++) {
        float o = 0.0f;
        #pragma unroll
        for (int jj = 0; jj < TT; jj++) o = fmaf(p[t][jj], v[jj][tid], o);
        __half hh, ll;
        f2hl(o, hh, ll);
        size_t oi = (size_t)(seq * TT + t) * CC + h * HD + tid;
        oh[oi] = hh;
        ol[oi] = ll;
    }
}

// ---------------------------------------------------------------------------
// Spatial scores: per z=(s,h): S = Q * K^T, 197x197x64.
// ---------------------------------------------------------------------------
__global__ void spatial_scores(const float* __restrict__ qkv, float* __restrict__ sc)
{
    int z = blockIdx.z, s = z / NH, h = z % NH;
    const float* Q  = qkv + (size_t)s * SL * C3 + h * HD;
    const float* Kp = Q + CC;
    float* S = sc + (size_t)z * SL2;
    __shared__ float Qs[16][68], Ks[16][68];
    int tid = threadIdx.x;
    int tx = tid & 15, ty = tid >> 4;
    int row0 = blockIdx.y * 64, col0 = blockIdx.x * 64;
    float acc[4][4] = {};
    int lr = tid >> 2;
    int lc = (tid & 3) << 2;
    #pragma unroll
    for (int k0 = 0; k0 < HD; k0 += 16) {
        #pragma unroll
        for (int u = 0; u < 4; u++) {
            int gr = row0 + lr;
            Qs[lc + u][lr] = (gr < SL) ? Q[(size_t)gr * C3 + k0 + lc + u] : 0.0f;
            int gc = col0 + lr;
            Ks[lc + u][lr] = (gc < SL) ? Kp[(size_t)gc * C3 + k0 + lc + u] : 0.0f;
        }
        __syncthreads();
        #pragma unroll
        for (int kk = 0; kk < 16; kk++) {
            float4 a4 = *(const float4*)&Qs[kk][ty * 4];
            float4 b4 = *(const float4*)&Ks[kk][tx * 4];
            float a[4] = {a4.x, a4.y, a4.z, a4.w};
            float b[4] = {b4.x, b4.y, b4.z, b4.w};
            #pragma unroll
            for (int i = 0; i < 4; i++)
                #pragma unroll
                for (int j = 0; j < 4; j++)
                    acc[i][j] = fmaf(a[i], b[j], acc[i][j]);
        }
        __syncthreads();
    }
    #pragma unroll
    for (int i = 0; i < 4; i++) {
        int m = row0 + ty * 4 + i;
        if (m >= SL) continue;
        #pragma unroll
        for (int j = 0; j < 4; j++) {
            int n = col0 + tx * 4 + j;
            if (n < SL) S[(size_t)m * SL + n] = acc[i][j];
        }
    }
}

// ---------------------------------------------------------------------------
// Softmax over rows of length 197 (1/8 scale folded in).
// ---------------------------------------------------------------------------
__global__ void softmax197(float* __restrict__ sc, int nrows)
{
    int row = blockIdx.x * 8 + (threadIdx.x >> 5);
    if (row >= nrows) return;
    int lane = threadIdx.x & 31;
    float* r = sc + (size_t)row * SL;
    float mx = -1e30f;
    for (int j = lane; j < SL; j += 32) mx = fmaxf(mx, r[j] * 0.125f);
    #pragma unroll
    for (int o = 16; o; o >>= 1) mx = fmaxf(mx, __shfl_xor_sync(0xffffffffu, mx, o));
    float sum = 0.0f;
    for (int j = lane; j < SL; j += 32) {
        float e = expf(r[j] * 0.125f - mx);
        r[j] = e; sum += e;
    }
    #pragma unroll
    for (int o = 16; o; o >>= 1) sum += __shfl_xor_sync(0xffffffffu, sum, o);
    float inv = 1.0f / sum;
    for (int j = lane; j < SL; j += 32) r[j] *= inv;
}

// ---------------------------------------------------------------------------
// Spatial P*V: per z: O = P(197x197) * V(197x64). Writes hi/lo fp16.
// ---------------------------------------------------------------------------
__global__ void spatial_pv(const float* __restrict__ sc, const float* __restrict__ qkv,
                           __half* __restrict__ oh, __half* __restrict__ ol)
{
    int z = blockIdx.z, s = z / NH, h = z % NH;
    const float* P = sc + (size_t)z * SL2;
    const float* V = qkv + (size_t)s * SL * C3 + 2 * CC + h * HD;
    size_t obase = (size_t)s * SL * CC + h * HD;
    __shared__ float Ps[16][68], Vs[16][68];
    int tid = threadIdx.x;
    int tx = tid & 15, ty = tid >> 4;
    int row0 = blockIdx.y * 64;
    float acc[4][4] = {};
    int lrp = tid >> 2, lcp = (tid & 3) << 2;
    int lrv = tid >> 4, lcv = (tid & 15) << 2;
    for (int k0 = 0; k0 < SL; k0 += 16) {
        #pragma unroll
        for (int u = 0; u < 4; u++) {
            int gm = row0 + lrp, gk = k0 + lcp + u;
            Ps[lcp + u][lrp] = (gm < SL && gk < SL) ? P[(size_t)gm * SL + gk] : 0.0f;
        }
        {
            int gk = k0 + lrv;
            #pragma unroll
            for (int u = 0; u < 4; u++)
                Vs[lrv][lcv + u] = (gk < SL) ? V[(size_t)gk * C3 + lcv + u] : 0.0f;
        }
        __syncthreads();
        #pragma unroll
        for (int kk = 0; kk < 16; kk++) {
            float4 a4 = *(const float4*)&Ps[kk][ty * 4];
            float4 b4 = *(const float4*)&Vs[kk][tx * 4];
            float a[4] = {a4.x, a4.y, a4.z, a4.w};
            float b[4] = {b4.x, b4.y, b4.z, b4.w};
            #pragma unroll
            for (int i = 0; i < 4; i++)
                #pragma unroll
                for (int j = 0; j < 4; j++)
                    acc[i][j] = fmaf(a[i], b[j], acc[i][j]);
        }
        __syncthreads();
    }
    #pragma unroll
    for (int i = 0; i < 4; i++) {
        int m = row0 + ty * 4 + i;
        if (m >= SL) continue;
        #pragma unroll
        for (int j = 0; j < 4; j++) {
            __half hh, ll;
            f2hl(acc[i][j], hh, ll);
            size_t oi = obase + (size_t)m * CC + tx * 4 + j;
            oh[oi] = hh;
            ol[oi] = ll;
        }
    }
}

// ---------------------------------------------------------------------------
// Assemble x_new into d_out
// ---------------------------------------------------------------------------
__global__ void assemble(const float* __restrict__ x, const float* __restrict__ xt,
                         const float* __restrict__ ps, float* __restrict__ out)
{
    int row = blockIdx.x;
    int b = row / NTOK, n = row % NTOK;
    size_t orow = (size_t)row * CC;
    if (n == 0) {
        for (int c = threadIdx.x; c < CC; c += 256) {
            float acc = 0.0f;
            #pragma unroll
            for (int t = 0; t < TT; t++)
                acc += ps[((size_t)(b * TT + t) * SL) * CC + c];
            out[orow + c] = x[orow + c] + acc * 0.125f;
        }
    } else {
        int r = n - 1, hw = r >> 3, t = r & 7;
        size_t xtrow = ((size_t)b * 1568 + r) * CC;
        size_t psrow = ((size_t)((b * TT + t) * SL + 1 + hw)) * CC;
        for (int c = threadIdx.x; c < CC; c += 256)
            out[orow + c] = xt[xtrow + c] + ps[psrow + c];
    }
}

// ---------------------------------------------------------------------------
// Host launch
// ---------------------------------------------------------------------------
extern "C" void kernel_launch(void* const* d_in, const int* in_sizes, int n_in,
                              void* d_out, int out_size)
{
    const float* x        = (const float*)d_in[0];
    const float* ln_t_g   = (const float*)d_in[1];
    const float* ln_t_b   = (const float*)d_in[2];
    const float* t_qkv_w  = (const float*)d_in[3];
    const float* t_qkv_b  = (const float*)d_in[4];
    const float* t_proj_w = (const float*)d_in[5];
    const float* t_proj_b = (const float*)d_in[6];
    const float* t_fc_w   = (const float*)d_in[7];
    const float* t_fc_b   = (const float*)d_in[8];
    const float* ln1_g    = (const float*)d_in[9];
    const float* ln1_b    = (const float*)d_in[10];
    const float* s_qkv_w  = (const float*)d_in[11];
    const float* s_qkv_b  = (const float*)d_in[12];
    const float* s_proj_w = (const float*)d_in[13];
    const float* s_proj_b = (const float*)d_in[14];
    const float* ln2_g    = (const float*)d_in[15];
    const float* ln2_b    = (const float*)d_in[16];
    const float* fc1_w    = (const float*)d_in[17];
    const float* fc1_b    = (const float*)d_in[18];
    const float* fc2_w    = (const float*)d_in[19];
    const float* fc2_b    = (const float*)d_in[20];
    float* out = (float*)d_out;

    float *qkv, *xt, *sc, *proj;
    __half *lnh, *lnl, *ath, *atl, *pjh, *pjl, *f1h, *f1l;
    cudaGetSymbolAddress((void**)&qkv,  g_qkv);
    cudaGetSymbolAddress((void**)&xt,   g_xt);
    cudaGetSymbolAddress((void**)&sc,   g_sc);
    cudaGetSymbolAddress((void**)&proj, g_proj);
    cudaGetSymbolAddress((void**)&lnh,  g_ln_h);
    cudaGetSymbolAddress((void**)&lnl,  g_ln_l);
    cudaGetSymbolAddress((void**)&ath,  g_at_h);
    cudaGetSymbolAddress((void**)&atl,  g_at_l);
    cudaGetSymbolAddress((void**)&pjh,  g_pj_h);
    cudaGetSymbolAddress((void**)&pjl,  g_pj_l);
    cudaGetSymbolAddress((void**)&f1h,  g_f1_h);
    cudaGetSymbolAddress((void**)&f1l,  g_f1_l);

    __half *wtq, *wtp, *wtf, *wsq, *wsp, *wf1, *wf2;
    cudaGetSymbolAddress((void**)&wtq, g_wtq);
    cudaGetSymbolAddress((void**)&wtp, g_wtp);
    cudaGetSymbolAddress((void**)&wtf, g_wtf);
    cudaGetSymbolAddress((void**)&wsq, g_wsq);
    cudaGetSymbolAddress((void**)&wsp, g_wsp);
    cudaGetSymbolAddress((void**)&wf1, g_wf1);
    cudaGetSymbolAddress((void**)&wf2, g_wf2);

    cudaFuncSetAttribute(gemm_mma<0,0>, cudaFuncAttributeMaxDynamicSharedMemorySize, GEMM_SMEM);
    cudaFuncSetAttribute(gemm_mma<0,1>, cudaFuncAttributeMaxDynamicSharedMemorySize, GEMM_SMEM);
    cudaFuncSetAttribute(gemm_mma<1,1>, cudaFuncAttributeMaxDynamicSharedMemorySize, GEMM_SMEM);
    cudaFuncSetAttribute(gemm_mma<2,0>, cudaFuncAttributeMaxDynamicSharedMemorySize, GEMM_SMEM);
    cudaFuncSetAttribute(gemm_mma<3,0>, cudaFuncAttributeMaxDynamicSharedMemorySize, GEMM_SMEM);

    // 0. convert all weights in one launch (single fp16)
    {
        WSegs w;
        w.src[0] = (const float4*)t_qkv_w;  w.dh[0] = (__half2*)wtq; w.n4[0] = C3 * CC / 4;
        w.src[1] = (const float4*)t_proj_w; w.dh[1] = (__half2*)wtp; w.n4[1] = CC * CC / 4;
        w.src[2] = (const float4*)t_fc_w;   w.dh[2] = (__half2*)wtf; w.n4[2] = CC * CC / 4;
        w.src[3] = (const float4*)s_qkv_w;  w.dh[3] = (__half2*)wsq; w.n4[3] = C3 * CC / 4;
        w.src[4] = (const float4*)s_proj_w; w.dh[4] = (__half2*)wsp; w.n4[4] = CC * CC / 4;
        w.src[5] = (const float4*)fc1_w;    w.dh[5] = (__half2*)wf1; w.n4[5] = HIDDEN * CC / 4;
        w.src[6] = (const float4*)fc2_w;    w.dh[6] = (__half2*)wf2; w.n4[6] = CC * HIDDEN / 4;
        int total4 = 0;
        for (int i = 0; i < 7; i++) total4 += w.n4[i];
        conv_all<<<(total4 + 255) / 256, 256>>>(w, total4);
    }

    // 1. temporal LN (skip cls) -> hi/lo
    ln_kernel<<<MT, 256>>>(x, nullptr, ln_t_g, ln_t_b, lnh, lnl, 0);

    // 2. temporal qkv -> fp32
    gemm_mma<0,0><<<dim3(C3/128, (MT+127)/128), 256, GEMM_SMEM>>>(
        lnh, lnl, wtq, t_qkv_b, qkv, nullptr, nullptr, nullptr, MT, C3, CC);

    // 3. temporal attention -> hi/lo
    temporal_attn<<<dim3(BB * HW, NH), 64>>>(qkv, ath, atl);

    // 4. temporal proj -> hi/lo
    gemm_mma<0,1><<<dim3(CC/128, (MT+127)/128), 256, GEMM_SMEM>>>(
        ath, atl, wtp, t_proj_b, nullptr, pjh, pjl, nullptr, MT, CC, CC);

    // 5. t_fc + residual from x (skip-cls) -> fp32 xt
    gemm_mma<2,0><<<dim3(CC/128, (MT+127)/128), 256, GEMM_SMEM>>>(
        pjh, pjl, wtf, t_fc_b, xt, nullptr, nullptr, x, MT, CC, CC);

    // 6. spatial gather + LN1 -> hi/lo
    ln_kernel<<<MS, 256>>>(x, xt, ln1_g, ln1_b, lnh, lnl, 1);

    // 7. spatial qkv -> fp32
    gemm_mma<0,0><<<dim3(C3/128, (MS+127)/128), 256, GEMM_SMEM>>>(
        lnh, lnl, wsq, s_qkv_b, qkv, nullptr, nullptr, nullptr, MS, C3, CC);

    // 8-10. spatial attention -> hi/lo
    spatial_scores<<<dim3(4, 4, ZB), 256>>>(qkv, sc);
    softmax197<<<(ZB * SL + 7) / 8, 256>>>(sc, ZB * SL);
    spatial_pv<<<dim3(1, 4, ZB), 256>>>(sc, qkv, ath, atl);

    // 11. spatial proj -> fp32
    gemm_mma<0,0><<<dim3(CC/128, (MS+127)/128), 256, GEMM_SMEM>>>(
        ath, atl, wsp, s_proj_b, proj, nullptr, nullptr, nullptr, MS, CC, CC);

    // 12. assemble x_new into d_out
    assemble<<<MX, 256>>>(x, xt, proj, out);

    // 13. LN2 -> hi/lo
    ln_kernel<<<MX, 256>>>(out, nullptr, ln2_g, ln2_b, lnh, lnl, 2);

    // 14. fc1 + gelu -> hi/lo
    gemm_mma<1,1><<<dim3(HIDDEN/128, (MX+127)/128), 256, GEMM_SMEM>>>(
        lnh, lnl, wf1, fc1_b, nullptr, f1h, f1l, nullptr, MX, HIDDEN, CC);

    // 15. fc2 + in-place residual on d_out
    gemm_mma<3,0><<<dim3(CC/128, (MX+127)/128), 256, GEMM_SMEM>>>(
        f1h, f1l, wf2, fc2_b, out, nullptr, nullptr, nullptr, MX, CC, HIDDEN);
}

// round 8
// speedup vs baseline: 1.3978x; 1.0493x over previous
#include <cuda_runtime.h>
#include <cuda_fp16.h>
#include <math.h>
#include <stdint.h>

// ---------------------------------------------------------------------------
// Problem constants
// ---------------------------------------------------------------------------
#define CC     768
#define C3     2304
#define NH     12
#define HD     64
#define HIDDEN 3072
#define TT     8
#define HW     196
#define BB     4
#define NTOK   1569
#define MT     6272
#define MS     6304
#define MX     6276
#define SL     197
#define SB     32
#define ZB     (SB*NH)
#define SL2    (SL*SL)
#define KP     224          // padded K for P/Vt (7 * 32)

// ---------------------------------------------------------------------------
// Static device scratch
// ---------------------------------------------------------------------------
__device__ float g_qkv [(size_t)MT * C3];      // fp32 qkv (temporal attention)
__device__ float g_xt  [(size_t)MT * CC];
__device__ float g_sc  [(size_t)ZB * SL2];     // fp32 spatial scores
__device__ float g_proj[(size_t)MS * CC];

// activation hi/lo fp16
__device__ __half g_ln_h[(size_t)MS * CC];
__device__ __half g_ln_l[(size_t)MS * CC];
__device__ __half g_at_h[(size_t)MS * CC];
__device__ __half g_at_l[(size_t)MS * CC];
__device__ __half g_pj_h[(size_t)MT * CC];
__device__ __half g_pj_l[(size_t)MT * CC];
__device__ __half g_f1_h[(size_t)MX * HIDDEN];
__device__ __half g_f1_l[(size_t)MX * HIDDEN];

// spatial qkv hi/lo fp16
__device__ __half g_qs_h[(size_t)MS * C3];
__device__ __half g_qs_l[(size_t)MS * C3];
// softmax P hi/lo (K-padded to 224)
__device__ __half g_p_h[(size_t)ZB * SL * KP];
__device__ __half g_p_l[(size_t)ZB * SL * KP];
// V transposed hi/lo [z][64][224]
__device__ __half g_vt_h[(size_t)ZB * HD * KP];
__device__ __half g_vt_l[(size_t)ZB * HD * KP];

// weights: single fp16
__device__ __half g_wtq[(size_t)C3 * CC];
__device__ __half g_wtp[(size_t)CC * CC];
__device__ __half g_wtf[(size_t)CC * CC];
__device__ __half g_wsq[(size_t)C3 * CC];
__device__ __half g_wsp[(size_t)CC * CC];
__device__ __half g_wf1[(size_t)HIDDEN * CC];
__device__ __half g_wf2[(size_t)CC * HIDDEN];

// ---------------------------------------------------------------------------
// Helpers
// ---------------------------------------------------------------------------
__device__ __forceinline__ float gelu_exact(float v) {
    return 0.5f * v * (1.0f + erff(v * 0.7071067811865475f));
}

__device__ __forceinline__ void f2hl(float x, __half& h, __half& l) {
    h = __float2half_rn(x);
    l = __float2half_rn(x - __half2float(h));
}

__device__ __forceinline__ uint32_t smem_u32(const void* p) {
    uint32_t a;
    asm("{ .reg .u64 t; cvta.to.shared.u64 t, %1; cvt.u32.u64 %0, t; }" : "=r"(a) : "l"(p));
    return a;
}

__device__ __forceinline__ void cpasync16(uint32_t dst, const void* src) {
    asm volatile("cp.async.cg.shared.global [%0], [%1], 16;" :: "r"(dst), "l"(src));
}
#define CP_COMMIT() asm volatile("cp.async.commit_group;" ::: "memory")
#define CP_WAIT0()  asm volatile("cp.async.wait_group 0;" ::: "memory")

__device__ __forceinline__ void ldm4(uint32_t* r, uint32_t addr) {
    asm volatile("ldmatrix.sync.aligned.m8n8.x4.shared.b16 {%0,%1,%2,%3}, [%4];"
                 : "=r"(r[0]), "=r"(r[1]), "=r"(r[2]), "=r"(r[3]) : "r"(addr));
}

__device__ __forceinline__ void mma16816(float* d, const uint32_t* a, const uint32_t* b) {
    asm volatile(
        "mma.sync.aligned.m16n8k16.row.col.f32.f16.f16.f32 "
        "{%0,%1,%2,%3}, {%4,%5,%6,%7}, {%8,%9}, {%0,%1,%2,%3};"
        : "+f"(d[0]), "+f"(d[1]), "+f"(d[2]), "+f"(d[3])
        : "r"(a[0]), "r"(a[1]), "r"(a[2]), "r"(a[3]), "r"(b[0]), "r"(b[1]));
}

// ---------------------------------------------------------------------------
// Split-fp16 HMMA NT GEMM (Round-7, passing). CTA 128x128, 8 warps (64Mx32N).
// ---------------------------------------------------------------------------
#define STG    30720u
#define OFF_AH 0u
#define OFF_AL 10240u
#define OFF_B  20480u
#define GEMM_SMEM (2 * STG)

template<int EPI, int OUT>
__global__ void __launch_bounds__(256)
gemm_mma(const __half* __restrict__ Ahg, const __half* __restrict__ Alg,
         const __half* __restrict__ Bg,
         const float* __restrict__ bias,
         float* __restrict__ C,
         __half* __restrict__ Ch, __half* __restrict__ Cl,
         const float* __restrict__ resid,
         int M, int N, int K)
{
    extern __shared__ char smem[];
    const uint32_t sb = smem_u32(smem);

    const int tid  = threadIdx.x;
    const int wid  = tid >> 5;
    const int lane = tid & 31;
    const int row0 = blockIdx.y * 128;
    const int col0 = blockIdx.x * 128;
    const int KT   = K >> 5;

    float acc[4][4][4];
    #pragma unroll
    for (int a = 0; a < 4; a++)
        #pragma unroll
        for (int b = 0; b < 4; b++)
            #pragma unroll
            for (int c = 0; c < 4; c++) acc[a][b][c] = 0.0f;

    auto load_stage = [&](int kt, int buf) {
        const int kw = kt * 32;
        const uint32_t dstb = sb + buf * STG;
        #pragma unroll
        for (int q = 0; q < 4; q++) {
            int cid = q * 256 + tid;
            int arr = cid >> 9;
            int idx = cid & 511;
            int row = idx >> 2, ch = idx & 3;
            int ar  = min(row0 + row, M - 1);
            const __half* src = (arr ? Alg : Ahg) + (size_t)ar * K + kw + ch * 8;
            cpasync16(dstb + (arr ? OFF_AL : OFF_AH) + row * 80u + ch * 16u, src);
        }
        #pragma unroll
        for (int q = 0; q < 2; q++) {
            int cid = q * 256 + tid;
            int row = cid >> 2, ch = cid & 3;
            const __half* src = Bg + (size_t)(col0 + row) * K + kw + ch * 8;
            cpasync16(dstb + OFF_B + row * 80u + ch * 16u, src);
        }
        CP_COMMIT();
    };

    load_stage(0, 0);
    CP_WAIT0();
    __syncthreads();

    const int m0w = (wid & 1) * 64;
    const int n0w = (wid >> 1) * 32;
    const uint32_t a_off = (uint32_t)(m0w + (lane & 15)) * 80u + (uint32_t)((lane >> 4) << 4);
    const uint32_t b_off = (uint32_t)(n0w + (lane & 7) + ((lane >> 4) << 3)) * 80u
                         + (uint32_t)(((lane >> 3) & 1) << 4);

    for (int kt = 0; kt < KT; kt++) {
        const int buf = kt & 1;
        if (kt + 1 < KT) load_stage(kt + 1, buf ^ 1);

        const uint32_t bb = sb + buf * STG;
        #pragma unroll
        for (int s = 0; s < 2; s++) {
            uint32_t ah[4][4], al[4][4], bh[4][2];
            #pragma unroll
            for (int mi = 0; mi < 4; mi++) {
                ldm4(ah[mi], bb + OFF_AH + a_off + mi * 1280u + s * 32u);
                ldm4(al[mi], bb + OFF_AL + a_off + mi * 1280u + s * 32u);
            }
            #pragma unroll
            for (int nj = 0; nj < 2; nj++) {
                uint32_t t[4];
                ldm4(t, bb + OFF_B + b_off + nj * 1280u + s * 32u);
                bh[nj*2][0] = t[0]; bh[nj*2][1] = t[1];
                bh[nj*2+1][0] = t[2]; bh[nj*2+1][1] = t[3];
            }
            #pragma unroll
            for (int mi = 0; mi < 4; mi++)
                #pragma unroll
                for (int nj = 0; nj < 4; nj++) {
                    mma16816(acc[mi][nj], ah[mi], bh[nj]);
                    mma16816(acc[mi][nj], al[mi], bh[nj]);
                }
        }
        CP_WAIT0();
        __syncthreads();
    }

    #pragma unroll
    for (int mi = 0; mi < 4; mi++) {
        const int rbase = row0 + m0w + mi * 16 + (lane >> 2);
        #pragma unroll
        for (int half = 0; half < 2; half++) {
            const int m = rbase + half * 8;
            if (m >= M) continue;
            #pragma unroll
            for (int nj = 0; nj < 4; nj++) {
                const int n = col0 + n0w + nj * 8 + (lane & 3) * 2;
                float v0 = acc[mi][nj][half * 2 + 0] + bias[n];
                float v1 = acc[mi][nj][half * 2 + 1] + bias[n + 1];
                if (EPI == 1) { v0 = gelu_exact(v0); v1 = gelu_exact(v1); }
                if (EPI == 2) {
                    const float* rs = resid + (size_t)(m + m / 1568 + 1) * CC + n;
                    v0 += rs[0]; v1 += rs[1];
                }
                if (OUT == 0) {
                    float* cp = C + (size_t)m * N + n;
                    if (EPI == 3) {
                        float2 old = *(const float2*)cp;
                        v0 += old.x; v1 += old.y;
                    }
                    float2 o = {v0, v1};
                    *(float2*)cp = o;
                } else {
                    __half h0, l0, h1, l1;
                    f2hl(v0, h0, l0);
                    f2hl(v1, h1, l1);
                    *(__half2*)(Ch + (size_t)m * N + n) = __halves2half2(h0, h1);
                    *(__half2*)(Cl + (size_t)m * N + n) = __halves2half2(l0, l1);
                }
            }
        }
    }
}

// ---------------------------------------------------------------------------
// Batched spatial scores via HMMA: per z, S = Q*K^T * 0.125.  197x197x64.
// CTA 128x128, 8 warps 64x32, 3 chains (QhKh + QhKl + QlKh).
// smem/stage: 4 arrays x 128 x 80B = 40960; double buffered.
// ---------------------------------------------------------------------------
#define SSTG    40960u
#define SOFF_AH 0u
#define SOFF_AL 10240u
#define SOFF_BH 20480u
#define SOFF_BL 30720u
#define SC_SMEM (2 * SSTG)

__global__ void __launch_bounds__(256)
attn_scores_mma(const __half* __restrict__ qh, const __half* __restrict__ ql,
                float* __restrict__ sc)
{
    extern __shared__ char smem[];
    const uint32_t sb = smem_u32(smem);

    const int z = blockIdx.z;
    const int s = z / NH, h = z % NH;
    const size_t base = (size_t)(s * SL) * C3 + h * HD;

    const int tid  = threadIdx.x;
    const int wid  = tid >> 5;
    const int lane = tid & 31;
    const int row0 = blockIdx.y * 128;
    const int col0 = blockIdx.x * 128;

    float acc[4][4][4];
    #pragma unroll
    for (int a = 0; a < 4; a++)
        #pragma unroll
        for (int b = 0; b < 4; b++)
            #pragma unroll
            for (int c = 0; c < 4; c++) acc[a][b][c] = 0.0f;

    auto load_stage = [&](int kt, int buf) {
        const int kw = kt * 32;
        const uint32_t dstb = sb + buf * SSTG;
        #pragma unroll
        for (int q = 0; q < 8; q++) {
            int cid = q * 256 + tid;          // 0..2047
            int side = cid >> 10;             // 0 = Q(A), 1 = K(B)
            int rem  = cid & 1023;
            int arr  = rem >> 9;              // 0 = hi, 1 = lo
            int idx  = rem & 511;
            int row  = idx >> 2, ch = idx & 3;
            int gr   = min((side ? col0 : row0) + row, SL - 1);
            const __half* srcb = arr ? ql : qh;
            const __half* src  = srcb + base + (size_t)gr * C3 + (side ? CC : 0) + kw + ch * 8;
            uint32_t off = side ? (arr ? SOFF_BL : SOFF_BH) : (arr ? SOFF_AL : SOFF_AH);
            cpasync16(dstb + off + row * 80u + ch * 16u, src);
        }
        CP_COMMIT();
    };

    load_stage(0, 0);
    CP_WAIT0();
    __syncthreads();

    const int m0w = (wid & 1) * 64;
    const int n0w = (wid >> 1) * 32;
    const uint32_t a_off = (uint32_t)(m0w + (lane & 15)) * 80u + (uint32_t)((lane >> 4) << 4);
    const uint32_t b_off = (uint32_t)(n0w + (lane & 7) + ((lane >> 4) << 3)) * 80u
                         + (uint32_t)(((lane >> 3) & 1) << 4);

    #pragma unroll
    for (int kt = 0; kt < 2; kt++) {          // K = 64
        const int buf = kt & 1;
        if (kt + 1 < 2) load_stage(kt + 1, buf ^ 1);

        const uint32_t bb = sb + buf * SSTG;
        #pragma unroll
        for (int s2 = 0; s2 < 2; s2++) {
            uint32_t ah[4][4], al[4][4], bh[4][2], bl[4][2];
            #pragma unroll
            for (int mi = 0; mi < 4; mi++) {
                ldm4(ah[mi], bb + SOFF_AH + a_off + mi * 1280u + s2 * 32u);
                ldm4(al[mi], bb + SOFF_AL + a_off + mi * 1280u + s2 * 32u);
            }
            #pragma unroll
            for (int nj = 0; nj < 2; nj++) {
                uint32_t t[4];
                ldm4(t, bb + SOFF_BH + b_off + nj * 1280u + s2 * 32u);
                bh[nj*2][0] = t[0]; bh[nj*2][1] = t[1];
                bh[nj*2+1][0] = t[2]; bh[nj*2+1][1] = t[3];
                ldm4(t, bb + SOFF_BL + b_off + nj * 1280u + s2 * 32u);
                bl[nj*2][0] = t[0]; bl[nj*2][1] = t[1];
                bl[nj*2+1][0] = t[2]; bl[nj*2+1][1] = t[3];
            }
            #pragma unroll
            for (int mi = 0; mi < 4; mi++)
                #pragma unroll
                for (int nj = 0; nj < 4; nj++) {
                    mma16816(acc[mi][nj], ah[mi], bh[nj]);
                    mma16816(acc[mi][nj], ah[mi], bl[nj]);
                    mma16816(acc[mi][nj], al[mi], bh[nj]);
                }
        }
        CP_WAIT0();
        __syncthreads();
    }

    float* S = sc + (size_t)z * SL2;
    #pragma unroll
    for (int mi = 0; mi < 4; mi++) {
        const int rbase = row0 + m0w + mi * 16 + (lane >> 2);
        #pragma unroll
        for (int half = 0; half < 2; half++) {
            const int m = rbase + half * 8;
            if (m >= SL) continue;
            #pragma unroll
            for (int nj = 0; nj < 4; nj++) {
                const int n = col0 + n0w + nj * 8 + (lane & 3) * 2;
                if (n < SL)     S[(size_t)m * SL + n]     = acc[mi][nj][half * 2 + 0] * 0.125f;
                if (n + 1 < SL) S[(size_t)m * SL + n + 1] = acc[mi][nj][half * 2 + 1] * 0.125f;
            }
        }
    }
}

// ---------------------------------------------------------------------------
// Batched PV via HMMA: per z, O = P(197x197) * V(197x64), P/Vt hi/lo fp16,
// K padded to 224. CTA 128(M)x64(N), 8 warps 32x32, 3 chains.
// smem/stage: A 2x128x80 + B 2x64x80 = 30720; double buffered.
// ---------------------------------------------------------------------------
#define PSTG    30720u
#define POFF_AH 0u
#define POFF_AL 10240u
#define POFF_BH 20480u
#define POFF_BL 25600u
#define PV_SMEM (2 * PSTG)

__global__ void __launch_bounds__(256)
attn_pv_mma(const __half* __restrict__ ph, const __half* __restrict__ pl,
            const __half* __restrict__ vth, const __half* __restrict__ vtl,
            __half* __restrict__ oh, __half* __restrict__ ol)
{
    extern __shared__ char smem[];
    const uint32_t sb = smem_u32(smem);

    const int z = blockIdx.y;
    const int s = z / NH, h = z % NH;
    const size_t pbase = (size_t)z * SL * KP;
    const size_t vbase = (size_t)z * HD * KP;

    const int tid  = threadIdx.x;
    const int wid  = tid >> 5;
    const int lane = tid & 31;
    const int row0 = blockIdx.x * 128;

    float acc[2][4][4];
    #pragma unroll
    for (int a = 0; a < 2; a++)
        #pragma unroll
        for (int b = 0; b < 4; b++)
            #pragma unroll
            for (int c = 0; c < 4; c++) acc[a][b][c] = 0.0f;

    auto load_stage = [&](int kt, int buf) {
        const int kw = kt * 32;
        const uint32_t dstb = sb + buf * PSTG;
        // A (P): 2 arrays x 128 rows x 4 chunks = 1024
        #pragma unroll
        for (int q = 0; q < 4; q++) {
            int cid = q * 256 + tid;
            int arr = cid >> 9;
            int idx = cid & 511;
            int row = idx >> 2, ch = idx & 3;
            int gr  = min(row0 + row, SL - 1);
            const __half* src = (arr ? pl : ph) + pbase + (size_t)gr * KP + kw + ch * 8;
            cpasync16(dstb + (arr ? POFF_AL : POFF_AH) + row * 80u + ch * 16u, src);
        }
        // B (Vt): 2 arrays x 64 rows x 4 chunks = 512
        #pragma unroll
        for (int q = 0; q < 2; q++) {
            int cid = q * 256 + tid;
            int arr = cid >> 8;
            int idx = cid & 255;
            int row = idx >> 2, ch = idx & 3;
            const __half* src = (arr ? vtl : vth) + vbase + (size_t)row * KP + kw + ch * 8;
            cpasync16(dstb + (arr ? POFF_BL : POFF_BH) + row * 80u + ch * 16u, src);
        }
        CP_COMMIT();
    };

    load_stage(0, 0);
    CP_WAIT0();
    __syncthreads();

    const int m0w = (wid & 3) * 32;
    const int n0w = (wid >> 2) * 32;
    const uint32_t a_off = (uint32_t)(m0w + (lane & 15)) * 80u + (uint32_t)((lane >> 4) << 4);
    const uint32_t b_off = (uint32_t)(n0w + (lane & 7) + ((lane >> 4) << 3)) * 80u
                         + (uint32_t)(((lane >> 3) & 1) << 4);

    for (int kt = 0; kt < KP / 32; kt++) {
        const int buf = kt & 1;
        if (kt + 1 < KP / 32) load_stage(kt + 1, buf ^ 1);

        const uint32_t bb = sb + buf * PSTG;
        #pragma unroll
        for (int s2 = 0; s2 < 2; s2++) {
            uint32_t ah[2][4], al[2][4], bh[4][2], bl[4][2];
            #pragma unroll
            for (int mi = 0; mi < 2; mi++) {
                ldm4(ah[mi], bb + POFF_AH + a_off + mi * 1280u + s2 * 32u);
                ldm4(al[mi], bb + POFF_AL + a_off + mi * 1280u + s2 * 32u);
            }
            #pragma unroll
            for (int nj = 0; nj < 2; nj++) {
                uint32_t t[4];
                ldm4(t, bb + POFF_BH + b_off + nj * 1280u + s2 * 32u);
                bh[nj*2][0] = t[0]; bh[nj*2][1] = t[1];
                bh[nj*2+1][0] = t[2]; bh[nj*2+1][1] = t[3];
                ldm4(t, bb + POFF_BL + b_off + nj * 1280u + s2 * 32u);
                bl[nj*2][0] = t[0]; bl[nj*2][1] = t[1];
                bl[nj*2+1][0] = t[2]; bl[nj*2+1][1] = t[3];
            }
            #pragma unroll
            for (int mi = 0; mi < 2; mi++)
                #pragma unroll
                for (int nj = 0; nj < 4; nj++) {
                    mma16816(acc[mi][nj], ah[mi], bh[nj]);
                    mma16816(acc[mi][nj], ah[mi], bl[nj]);
                    mma16816(acc[mi][nj], al[mi], bh[nj]);
                }
        }
        CP_WAIT0();
        __syncthreads();
    }

    #pragma unroll
    for (int mi = 0; mi < 2; mi++) {
        const int rbase = row0 + m0w + mi * 16 + (lane >> 2);
        #pragma unroll
        for (int half = 0; half < 2; half++) {
            const int m = rbase + half * 8;
            if (m >= SL) continue;
            size_t ob = (size_t)(s * SL + m) * CC + h * HD;
            #pragma unroll
            for (int nj = 0; nj < 4; nj++) {
                const int n = n0w + nj * 8 + (lane & 3) * 2;
                __half h0, l0, h1, l1;
                f2hl(acc[mi][nj][half * 2 + 0], h0, l0);
                f2hl(acc[mi][nj][half * 2 + 1], h1, l1);
                *(__half2*)(oh + ob + n) = __halves2half2(h0, h1);
                *(__half2*)(ol + ob + n) = __halves2half2(l0, l1);
            }
        }
    }
}

// ---------------------------------------------------------------------------
// V transpose: per z, Vt[d][t] = V[t][d], padded t->224 with zeros. hi+lo.
// ---------------------------------------------------------------------------
__global__ void transpose_v(const __half* __restrict__ qh, const __half* __restrict__ ql,
                            __half* __restrict__ vth, __half* __restrict__ vtl)
{
    int z = blockIdx.x;
    int s = z / NH, h = z % NH;
    size_t vbase = (size_t)(s * SL) * C3 + 2 * CC + h * HD;
    size_t obase = (size_t)z * HD * KP;
    __shared__ __half shh[32][66], shl[32][66];
    int tid = threadIdx.x;

    for (int t0 = 0; t0 < KP; t0 += 32) {
        #pragma unroll
        for (int i = 0; i < 8; i++) {
            int e = i * 256 + tid;       // 32 x 64 = 2048
            int t = e >> 6, d = e & 63;
            int gt = t0 + t;
            if (gt < SL) {
                size_t gi = vbase + (size_t)gt * C3 + d;
                shh[t][d] = qh[gi];
                shl[t][d] = ql[gi];
            } else {
                shh[t][d] = __float2half(0.0f);
                shl[t][d] = __float2half(0.0f);
            }
        }
        __syncthreads();
        #pragma unroll
        for (int i = 0; i < 8; i++) {
            int e = i * 256 + tid;       // 64 x 32
            int d = e >> 5, t = e & 31;
            vth[obase + (size_t)d * KP + t0 + t] = shh[t][d];
            vtl[obase + (size_t)d * KP + t0 + t] = shl[t][d];
        }
        __syncthreads();
    }
}

// ---------------------------------------------------------------------------
// Fused weight conversion: all 7 weights -> single fp16, one launch.
// ---------------------------------------------------------------------------
struct WSegs {
    const float4* src[7];
    __half2*      dh[7];
    int           n4[7];
};

__global__ void conv_all(WSegs w, int total4)
{
    int i = blockIdx.x * blockDim.x + threadIdx.x;
    if (i >= total4) return;
    int rem = i;
    #pragma unroll
    for (int s = 0; s < 7; s++) {
        if (rem < w.n4[s]) {
            float4 v = w.src[s][rem];
            w.dh[s][rem * 2 + 0] = __halves2half2(__float2half_rn(v.x), __float2half_rn(v.y));
            w.dh[s][rem * 2 + 1] = __halves2half2(__float2half_rn(v.z), __float2half_rn(v.w));
            return;
        }
        rem -= w.n4[s];
    }
}

// ---------------------------------------------------------------------------
// LayerNorm over 768 (=256*3). One block/row. Writes hi/lo fp16.
// ---------------------------------------------------------------------------
__global__ void ln_kernel(const float* __restrict__ src0,
                          const float* __restrict__ xt,
                          const float* __restrict__ g,
                          const float* __restrict__ bta,
                          __half* __restrict__ oh,
                          __half* __restrict__ ol, int mode)
{
    int m = blockIdx.x;
    const float* src;
    if (mode == 0) {
        src = src0 + (size_t)(m + m / 1568 + 1) * CC;
    } else if (mode == 1) {
        int sb = m / SL, p = m % SL;
        int b = sb >> 3, t = sb & 7;
        if (p == 0) src = src0 + (size_t)b * NTOK * CC;
        else        src = xt + ((size_t)(b * HW + (p - 1)) * TT + t) * CC;
    } else {
        src = src0 + (size_t)m * CC;
    }
    int tid = threadIdx.x;
    float v0 = src[tid], v1 = src[tid + 256], v2 = src[tid + 512];
    float s = v0 + v1 + v2;
    __shared__ float sh[32];
    int lane = tid & 31, wid = tid >> 5;
    #pragma unroll
    for (int o = 16; o; o >>= 1) s += __shfl_xor_sync(0xffffffffu, s, o);
    if (lane == 0) sh[wid] = s;
    __syncthreads();
    if (wid == 0) {
        float t2 = (lane < 8) ? sh[lane] : 0.0f;
        #pragma unroll
        for (int o = 4; o; o >>= 1) t2 += __shfl_xor_sync(0xffffffffu, t2, o);
        if (lane == 0) sh[0] = t2;
    }
    __syncthreads();
    float mean = sh[0] * (1.0f / 768.0f);
    __syncthreads();
    float d0 = v0 - mean, d1 = v1 - mean, d2 = v2 - mean;
    float s2 = d0 * d0 + d1 * d1 + d2 * d2;
    #pragma unroll
    for (int o = 16; o; o >>= 1) s2 += __shfl_xor_sync(0xffffffffu, s2, o);
    if (lane == 0) sh[wid] = s2;
    __syncthreads();
    if (wid == 0) {
        float t2 = (lane < 8) ? sh[lane] : 0.0f;
        #pragma unroll
        for (int o = 4; o; o >>= 1) t2 += __shfl_xor_sync(0xffffffffu, t2, o);
        if (lane == 0) sh[0] = t2;
    }
    __syncthreads();
    float inv = rsqrtf(sh[0] * (1.0f / 768.0f) + 1e-5f);
    size_t ob = (size_t)m * CC;
    #pragma unroll
    for (int p = 0; p < 3; p++) {
        float d = (p == 0) ? d0 : (p == 1) ? d1 : d2;
        int c = tid + p * 256;
        float v = d * inv * g[c] + bta[c];
        __half h, l;
        f2hl(v, h, l);
        oh[ob + c] = h;
        ol[ob + c] = l;
    }
}

// ---------------------------------------------------------------------------
// Temporal attention: fused per (seq, head). Padded smem (conflict-free).
// ---------------------------------------------------------------------------
__global__ void temporal_attn(const float* __restrict__ qkv,
                              __half* __restrict__ oh,
                              __half* __restrict__ ol)
{
    int seq = blockIdx.x, h = blockIdx.y;
    __shared__ float q[TT][HD + 1], k[TT][HD + 1], v[TT][HD + 1], p[TT][TT];
    int tid = threadIdx.x;
    size_t base = (size_t)(seq * TT) * C3 + h * HD;
    #pragma unroll
    for (int t = 0; t < TT; t++) {
        q[t][tid] = qkv[base + (size_t)t * C3 + tid];
        k[t][tid] = qkv[base + (size_t)t * C3 + CC + tid];
        v[t][tid] = qkv[base + (size_t)t * C3 + 2 * CC + tid];
    }
    __syncthreads();
    int i = tid >> 3, j = tid & 7;
    float s = 0.0f;
    #pragma unroll
    for (int d = 0; d < HD; d++) s = fmaf(q[i][d], k[j][d], s);
    p[i][j] = s * 0.125f;
    __syncthreads();
    if (tid < TT) {
        float mx = -1e30f;
        #pragma unroll
        for (int jj = 0; jj < TT; jj++) mx = fmaxf(mx, p[tid][jj]);
        float sum = 0.0f;
        #pragma unroll
        for (int jj = 0; jj < TT; jj++) {
            float e = expf(p[tid][jj] - mx);
            p[tid][jj] = e; sum += e;
        }
        float invs = 1.0f / sum;
        #pragma unroll
        for (int jj = 0; jj < TT; jj++) p[tid][jj] *= invs;
    }
    __syncthreads();
    #pragma unroll
    for (int t = 0; t < TT; t++) {
        float o = 0.0f;
        #pragma unroll
        for (int jj = 0; jj < TT; jj++) o = fmaf(p[t][jj], v[jj][tid], o);
        __half hh, ll;
        f2hl(o, hh, ll);
        size_t oi = (size_t)(seq * TT + t) * CC + h * HD + tid;
        oh[oi] = hh;
        ol[oi] = ll;
    }
}

// ---------------------------------------------------------------------------
// Softmax over rows of length 197 (scale already folded into scores).
// Writes hi/lo fp16 P into KP-padded layout, zeroing the tail.
// ---------------------------------------------------------------------------
__global__ void softmax197(const float* __restrict__ sc,
                           __half* __restrict__ ph, __half* __restrict__ pl,
                           int nrows)
{
    int row = blockIdx.x * 8 + (threadIdx.x >> 5);
    if (row >= nrows) return;
    int lane = threadIdx.x & 31;
    const float* r = sc + (size_t)row * SL;
    size_t ob = (size_t)row * KP;
    float mx = -1e30f;
    for (int j = lane; j < SL; j += 32) mx = fmaxf(mx, r[j]);
    #pragma unroll
    for (int o = 16; o; o >>= 1) mx = fmaxf(mx, __shfl_xor_sync(0xffffffffu, mx, o));
    float sum = 0.0f;
    float ev[7];
    #pragma unroll
    for (int q = 0; q < 7; q++) {
        int j = lane + q * 32;
        float e = (j < SL) ? expf(r[j] - mx) : 0.0f;
        ev[q] = e; sum += e;
    }
    #pragma unroll
    for (int o = 16; o; o >>= 1) sum += __shfl_xor_sync(0xffffffffu, sum, o);
    float inv = 1.0f / sum;
    #pragma unroll
    for (int q = 0; q < 7; q++) {
        int j = lane + q * 32;
        float pv = (j < SL) ? ev[q] * inv : 0.0f;   // tail [197,224) zeroed
        __half h, l;
        f2hl(pv, h, l);
        ph[ob + j] = h;
        pl[ob + j] = l;
    }
}

// ---------------------------------------------------------------------------
// Assemble x_new into d_out
// ---------------------------------------------------------------------------
__global__ void assemble(const float* __restrict__ x, const float* __restrict__ xt,
                         const float* __restrict__ ps, float* __restrict__ out)
{
    int row = blockIdx.x;
    int b = row / NTOK, n = row % NTOK;
    size_t orow = (size_t)row * CC;
    if (n == 0) {
        for (int c = threadIdx.x; c < CC; c += 256) {
            float acc = 0.0f;
            #pragma unroll
            for (int t = 0; t < TT; t++)
                acc += ps[((size_t)(b * TT + t) * SL) * CC + c];
            out[orow + c] = x[orow + c] + acc * 0.125f;
        }
    } else {
        int r = n - 1, hw = r >> 3, t = r & 7;
        size_t xtrow = ((size_t)b * 1568 + r) * CC;
        size_t psrow = ((size_t)((b * TT + t) * SL + 1 + hw)) * CC;
        for (int c = threadIdx.x; c < CC; c += 256)
            out[orow + c] = xt[xtrow + c] + ps[psrow + c];
    }
}

// ---------------------------------------------------------------------------
// Host launch
// ---------------------------------------------------------------------------
extern "C" void kernel_launch(void* const* d_in, const int* in_sizes, int n_in,
                              void* d_out, int out_size)
{
    const float* x        = (const float*)d_in[0];
    const float* ln_t_g   = (const float*)d_in[1];
    const float* ln_t_b   = (const float*)d_in[2];
    const float* t_qkv_w  = (const float*)d_in[3];
    const float* t_qkv_b  = (const float*)d_in[4];
    const float* t_proj_w = (const float*)d_in[5];
    const float* t_proj_b = (const float*)d_in[6];
    const float* t_fc_w   = (const float*)d_in[7];
    const float* t_fc_b   = (const float*)d_in[8];
    const float* ln1_g    = (const float*)d_in[9];
    const float* ln1_b    = (const float*)d_in[10];
    const float* s_qkv_w  = (const float*)d_in[11];
    const float* s_qkv_b  = (const float*)d_in[12];
    const float* s_proj_w = (const float*)d_in[13];
    const float* s_proj_b = (const float*)d_in[14];
    const float* ln2_g    = (const float*)d_in[15];
    const float* ln2_b    = (const float*)d_in[16];
    const float* fc1_w    = (const float*)d_in[17];
    const float* fc1_b    = (const float*)d_in[18];
    const float* fc2_w    = (const float*)d_in[19];
    const float* fc2_b    = (const float*)d_in[20];
    float* out = (float*)d_out;

    float *qkv, *xt, *sc, *proj;
    __half *lnh, *lnl, *ath, *atl, *pjh, *pjl, *f1h, *f1l;
    __half *qsh, *qsl, *ph, *pl, *vth, *vtl;
    cudaGetSymbolAddress((void**)&qkv,  g_qkv);
    cudaGetSymbolAddress((void**)&xt,   g_xt);
    cudaGetSymbolAddress((void**)&sc,   g_sc);
    cudaGetSymbolAddress((void**)&proj, g_proj);
    cudaGetSymbolAddress((void**)&lnh,  g_ln_h);
    cudaGetSymbolAddress((void**)&lnl,  g_ln_l);
    cudaGetSymbolAddress((void**)&ath,  g_at_h);
    cudaGetSymbolAddress((void**)&atl,  g_at_l);
    cudaGetSymbolAddress((void**)&pjh,  g_pj_h);
    cudaGetSymbolAddress((void**)&pjl,  g_pj_l);
    cudaGetSymbolAddress((void**)&f1h,  g_f1_h);
    cudaGetSymbolAddress((void**)&f1l,  g_f1_l);
    cudaGetSymbolAddress((void**)&qsh,  g_qs_h);
    cudaGetSymbolAddress((void**)&qsl,  g_qs_l);
    cudaGetSymbolAddress((void**)&ph,   g_p_h);
    cudaGetSymbolAddress((void**)&pl,   g_p_l);
    cudaGetSymbolAddress((void**)&vth,  g_vt_h);
    cudaGetSymbolAddress((void**)&vtl,  g_vt_l);

    __half *wtq, *wtp, *wtf, *wsq, *wsp, *wf1, *wf2;
    cudaGetSymbolAddress((void**)&wtq, g_wtq);
    cudaGetSymbolAddress((void**)&wtp, g_wtp);
    cudaGetSymbolAddress((void**)&wtf, g_wtf);
    cudaGetSymbolAddress((void**)&wsq, g_wsq);
    cudaGetSymbolAddress((void**)&wsp, g_wsp);
    cudaGetSymbolAddress((void**)&wf1, g_wf1);
    cudaGetSymbolAddress((void**)&wf2, g_wf2);

    cudaFuncSetAttribute(gemm_mma<0,0>, cudaFuncAttributeMaxDynamicSharedMemorySize, GEMM_SMEM);
    cudaFuncSetAttribute(gemm_mma<0,1>, cudaFuncAttributeMaxDynamicSharedMemorySize, GEMM_SMEM);
    cudaFuncSetAttribute(gemm_mma<1,1>, cudaFuncAttributeMaxDynamicSharedMemorySize, GEMM_SMEM);
    cudaFuncSetAttribute(gemm_mma<2,0>, cudaFuncAttributeMaxDynamicSharedMemorySize, GEMM_SMEM);
    cudaFuncSetAttribute(gemm_mma<3,0>, cudaFuncAttributeMaxDynamicSharedMemorySize, GEMM_SMEM);
    cudaFuncSetAttribute(attn_scores_mma, cudaFuncAttributeMaxDynamicSharedMemorySize, SC_SMEM);
    cudaFuncSetAttribute(attn_pv_mma, cudaFuncAttributeMaxDynamicSharedMemorySize, PV_SMEM);

    // 0. convert all weights in one launch (single fp16)
    {
        WSegs w;
        w.src[0] = (const float4*)t_qkv_w;  w.dh[0] = (__half2*)wtq; w.n4[0] = C3 * CC / 4;
        w.src[1] = (const float4*)t_proj_w; w.dh[1] = (__half2*)wtp; w.n4[1] = CC * CC / 4;
        w.src[2] = (const float4*)t_fc_w;   w.dh[2] = (__half2*)wtf; w.n4[2] = CC * CC / 4;
        w.src[3] = (const float4*)s_qkv_w;  w.dh[3] = (__half2*)wsq; w.n4[3] = C3 * CC / 4;
        w.src[4] = (const float4*)s_proj_w; w.dh[4] = (__half2*)wsp; w.n4[4] = CC * CC / 4;
        w.src[5] = (const float4*)fc1_w;    w.dh[5] = (__half2*)wf1; w.n4[5] = HIDDEN * CC / 4;
        w.src[6] = (const float4*)fc2_w;    w.dh[6] = (__half2*)wf2; w.n4[6] = CC * HIDDEN / 4;
        int total4 = 0;
        for (int i = 0; i < 7; i++) total4 += w.n4[i];
        conv_all<<<(total4 + 255) / 256, 256>>>(w, total4);
    }

    // 1. temporal LN (skip cls) -> hi/lo
    ln_kernel<<<MT, 256>>>(x, nullptr, ln_t_g, ln_t_b, lnh, lnl, 0);

    // 2. temporal qkv -> fp32
    gemm_mma<0,0><<<dim3(C3/128, (MT+127)/128), 256, GEMM_SMEM>>>(
        lnh, lnl, wtq, t_qkv_b, qkv, nullptr, nullptr, nullptr, MT, C3, CC);

    // 3. temporal attention -> hi/lo
    temporal_attn<<<dim3(BB * HW, NH), 64>>>(qkv, ath, atl);

    // 4. temporal proj -> hi/lo
    gemm_mma<0,1><<<dim3(CC/128, (MT+127)/128), 256, GEMM_SMEM>>>(
        ath, atl, wtp, t_proj_b, nullptr, pjh, pjl, nullptr, MT, CC, CC);

    // 5. t_fc + residual from x (skip-cls) -> fp32 xt
    gemm_mma<2,0><<<dim3(CC/128, (MT+127)/128), 256, GEMM_SMEM>>>(
        pjh, pjl, wtf, t_fc_b, xt, nullptr, nullptr, x, MT, CC, CC);

    // 6. spatial gather + LN1 -> hi/lo
    ln_kernel<<<MS, 256>>>(x, xt, ln1_g, ln1_b, lnh, lnl, 1);

    // 7. spatial qkv -> hi/lo fp16
    gemm_mma<0,1><<<dim3(C3/128, (MS+127)/128), 256, GEMM_SMEM>>>(
        lnh, lnl, wsq, s_qkv_b, nullptr, qsh, qsl, nullptr, MS, C3, CC);

    // 8-10. spatial attention (tensor cores)
    attn_scores_mma<<<dim3(2, 2, ZB), 256, SC_SMEM>>>(qsh, qsl, sc);
    transpose_v<<<ZB, 256>>>(qsh, qsl, vth, vtl);
    softmax197<<<(ZB * SL + 7) / 8, 256>>>(sc, ph, pl, ZB * SL);
    attn_pv_mma<<<dim3(2, ZB), 256, PV_SMEM>>>(ph, pl, vth, vtl, ath, atl);

    // 11. spatial proj -> fp32
    gemm_mma<0,0><<<dim3(CC/128, (MS+127)/128), 256, GEMM_SMEM>>>(
        ath, atl, wsp, s_proj_b, proj, nullptr, nullptr, nullptr, MS, CC, CC);

    // 12. assemble x_new into d_out
    assemble<<<MX, 256>>>(x, xt, proj, out);

    // 13. LN2 -> hi/lo
    ln_kernel<<<MX, 256>>>(out, nullptr, ln2_g, ln2_b, lnh, lnl, 2);

    // 14. fc1 + gelu -> hi/lo
    gemm_mma<1,1><<<dim3(HIDDEN/128, (MX+127)/128), 256, GEMM_SMEM>>>(
        lnh, lnl, wf1, fc1_b, nullptr, f1h, f1l, nullptr, MX, HIDDEN, CC);

    // 15. fc2 + in-place residual on d_out
    gemm_mma<3,0><<<dim3(CC/128, (MX+127)/128), 256, GEMM_SMEM>>>(
        f1h, f1l, wf2, fc2_b, out, nullptr, nullptr, nullptr, MX, CC, HIDDEN);
}

// round 9
// speedup vs baseline: 1.4793x; 1.0583x over previous
#include <cuda_runtime.h>
#include <cuda_fp16.h>
#include <math.h>
#include <stdint.h>

// ---------------------------------------------------------------------------
// Problem constants
// ---------------------------------------------------------------------------
#define CC     768
#define C3     2304
#define NH     12
#define HD     64
#define HIDDEN 3072
#define TT     8
#define HW     196
#define BB     4
#define NTOK   1569
#define MT     6272
#define MS     6304
#define MX     6276
#define SL     197
#define SB     32
#define ZB     (SB*NH)
#define SL2    (SL*SL)
#define KP     224          // padded K for P/Vt (7 * 32)

// ---------------------------------------------------------------------------
// Static device scratch
// ---------------------------------------------------------------------------
__device__ float g_qkv [(size_t)MT * C3];      // fp32 qkv (temporal attention)
__device__ float g_xt  [(size_t)MT * CC];
__device__ float g_sc  [(size_t)ZB * SL2];     // fp32 spatial scores
__device__ float g_proj[(size_t)MS * CC];

// activation hi/lo fp16
__device__ __half g_ln_h[(size_t)MS * CC];
__device__ __half g_ln_l[(size_t)MS * CC];
__device__ __half g_at_h[(size_t)MS * CC];
__device__ __half g_at_l[(size_t)MS * CC];
__device__ __half g_pj_h[(size_t)MT * CC];
__device__ __half g_pj_l[(size_t)MT * CC];
__device__ __half g_f1_h[(size_t)MX * HIDDEN];
__device__ __half g_f1_l[(size_t)MX * HIDDEN];

// spatial qkv hi/lo fp16
__device__ __half g_qs_h[(size_t)MS * C3];
__device__ __half g_qs_l[(size_t)MS * C3];
// softmax P hi/lo (K-padded to 224)
__device__ __half g_p_h[(size_t)ZB * SL * KP];
__device__ __half g_p_l[(size_t)ZB * SL * KP];
// V transposed hi/lo [z][64][224]
__device__ __half g_vt_h[(size_t)ZB * HD * KP];
__device__ __half g_vt_l[(size_t)ZB * HD * KP];

// weights: single fp16
__device__ __half g_wtq[(size_t)C3 * CC];
__device__ __half g_wtp[(size_t)CC * CC];
__device__ __half g_wtf[(size_t)CC * CC];
__device__ __half g_wsq[(size_t)C3 * CC];
__device__ __half g_wsp[(size_t)CC * CC];
__device__ __half g_wf1[(size_t)HIDDEN * CC];
__device__ __half g_wf2[(size_t)CC * HIDDEN];

// ---------------------------------------------------------------------------
// Helpers
// ---------------------------------------------------------------------------
__device__ __forceinline__ float gelu_exact(float v) {
    return 0.5f * v * (1.0f + erff(v * 0.7071067811865475f));
}

__device__ __forceinline__ void f2hl(float x, __half& h, __half& l) {
    h = __float2half_rn(x);
    l = __float2half_rn(x - __half2float(h));
}

__device__ __forceinline__ uint32_t smem_u32(const void* p) {
    uint32_t a;
    asm("{ .reg .u64 t; cvta.to.shared.u64 t, %1; cvt.u32.u64 %0, t; }" : "=r"(a) : "l"(p));
    return a;
}

__device__ __forceinline__ void cpasync16(uint32_t dst, const void* src) {
    asm volatile("cp.async.cg.shared.global [%0], [%1], 16;" :: "r"(dst), "l"(src));
}
#define CP_COMMIT() asm volatile("cp.async.commit_group;" ::: "memory")
#define CP_WAIT0()  asm volatile("cp.async.wait_group 0;" ::: "memory")
#define CP_WAIT1()  asm volatile("cp.async.wait_group 1;" ::: "memory")

__device__ __forceinline__ void ldm4(uint32_t* r, uint32_t addr) {
    asm volatile("ldmatrix.sync.aligned.m8n8.x4.shared.b16 {%0,%1,%2,%3}, [%4];"
                 : "=r"(r[0]), "=r"(r[1]), "=r"(r[2]), "=r"(r[3]) : "r"(addr));
}

__device__ __forceinline__ void mma16816(float* d, const uint32_t* a, const uint32_t* b) {
    asm volatile(
        "mma.sync.aligned.m16n8k16.row.col.f32.f16.f16.f32 "
        "{%0,%1,%2,%3}, {%4,%5,%6,%7}, {%8,%9}, {%0,%1,%2,%3};"
        : "+f"(d[0]), "+f"(d[1]), "+f"(d[2]), "+f"(d[3])
        : "r"(a[0]), "r"(a[1]), "r"(a[2]), "r"(a[3]), "r"(b[0]), "r"(b[1]));
}

// ---------------------------------------------------------------------------
// Split-fp16 HMMA NT GEMM. CTA 128x128, 8 warps (64Mx32N), k-step 32,
// THREE-stage cp.async pipeline (wait_group 1).
// ---------------------------------------------------------------------------
#define STG    30720u
#define OFF_AH 0u
#define OFF_AL 10240u
#define OFF_B  20480u
#define GEMM_SMEM (3 * STG)

template<int EPI, int OUT>
__global__ void __launch_bounds__(256)
gemm_mma(const __half* __restrict__ Ahg, const __half* __restrict__ Alg,
         const __half* __restrict__ Bg,
         const float* __restrict__ bias,
         float* __restrict__ C,
         __half* __restrict__ Ch, __half* __restrict__ Cl,
         const float* __restrict__ resid,
         int M, int N, int K)
{
    extern __shared__ char smem[];
    const uint32_t sb = smem_u32(smem);

    const int tid  = threadIdx.x;
    const int wid  = tid >> 5;
    const int lane = tid & 31;
    const int row0 = blockIdx.y * 128;
    const int col0 = blockIdx.x * 128;
    const int KT   = K >> 5;

    float acc[4][4][4];
    #pragma unroll
    for (int a = 0; a < 4; a++)
        #pragma unroll
        for (int b = 0; b < 4; b++)
            #pragma unroll
            for (int c = 0; c < 4; c++) acc[a][b][c] = 0.0f;

    auto load_stage = [&](int kt, int buf) {
        const int kw = kt * 32;
        const uint32_t dstb = sb + buf * STG;
        #pragma unroll
        for (int q = 0; q < 4; q++) {
            int cid = q * 256 + tid;
            int arr = cid >> 9;
            int idx = cid & 511;
            int row = idx >> 2, ch = idx & 3;
            int ar  = min(row0 + row, M - 1);
            const __half* src = (arr ? Alg : Ahg) + (size_t)ar * K + kw + ch * 8;
            cpasync16(dstb + (arr ? OFF_AL : OFF_AH) + row * 80u + ch * 16u, src);
        }
        #pragma unroll
        for (int q = 0; q < 2; q++) {
            int cid = q * 256 + tid;
            int row = cid >> 2, ch = cid & 3;
            const __half* src = Bg + (size_t)(col0 + row) * K + kw + ch * 8;
            cpasync16(dstb + OFF_B + row * 80u + ch * 16u, src);
        }
        CP_COMMIT();
    };

    load_stage(0, 0);
    load_stage(1, 1);           // KT >= 24 at every call site
    CP_WAIT1();                 // stage 0 complete
    __syncthreads();

    const int m0w = (wid & 1) * 64;
    const int n0w = (wid >> 1) * 32;
    const uint32_t a_off = (uint32_t)(m0w + (lane & 15)) * 80u + (uint32_t)((lane >> 4) << 4);
    const uint32_t b_off = (uint32_t)(n0w + (lane & 7) + ((lane >> 4) << 3)) * 80u
                         + (uint32_t)(((lane >> 3) & 1) << 4);

    for (int kt = 0; kt < KT; kt++) {
        const int buf = kt % 3;
        const uint32_t bb = sb + buf * STG;
        #pragma unroll
        for (int s = 0; s < 2; s++) {
            uint32_t ah[4][4], al[4][4], bh[4][2];
            #pragma unroll
            for (int mi = 0; mi < 4; mi++) {
                ldm4(ah[mi], bb + OFF_AH + a_off + mi * 1280u + s * 32u);
                ldm4(al[mi], bb + OFF_AL + a_off + mi * 1280u + s * 32u);
            }
            #pragma unroll
            for (int nj = 0; nj < 2; nj++) {
                uint32_t t[4];
                ldm4(t, bb + OFF_B + b_off + nj * 1280u + s * 32u);
                bh[nj*2][0] = t[0]; bh[nj*2][1] = t[1];
                bh[nj*2+1][0] = t[2]; bh[nj*2+1][1] = t[3];
            }
            #pragma unroll
            for (int mi = 0; mi < 4; mi++)
                #pragma unroll
                for (int nj = 0; nj < 4; nj++) {
                    mma16816(acc[mi][nj], ah[mi], bh[nj]);
                    mma16816(acc[mi][nj], al[mi], bh[nj]);
                }
        }
        if (kt + 2 < KT) {
            load_stage(kt + 2, (kt + 2) % 3);
            CP_WAIT1();         // stage kt+1 complete; kt+2 in flight
        } else {
            CP_WAIT0();         // drain tail
        }
        __syncthreads();
    }

    #pragma unroll
    for (int mi = 0; mi < 4; mi++) {
        const int rbase = row0 + m0w + mi * 16 + (lane >> 2);
        #pragma unroll
        for (int half = 0; half < 2; half++) {
            const int m = rbase + half * 8;
            if (m >= M) continue;
            #pragma unroll
            for (int nj = 0; nj < 4; nj++) {
                const int n = col0 + n0w + nj * 8 + (lane & 3) * 2;
                float v0 = acc[mi][nj][half * 2 + 0] + bias[n];
                float v1 = acc[mi][nj][half * 2 + 1] + bias[n + 1];
                if (EPI == 1) { v0 = gelu_exact(v0); v1 = gelu_exact(v1); }
                if (EPI == 2) {
                    const float* rs = resid + (size_t)(m + m / 1568 + 1) * CC + n;
                    v0 += rs[0]; v1 += rs[1];
                }
                if (OUT == 0) {
                    float* cp = C + (size_t)m * N + n;
                    if (EPI == 3) {
                        float2 old = *(const float2*)cp;
                        v0 += old.x; v1 += old.y;
                    }
                    float2 o = {v0, v1};
                    *(float2*)cp = o;
                } else {
                    __half h0, l0, h1, l1;
                    f2hl(v0, h0, l0);
                    f2hl(v1, h1, l1);
                    *(__half2*)(Ch + (size_t)m * N + n) = __halves2half2(h0, h1);
                    *(__half2*)(Cl + (size_t)m * N + n) = __halves2half2(l0, l1);
                }
            }
        }
    }
}

// ---------------------------------------------------------------------------
// Batched spatial scores via HMMA (Round-8, passing).
// ---------------------------------------------------------------------------
#define SSTG    40960u
#define SOFF_AH 0u
#define SOFF_AL 10240u
#define SOFF_BH 20480u
#define SOFF_BL 30720u
#define SC_SMEM (2 * SSTG)

__global__ void __launch_bounds__(256)
attn_scores_mma(const __half* __restrict__ qh, const __half* __restrict__ ql,
                float* __restrict__ sc)
{
    extern __shared__ char smem[];
    const uint32_t sb = smem_u32(smem);

    const int z = blockIdx.z;
    const int s = z / NH, h = z % NH;
    const size_t base = (size_t)(s * SL) * C3 + h * HD;

    const int tid  = threadIdx.x;
    const int wid  = tid >> 5;
    const int lane = tid & 31;
    const int row0 = blockIdx.y * 128;
    const int col0 = blockIdx.x * 128;

    float acc[4][4][4];
    #pragma unroll
    for (int a = 0; a < 4; a++)
        #pragma unroll
        for (int b = 0; b < 4; b++)
            #pragma unroll
            for (int c = 0; c < 4; c++) acc[a][b][c] = 0.0f;

    auto load_stage = [&](int kt, int buf) {
        const int kw = kt * 32;
        const uint32_t dstb = sb + buf * SSTG;
        #pragma unroll
        for (int q = 0; q < 8; q++) {
            int cid = q * 256 + tid;
            int side = cid >> 10;
            int rem  = cid & 1023;
            int arr  = rem >> 9;
            int idx  = rem & 511;
            int row  = idx >> 2, ch = idx & 3;
            int gr   = min((side ? col0 : row0) + row, SL - 1);
            const __half* srcb = arr ? ql : qh;
            const __half* src  = srcb + base + (size_t)gr * C3 + (side ? CC : 0) + kw + ch * 8;
            uint32_t off = side ? (arr ? SOFF_BL : SOFF_BH) : (arr ? SOFF_AL : SOFF_AH);
            cpasync16(dstb + off + row * 80u + ch * 16u, src);
        }
        CP_COMMIT();
    };

    load_stage(0, 0);
    CP_WAIT0();
    __syncthreads();

    const int m0w = (wid & 1) * 64;
    const int n0w = (wid >> 1) * 32;
    const uint32_t a_off = (uint32_t)(m0w + (lane & 15)) * 80u + (uint32_t)((lane >> 4) << 4);
    const uint32_t b_off = (uint32_t)(n0w + (lane & 7) + ((lane >> 4) << 3)) * 80u
                         + (uint32_t)(((lane >> 3) & 1) << 4);

    #pragma unroll
    for (int kt = 0; kt < 2; kt++) {
        const int buf = kt & 1;
        if (kt + 1 < 2) load_stage(kt + 1, buf ^ 1);

        const uint32_t bb = sb + buf * SSTG;
        #pragma unroll
        for (int s2 = 0; s2 < 2; s2++) {
            uint32_t ah[4][4], al[4][4], bh[4][2], bl[4][2];
            #pragma unroll
            for (int mi = 0; mi < 4; mi++) {
                ldm4(ah[mi], bb + SOFF_AH + a_off + mi * 1280u + s2 * 32u);
                ldm4(al[mi], bb + SOFF_AL + a_off + mi * 1280u + s2 * 32u);
            }
            #pragma unroll
            for (int nj = 0; nj < 2; nj++) {
                uint32_t t[4];
                ldm4(t, bb + SOFF_BH + b_off + nj * 1280u + s2 * 32u);
                bh[nj*2][0] = t[0]; bh[nj*2][1] = t[1];
                bh[nj*2+1][0] = t[2]; bh[nj*2+1][1] = t[3];
                ldm4(t, bb + SOFF_BL + b_off + nj * 1280u + s2 * 32u);
                bl[nj*2][0] = t[0]; bl[nj*2][1] = t[1];
                bl[nj*2+1][0] = t[2]; bl[nj*2+1][1] = t[3];
            }
            #pragma unroll
            for (int mi = 0; mi < 4; mi++)
                #pragma unroll
                for (int nj = 0; nj < 4; nj++) {
                    mma16816(acc[mi][nj], ah[mi], bh[nj]);
                    mma16816(acc[mi][nj], ah[mi], bl[nj]);
                    mma16816(acc[mi][nj], al[mi], bh[nj]);
                }
        }
        CP_WAIT0();
        __syncthreads();
    }

    float* S = sc + (size_t)z * SL2;
    #pragma unroll
    for (int mi = 0; mi < 4; mi++) {
        const int rbase = row0 + m0w + mi * 16 + (lane >> 2);
        #pragma unroll
        for (int half = 0; half < 2; half++) {
            const int m = rbase + half * 8;
            if (m >= SL) continue;
            #pragma unroll
            for (int nj = 0; nj < 4; nj++) {
                const int n = col0 + n0w + nj * 8 + (lane & 3) * 2;
                if (n < SL)     S[(size_t)m * SL + n]     = acc[mi][nj][half * 2 + 0] * 0.125f;
                if (n + 1 < SL) S[(size_t)m * SL + n + 1] = acc[mi][nj][half * 2 + 1] * 0.125f;
            }
        }
    }
}

// ---------------------------------------------------------------------------
// Batched PV via HMMA (Round-8, passing).
// ---------------------------------------------------------------------------
#define PSTG    30720u
#define POFF_AH 0u
#define POFF_AL 10240u
#define POFF_BH 20480u
#define POFF_BL 25600u
#define PV_SMEM (2 * PSTG)

__global__ void __launch_bounds__(256)
attn_pv_mma(const __half* __restrict__ ph, const __half* __restrict__ pl,
            const __half* __restrict__ vth, const __half* __restrict__ vtl,
            __half* __restrict__ oh, __half* __restrict__ ol)
{
    extern __shared__ char smem[];
    const uint32_t sb = smem_u32(smem);

    const int z = blockIdx.y;
    const int s = z / NH, h = z % NH;
    const size_t pbase = (size_t)z * SL * KP;
    const size_t vbase = (size_t)z * HD * KP;

    const int tid  = threadIdx.x;
    const int wid  = tid >> 5;
    const int lane = tid & 31;
    const int row0 = blockIdx.x * 128;

    float acc[2][4][4];
    #pragma unroll
    for (int a = 0; a < 2; a++)
        #pragma unroll
        for (int b = 0; b < 4; b++)
            #pragma unroll
            for (int c = 0; c < 4; c++) acc[a][b][c] = 0.0f;

    auto load_stage = [&](int kt, int buf) {
        const int kw = kt * 32;
        const uint32_t dstb = sb + buf * PSTG;
        #pragma unroll
        for (int q = 0; q < 4; q++) {
            int cid = q * 256 + tid;
            int arr = cid >> 9;
            int idx = cid & 511;
            int row = idx >> 2, ch = idx & 3;
            int gr  = min(row0 + row, SL - 1);
            const __half* src = (arr ? pl : ph) + pbase + (size_t)gr * KP + kw + ch * 8;
            cpasync16(dstb + (arr ? POFF_AL : POFF_AH) + row * 80u + ch * 16u, src);
        }
        #pragma unroll
        for (int q = 0; q < 2; q++) {
            int cid = q * 256 + tid;
            int arr = cid >> 8;
            int idx = cid & 255;
            int row = idx >> 2, ch = idx & 3;
            const __half* src = (arr ? vtl : vth) + vbase + (size_t)row * KP + kw + ch * 8;
            cpasync16(dstb + (arr ? POFF_BL : POFF_BH) + row * 80u + ch * 16u, src);
        }
        CP_COMMIT();
    };

    load_stage(0, 0);
    CP_WAIT0();
    __syncthreads();

    const int m0w = (wid & 3) * 32;
    const int n0w = (wid >> 2) * 32;
    const uint32_t a_off = (uint32_t)(m0w + (lane & 15)) * 80u + (uint32_t)((lane >> 4) << 4);
    const uint32_t b_off = (uint32_t)(n0w + (lane & 7) + ((lane >> 4) << 3)) * 80u
                         + (uint32_t)(((lane >> 3) & 1) << 4);

    for (int kt = 0; kt < KP / 32; kt++) {
        const int buf = kt & 1;
        if (kt + 1 < KP / 32) load_stage(kt + 1, buf ^ 1);

        const uint32_t bb = sb + buf * PSTG;
        #pragma unroll
        for (int s2 = 0; s2 < 2; s2++) {
            uint32_t ah[2][4], al[2][4], bh[4][2], bl[4][2];
            #pragma unroll
            for (int mi = 0; mi < 2; mi++) {
                ldm4(ah[mi], bb + POFF_AH + a_off + mi * 1280u + s2 * 32u);
                ldm4(al[mi], bb + POFF_AL + a_off + mi * 1280u + s2 * 32u);
            }
            #pragma unroll
            for (int nj = 0; nj < 2; nj++) {
                uint32_t t[4];
                ldm4(t, bb + POFF_BH + b_off + nj * 1280u + s2 * 32u);
                bh[nj*2][0] = t[0]; bh[nj*2][1] = t[1];
                bh[nj*2+1][0] = t[2]; bh[nj*2+1][1] = t[3];
                ldm4(t, bb + POFF_BL + b_off + nj * 1280u + s2 * 32u);
                bl[nj*2][0] = t[0]; bl[nj*2][1] = t[1];
                bl[nj*2+1][0] = t[2]; bl[nj*2+1][1] = t[3];
            }
            #pragma unroll
            for (int mi = 0; mi < 2; mi++)
                #pragma unroll
                for (int nj = 0; nj < 4; nj++) {
                    mma16816(acc[mi][nj], ah[mi], bh[nj]);
                    mma16816(acc[mi][nj], ah[mi], bl[nj]);
                    mma16816(acc[mi][nj], al[mi], bh[nj]);
                }
        }
        CP_WAIT0();
        __syncthreads();
    }

    #pragma unroll
    for (int mi = 0; mi < 2; mi++) {
        const int rbase = row0 + m0w + mi * 16 + (lane >> 2);
        #pragma unroll
        for (int half = 0; half < 2; half++) {
            const int m = rbase + half * 8;
            if (m >= SL) continue;
            size_t ob = (size_t)(s * SL + m) * CC + h * HD;
            #pragma unroll
            for (int nj = 0; nj < 4; nj++) {
                const int n = n0w + nj * 8 + (lane & 3) * 2;
                __half h0, l0, h1, l1;
                f2hl(acc[mi][nj][half * 2 + 0], h0, l0);
                f2hl(acc[mi][nj][half * 2 + 1], h1, l1);
                *(__half2*)(oh + ob + n) = __halves2half2(h0, h1);
                *(__half2*)(ol + ob + n) = __halves2half2(l0, l1);
            }
        }
    }
}

// ---------------------------------------------------------------------------
// V transpose: per z, Vt[d][t] = V[t][d], padded t->224 with zeros. hi+lo.
// ---------------------------------------------------------------------------
__global__ void transpose_v(const __half* __restrict__ qh, const __half* __restrict__ ql,
                            __half* __restrict__ vth, __half* __restrict__ vtl)
{
    int z = blockIdx.x;
    int s = z / NH, h = z % NH;
    size_t vbase = (size_t)(s * SL) * C3 + 2 * CC + h * HD;
    size_t obase = (size_t)z * HD * KP;
    __shared__ __half shh[32][66], shl[32][66];
    int tid = threadIdx.x;

    for (int t0 = 0; t0 < KP; t0 += 32) {
        #pragma unroll
        for (int i = 0; i < 8; i++) {
            int e = i * 256 + tid;
            int t = e >> 6, d = e & 63;
            int gt = t0 + t;
            if (gt < SL) {
                size_t gi = vbase + (size_t)gt * C3 + d;
                shh[t][d] = qh[gi];
                shl[t][d] = ql[gi];
            } else {
                shh[t][d] = __float2half(0.0f);
                shl[t][d] = __float2half(0.0f);
            }
        }
        __syncthreads();
        #pragma unroll
        for (int i = 0; i < 8; i++) {
            int e = i * 256 + tid;
            int d = e >> 5, t = e & 31;
            vth[obase + (size_t)d * KP + t0 + t] = shh[t][d];
            vtl[obase + (size_t)d * KP + t0 + t] = shl[t][d];
        }
        __syncthreads();
    }
}

// ---------------------------------------------------------------------------
// Fused weight conversion: all 7 weights -> single fp16, one launch.
// ---------------------------------------------------------------------------
struct WSegs {
    const float4* src[7];
    __half2*      dh[7];
    int           n4[7];
};

__global__ void conv_all(WSegs w, int total4)
{
    int i = blockIdx.x * blockDim.x + threadIdx.x;
    if (i >= total4) return;
    int rem = i;
    #pragma unroll
    for (int s = 0; s < 7; s++) {
        if (rem < w.n4[s]) {
            float4 v = w.src[s][rem];
            w.dh[s][rem * 2 + 0] = __halves2half2(__float2half_rn(v.x), __float2half_rn(v.y));
            w.dh[s][rem * 2 + 1] = __halves2half2(__float2half_rn(v.z), __float2half_rn(v.w));
            return;
        }
        rem -= w.n4[s];
    }
}

// ---------------------------------------------------------------------------
// LN core (shared by ln_kernel and assemble_ln): values v0,v1,v2 per thread.
// ---------------------------------------------------------------------------
__device__ __forceinline__ void ln_core(float v0, float v1, float v2,
                                        const float* __restrict__ g,
                                        const float* __restrict__ bta,
                                        __half* __restrict__ oh,
                                        __half* __restrict__ ol, size_t ob)
{
    int tid = threadIdx.x;
    int lane = tid & 31, wid = tid >> 5;
    __shared__ float sh[32];
    float s = v0 + v1 + v2;
    #pragma unroll
    for (int o = 16; o; o >>= 1) s += __shfl_xor_sync(0xffffffffu, s, o);
    if (lane == 0) sh[wid] = s;
    __syncthreads();
    if (wid == 0) {
        float t2 = (lane < 8) ? sh[lane] : 0.0f;
        #pragma unroll
        for (int o = 4; o; o >>= 1) t2 += __shfl_xor_sync(0xffffffffu, t2, o);
        if (lane == 0) sh[0] = t2;
    }
    __syncthreads();
    float mean = sh[0] * (1.0f / 768.0f);
    __syncthreads();
    float d0 = v0 - mean, d1 = v1 - mean, d2 = v2 - mean;
    float s2 = d0 * d0 + d1 * d1 + d2 * d2;
    #pragma unroll
    for (int o = 16; o; o >>= 1) s2 += __shfl_xor_sync(0xffffffffu, s2, o);
    if (lane == 0) sh[wid] = s2;
    __syncthreads();
    if (wid == 0) {
        float t2 = (lane < 8) ? sh[lane] : 0.0f;
        #pragma unroll
        for (int o = 4; o; o >>= 1) t2 += __shfl_xor_sync(0xffffffffu, t2, o);
        if (lane == 0) sh[0] = t2;
    }
    __syncthreads();
    float inv = rsqrtf(sh[0] * (1.0f / 768.0f) + 1e-5f);
    #pragma unroll
    for (int p = 0; p < 3; p++) {
        float d = (p == 0) ? d0 : (p == 1) ? d1 : d2;
        int c = tid + p * 256;
        float v = d * inv * g[c] + bta[c];
        __half h, l;
        f2hl(v, h, l);
        oh[ob + c] = h;
        ol[ob + c] = l;
    }
}

// ---------------------------------------------------------------------------
// LayerNorm (modes 0/1 gather). One block/row. Writes hi/lo fp16.
// ---------------------------------------------------------------------------
__global__ void ln_kernel(const float* __restrict__ src0,
                          const float* __restrict__ xt,
                          const float* __restrict__ g,
                          const float* __restrict__ bta,
                          __half* __restrict__ oh,
                          __half* __restrict__ ol, int mode)
{
    int m = blockIdx.x;
    const float* src;
    if (mode == 0) {
        src = src0 + (size_t)(m + m / 1568 + 1) * CC;
    } else {
        int sb = m / SL, p = m % SL;
        int b = sb >> 3, t = sb & 7;
        if (p == 0) src = src0 + (size_t)b * NTOK * CC;
        else        src = xt + ((size_t)(b * HW + (p - 1)) * TT + t) * CC;
    }
    int tid = threadIdx.x;
    float v0 = src[tid], v1 = src[tid + 256], v2 = src[tid + 512];
    ln_core(v0, v1, v2, g, bta, oh, ol, (size_t)m * CC);
}

// ---------------------------------------------------------------------------
// Fused assemble + LN2: computes x_new row into d_out AND its LayerNorm
// into hi/lo fp16 in one pass (values stay in registers).
// ---------------------------------------------------------------------------
__global__ void assemble_ln(const float* __restrict__ x, const float* __restrict__ xt,
                            const float* __restrict__ ps,
                            const float* __restrict__ g, const float* __restrict__ bta,
                            float* __restrict__ out,
                            __half* __restrict__ oh, __half* __restrict__ ol)
{
    int row = blockIdx.x;
    int b = row / NTOK, n = row % NTOK;
    size_t orow = (size_t)row * CC;
    int tid = threadIdx.x;
    float v[3];
    if (n == 0) {
        #pragma unroll
        for (int p = 0; p < 3; p++) {
            int c = tid + p * 256;
            float acc = 0.0f;
            #pragma unroll
            for (int t = 0; t < TT; t++)
                acc += ps[((size_t)(b * TT + t) * SL) * CC + c];
            v[p] = x[orow + c] + acc * 0.125f;
        }
    } else {
        int r = n - 1, hw = r >> 3, t = r & 7;
        size_t xtrow = ((size_t)b * 1568 + r) * CC;
        size_t psrow = ((size_t)((b * TT + t) * SL + 1 + hw)) * CC;
        #pragma unroll
        for (int p = 0; p < 3; p++) {
            int c = tid + p * 256;
            v[p] = xt[xtrow + c] + ps[psrow + c];
        }
    }
    #pragma unroll
    for (int p = 0; p < 3; p++)
        out[orow + tid + p * 256] = v[p];
    ln_core(v[0], v[1], v[2], g, bta, oh, ol, orow);
}

// ---------------------------------------------------------------------------
// Temporal attention: fused per (seq, head). Padded smem (conflict-free).
// ---------------------------------------------------------------------------
__global__ void temporal_attn(const float* __restrict__ qkv,
                              __half* __restrict__ oh,
                              __half* __restrict__ ol)
{
    int seq = blockIdx.x, h = blockIdx.y;
    __shared__ float q[TT][HD + 1], k[TT][HD + 1], v[TT][HD + 1], p[TT][TT];
    int tid = threadIdx.x;
    size_t base = (size_t)(seq * TT) * C3 + h * HD;
    #pragma unroll
    for (int t = 0; t < TT; t++) {
        q[t][tid] = qkv[base + (size_t)t * C3 + tid];
        k[t][tid] = qkv[base + (size_t)t * C3 + CC + tid];
        v[t][tid] = qkv[base + (size_t)t * C3 + 2 * CC + tid];
    }
    __syncthreads();
    int i = tid >> 3, j = tid & 7;
    float s = 0.0f;
    #pragma unroll
    for (int d = 0; d < HD; d++) s = fmaf(q[i][d], k[j][d], s);
    p[i][j] = s * 0.125f;
    __syncthreads();
    if (tid < TT) {
        float mx = -1e30f;
        #pragma unroll
        for (int jj = 0; jj < TT; jj++) mx = fmaxf(mx, p[tid][jj]);
        float sum = 0.0f;
        #pragma unroll
        for (int jj = 0; jj < TT; jj++) {
            float e = expf(p[tid][jj] - mx);
            p[tid][jj] = e; sum += e;
        }
        float invs = 1.0f / sum;
        #pragma unroll
        for (int jj = 0; jj < TT; jj++) p[tid][jj] *= invs;
    }
    __syncthreads();
    #pragma unroll
    for (int t = 0; t < TT; t++) {
        float o = 0.0f;
        #pragma unroll
        for (int jj = 0; jj < TT; jj++) o = fmaf(p[t][jj], v[jj][tid], o);
        __half hh, ll;
        f2hl(o, hh, ll);
        size_t oi = (size_t)(seq * TT + t) * CC + h * HD + tid;
        oh[oi] = hh;
        ol[oi] = ll;
    }
}

// ---------------------------------------------------------------------------
// Softmax over rows of length 197 -> hi/lo fp16 P, KP-padded, tail zeroed.
// ---------------------------------------------------------------------------
__global__ void softmax197(const float* __restrict__ sc,
                           __half* __restrict__ ph, __half* __restrict__ pl,
                           int nrows)
{
    int row = blockIdx.x * 8 + (threadIdx.x >> 5);
    if (row >= nrows) return;
    int lane = threadIdx.x & 31;
    const float* r = sc + (size_t)row * SL;
    size_t ob = (size_t)row * KP;
    float mx = -1e30f;
    for (int j = lane; j < SL; j += 32) mx = fmaxf(mx, r[j]);
    #pragma unroll
    for (int o = 16; o; o >>= 1) mx = fmaxf(mx, __shfl_xor_sync(0xffffffffu, mx, o));
    float sum = 0.0f;
    float ev[7];
    #pragma unroll
    for (int q = 0; q < 7; q++) {
        int j = lane + q * 32;
        float e = (j < SL) ? expf(r[j] - mx) : 0.0f;
        ev[q] = e; sum += e;
    }
    #pragma unroll
    for (int o = 16; o; o >>= 1) sum += __shfl_xor_sync(0xffffffffu, sum, o);
    float inv = 1.0f / sum;
    #pragma unroll
    for (int q = 0; q < 7; q++) {
        int j = lane + q * 32;
        float pv = (j < SL) ? ev[q] * inv : 0.0f;
        __half h, l;
        f2hl(pv, h, l);
        ph[ob + j] = h;
        pl[ob + j] = l;
    }
}

// ---------------------------------------------------------------------------
// Host launch
// ---------------------------------------------------------------------------
extern "C" void kernel_launch(void* const* d_in, const int* in_sizes, int n_in,
                              void* d_out, int out_size)
{
    const float* x        = (const float*)d_in[0];
    const float* ln_t_g   = (const float*)d_in[1];
    const float* ln_t_b   = (const float*)d_in[2];
    const float* t_qkv_w  = (const float*)d_in[3];
    const float* t_qkv_b  = (const float*)d_in[4];
    const float* t_proj_w = (const float*)d_in[5];
    const float* t_proj_b = (const float*)d_in[6];
    const float* t_fc_w   = (const float*)d_in[7];
    const float* t_fc_b   = (const float*)d_in[8];
    const float* ln1_g    = (const float*)d_in[9];
    const float* ln1_b    = (const float*)d_in[10];
    const float* s_qkv_w  = (const float*)d_in[11];
    const float* s_qkv_b  = (const float*)d_in[12];
    const float* s_proj_w = (const float*)d_in[13];
    const float* s_proj_b = (const float*)d_in[14];
    const float* ln2_g    = (const float*)d_in[15];
    const float* ln2_b    = (const float*)d_in[16];
    const float* fc1_w    = (const float*)d_in[17];
    const float* fc1_b    = (const float*)d_in[18];
    const float* fc2_w    = (const float*)d_in[19];
    const float* fc2_b    = (const float*)d_in[20];
    float* out = (float*)d_out;

    float *qkv, *xt, *sc, *proj;
    __half *lnh, *lnl, *ath, *atl, *pjh, *pjl, *f1h, *f1l;
    __half *qsh, *qsl, *ph, *pl, *vth, *vtl;
    cudaGetSymbolAddress((void**)&qkv,  g_qkv);
    cudaGetSymbolAddress((void**)&xt,   g_xt);
    cudaGetSymbolAddress((void**)&sc,   g_sc);
    cudaGetSymbolAddress((void**)&proj, g_proj);
    cudaGetSymbolAddress((void**)&lnh,  g_ln_h);
    cudaGetSymbolAddress((void**)&lnl,  g_ln_l);
    cudaGetSymbolAddress((void**)&ath,  g_at_h);
    cudaGetSymbolAddress((void**)&atl,  g_at_l);
    cudaGetSymbolAddress((void**)&pjh,  g_pj_h);
    cudaGetSymbolAddress((void**)&pjl,  g_pj_l);
    cudaGetSymbolAddress((void**)&f1h,  g_f1_h);
    cudaGetSymbolAddress((void**)&f1l,  g_f1_l);
    cudaGetSymbolAddress((void**)&qsh,  g_qs_h);
    cudaGetSymbolAddress((void**)&qsl,  g_qs_l);
    cudaGetSymbolAddress((void**)&ph,   g_p_h);
    cudaGetSymbolAddress((void**)&pl,   g_p_l);
    cudaGetSymbolAddress((void**)&vth,  g_vt_h);
    cudaGetSymbolAddress((void**)&vtl,  g_vt_l);

    __half *wtq, *wtp, *wtf, *wsq, *wsp, *wf1, *wf2;
    cudaGetSymbolAddress((void**)&wtq, g_wtq);
    cudaGetSymbolAddress((void**)&wtp, g_wtp);
    cudaGetSymbolAddress((void**)&wtf, g_wtf);
    cudaGetSymbolAddress((void**)&wsq, g_wsq);
    cudaGetSymbolAddress((void**)&wsp, g_wsp);
    cudaGetSymbolAddress((void**)&wf1, g_wf1);
    cudaGetSymbolAddress((void**)&wf2, g_wf2);

    cudaFuncSetAttribute(gemm_mma<0,0>, cudaFuncAttributeMaxDynamicSharedMemorySize, GEMM_SMEM);
    cudaFuncSetAttribute(gemm_mma<0,1>, cudaFuncAttributeMaxDynamicSharedMemorySize, GEMM_SMEM);
    cudaFuncSetAttribute(gemm_mma<1,1>, cudaFuncAttributeMaxDynamicSharedMemorySize, GEMM_SMEM);
    cudaFuncSetAttribute(gemm_mma<2,0>, cudaFuncAttributeMaxDynamicSharedMemorySize, GEMM_SMEM);
    cudaFuncSetAttribute(gemm_mma<3,0>, cudaFuncAttributeMaxDynamicSharedMemorySize, GEMM_SMEM);
    cudaFuncSetAttribute(attn_scores_mma, cudaFuncAttributeMaxDynamicSharedMemorySize, SC_SMEM);
    cudaFuncSetAttribute(attn_pv_mma, cudaFuncAttributeMaxDynamicSharedMemorySize, PV_SMEM);

    // 0. convert all weights in one launch (single fp16)
    {
        WSegs w;
        w.src[0] = (const float4*)t_qkv_w;  w.dh[0] = (__half2*)wtq; w.n4[0] = C3 * CC / 4;
        w.src[1] = (const float4*)t_proj_w; w.dh[1] = (__half2*)wtp; w.n4[1] = CC * CC / 4;
        w.src[2] = (const float4*)t_fc_w;   w.dh[2] = (__half2*)wtf; w.n4[2] = CC * CC / 4;
        w.src[3] = (const float4*)s_qkv_w;  w.dh[3] = (__half2*)wsq; w.n4[3] = C3 * CC / 4;
        w.src[4] = (const float4*)s_proj_w; w.dh[4] = (__half2*)wsp; w.n4[4] = CC * CC / 4;
        w.src[5] = (const float4*)fc1_w;    w.dh[5] = (__half2*)wf1; w.n4[5] = HIDDEN * CC / 4;
        w.src[6] = (const float4*)fc2_w;    w.dh[6] = (__half2*)wf2; w.n4[6] = CC * HIDDEN / 4;
        int total4 = 0;
        for (int i = 0; i < 7; i++) total4 += w.n4[i];
        conv_all<<<(total4 + 255) / 256, 256>>>(w, total4);
    }

    // 1. temporal LN (skip cls) -> hi/lo
    ln_kernel<<<MT, 256>>>(x, nullptr, ln_t_g, ln_t_b, lnh, lnl, 0);

    // 2. temporal qkv -> fp32
    gemm_mma<0,0><<<dim3(C3/128, (MT+127)/128), 256, GEMM_SMEM>>>(
        lnh, lnl, wtq, t_qkv_b, qkv, nullptr, nullptr, nullptr, MT, C3, CC);

    // 3. temporal attention -> hi/lo
    temporal_attn<<<dim3(BB * HW, NH), 64>>>(qkv, ath, atl);

    // 4. temporal proj -> hi/lo
    gemm_mma<0,1><<<dim3(CC/128, (MT+127)/128), 256, GEMM_SMEM>>>(
        ath, atl, wtp, t_proj_b, nullptr, pjh, pjl, nullptr, MT, CC, CC);

    // 5. t_fc + residual from x (skip-cls) -> fp32 xt
    gemm_mma<2,0><<<dim3(CC/128, (MT+127)/128), 256, GEMM_SMEM>>>(
        pjh, pjl, wtf, t_fc_b, xt, nullptr, nullptr, x, MT, CC, CC);

    // 6. spatial gather + LN1 -> hi/lo
    ln_kernel<<<MS, 256>>>(x, xt, ln1_g, ln1_b, lnh, lnl, 1);

    // 7. spatial qkv -> hi/lo fp16
    gemm_mma<0,1><<<dim3(C3/128, (MS+127)/128), 256, GEMM_SMEM>>>(
        lnh, lnl, wsq, s_qkv_b, nullptr, qsh, qsl, nullptr, MS, C3, CC);

    // 8-10. spatial attention (tensor cores)
    attn_scores_mma<<<dim3(2, 2, ZB), 256, SC_SMEM>>>(qsh, qsl, sc);
    transpose_v<<<ZB, 256>>>(qsh, qsl, vth, vtl);
    softmax197<<<(ZB * SL + 7) / 8, 256>>>(sc, ph, pl, ZB * SL);
    attn_pv_mma<<<dim3(2, ZB), 256, PV_SMEM>>>(ph, pl, vth, vtl, ath, atl);

    // 11. spatial proj -> fp32
    gemm_mma<0,0><<<dim3(CC/128, (MS+127)/128), 256, GEMM_SMEM>>>(
        ath, atl, wsp, s_proj_b, proj, nullptr, nullptr, nullptr, MS, CC, CC);

    // 12+13. assemble x_new into d_out AND LN2 -> hi/lo (fused)
    assemble_ln<<<MX, 256>>>(x, xt, proj, ln2_g, ln2_b, out, lnh, lnl);

    // 14. fc1 + gelu -> hi/lo
    gemm_mma<1,1><<<dim3(HIDDEN/128, (MX+127)/128), 256, GEMM_SMEM>>>(
        lnh, lnl, wf1, fc1_b, nullptr, f1h, f1l, nullptr, MX, HIDDEN, CC);

    // 15. fc2 + in-place residual on d_out
    gemm_mma<3,0><<<dim3(CC/128, (MX+127)/128), 256, GEMM_SMEM>>>(
        f1h, f1l, wf2, fc2_b, out, nullptr, nullptr, nullptr, MX, CC, HIDDEN);
}

// round 10
// speedup vs baseline: 1.5286x; 1.0333x over previous
#include <cuda_runtime.h>
#include <cuda_fp16.h>
#include <math.h>
#include <stdint.h>

// ---------------------------------------------------------------------------
// Problem constants
// ---------------------------------------------------------------------------
#define CC     768
#define C3     2304
#define NH     12
#define HD     64
#define HIDDEN 3072
#define TT     8
#define HW     196
#define BB     4
#define NTOK   1569
#define MT     6272
#define MS     6304
#define MX     6276
#define SL     197
#define SB     32
#define ZB     (SB*NH)
#define SL2    (SL*SL)
#define KP     224          // padded K for P/Vt (7 * 32)

// ---------------------------------------------------------------------------
// Static device scratch
// ---------------------------------------------------------------------------
__device__ float g_qkv [(size_t)MT * C3];      // fp32 qkv (temporal attention)
__device__ float g_xt  [(size_t)MT * CC];
__device__ float g_proj[(size_t)MS * CC];

// activation hi/lo fp16
__device__ __half g_ln_h[(size_t)MS * CC];
__device__ __half g_ln_l[(size_t)MS * CC];
__device__ __half g_at_h[(size_t)MS * CC];
__device__ __half g_at_l[(size_t)MS * CC];
__device__ __half g_pj_h[(size_t)MT * CC];
__device__ __half g_pj_l[(size_t)MT * CC];
__device__ __half g_f1_h[(size_t)MX * HIDDEN];
__device__ __half g_f1_l[(size_t)MX * HIDDEN];

// spatial qkv hi/lo fp16
__device__ __half g_qs_h[(size_t)MS * C3];
__device__ __half g_qs_l[(size_t)MS * C3];
// softmax P hi/lo (K-padded to 224)
__device__ __half g_p_h[(size_t)ZB * SL * KP];
__device__ __half g_p_l[(size_t)ZB * SL * KP];
// V transposed hi/lo [z][64][224]
__device__ __half g_vt_h[(size_t)ZB * HD * KP];
__device__ __half g_vt_l[(size_t)ZB * HD * KP];

// weights: single fp16
__device__ __half g_wtq[(size_t)C3 * CC];
__device__ __half g_wtp[(size_t)CC * CC];
__device__ __half g_wtf[(size_t)CC * CC];
__device__ __half g_wsq[(size_t)C3 * CC];
__device__ __half g_wsp[(size_t)CC * CC];
__device__ __half g_wf1[(size_t)HIDDEN * CC];
__device__ __half g_wf2[(size_t)CC * HIDDEN];

// ---------------------------------------------------------------------------
// Helpers
// ---------------------------------------------------------------------------
__device__ __forceinline__ float gelu_exact(float v) {
    return 0.5f * v * (1.0f + erff(v * 0.7071067811865475f));
}

__device__ __forceinline__ void f2hl(float x, __half& h, __half& l) {
    h = __float2half_rn(x);
    l = __float2half_rn(x - __half2float(h));
}

__device__ __forceinline__ uint32_t smem_u32(const void* p) {
    uint32_t a;
    asm("{ .reg .u64 t; cvta.to.shared.u64 t, %1; cvt.u32.u64 %0, t; }" : "=r"(a) : "l"(p));
    return a;
}

__device__ __forceinline__ void cpasync16(uint32_t dst, const void* src) {
    asm volatile("cp.async.cg.shared.global [%0], [%1], 16;" :: "r"(dst), "l"(src));
}
#define CP_COMMIT() asm volatile("cp.async.commit_group;" ::: "memory")
#define CP_WAIT0()  asm volatile("cp.async.wait_group 0;" ::: "memory")
#define CP_WAIT1()  asm volatile("cp.async.wait_group 1;" ::: "memory")

__device__ __forceinline__ void ldm4(uint32_t* r, uint32_t addr) {
    asm volatile("ldmatrix.sync.aligned.m8n8.x4.shared.b16 {%0,%1,%2,%3}, [%4];"
                 : "=r"(r[0]), "=r"(r[1]), "=r"(r[2]), "=r"(r[3]) : "r"(addr));
}

__device__ __forceinline__ void mma16816(float* d, const uint32_t* a, const uint32_t* b) {
    asm volatile(
        "mma.sync.aligned.m16n8k16.row.col.f32.f16.f16.f32 "
        "{%0,%1,%2,%3}, {%4,%5,%6,%7}, {%8,%9}, {%0,%1,%2,%3};"
        : "+f"(d[0]), "+f"(d[1]), "+f"(d[2]), "+f"(d[3])
        : "r"(a[0]), "r"(a[1]), "r"(a[2]), "r"(a[3]), "r"(b[0]), "r"(b[1]));
}

// ---------------------------------------------------------------------------
// Split-fp16 HMMA NT GEMM. CTA 128x128, 8 warps (64Mx32N), k-step 32,
// 3-stage cp.async pipeline (wait_group 1). Forced 2 CTAs/SM.
// ---------------------------------------------------------------------------
#define STG    30720u
#define OFF_AH 0u
#define OFF_AL 10240u
#define OFF_B  20480u
#define GEMM_SMEM (3 * STG)

template<int EPI, int OUT>
__global__ void __launch_bounds__(256, 2)
gemm_mma(const __half* __restrict__ Ahg, const __half* __restrict__ Alg,
         const __half* __restrict__ Bg,
         const float* __restrict__ bias,
         float* __restrict__ C,
         __half* __restrict__ Ch, __half* __restrict__ Cl,
         const float* __restrict__ resid,
         int M, int N, int K)
{
    extern __shared__ char smem[];
    const uint32_t sb = smem_u32(smem);

    const int tid  = threadIdx.x;
    const int wid  = tid >> 5;
    const int lane = tid & 31;
    const int row0 = blockIdx.y * 128;
    const int col0 = blockIdx.x * 128;
    const int KT   = K >> 5;

    float acc[4][4][4];
    #pragma unroll
    for (int a = 0; a < 4; a++)
        #pragma unroll
        for (int b = 0; b < 4; b++)
            #pragma unroll
            for (int c = 0; c < 4; c++) acc[a][b][c] = 0.0f;

    auto load_stage = [&](int kt, int buf) {
        const int kw = kt * 32;
        const uint32_t dstb = sb + buf * STG;
        #pragma unroll
        for (int q = 0; q < 4; q++) {
            int cid = q * 256 + tid;
            int arr = cid >> 9;
            int idx = cid & 511;
            int row = idx >> 2, ch = idx & 3;
            int ar  = min(row0 + row, M - 1);
            const __half* src = (arr ? Alg : Ahg) + (size_t)ar * K + kw + ch * 8;
            cpasync16(dstb + (arr ? OFF_AL : OFF_AH) + row * 80u + ch * 16u, src);
        }
        #pragma unroll
        for (int q = 0; q < 2; q++) {
            int cid = q * 256 + tid;
            int row = cid >> 2, ch = cid & 3;
            const __half* src = Bg + (size_t)(col0 + row) * K + kw + ch * 8;
            cpasync16(dstb + OFF_B + row * 80u + ch * 16u, src);
        }
        CP_COMMIT();
    };

    load_stage(0, 0);
    load_stage(1, 1);           // KT >= 24 at every call site
    CP_WAIT1();
    __syncthreads();

    const int m0w = (wid & 1) * 64;
    const int n0w = (wid >> 1) * 32;
    const uint32_t a_off = (uint32_t)(m0w + (lane & 15)) * 80u + (uint32_t)((lane >> 4) << 4);
    const uint32_t b_off = (uint32_t)(n0w + (lane & 7) + ((lane >> 4) << 3)) * 80u
                         + (uint32_t)(((lane >> 3) & 1) << 4);

    for (int kt = 0; kt < KT; kt++) {
        const int buf = kt % 3;
        const uint32_t bb = sb + buf * STG;
        #pragma unroll
        for (int s = 0; s < 2; s++) {
            uint32_t ah[4][4], al[4][4], bh[4][2];
            #pragma unroll
            for (int mi = 0; mi < 4; mi++) {
                ldm4(ah[mi], bb + OFF_AH + a_off + mi * 1280u + s * 32u);
                ldm4(al[mi], bb + OFF_AL + a_off + mi * 1280u + s * 32u);
            }
            #pragma unroll
            for (int nj = 0; nj < 2; nj++) {
                uint32_t t[4];
                ldm4(t, bb + OFF_B + b_off + nj * 1280u + s * 32u);
                bh[nj*2][0] = t[0]; bh[nj*2][1] = t[1];
                bh[nj*2+1][0] = t[2]; bh[nj*2+1][1] = t[3];
            }
            #pragma unroll
            for (int mi = 0; mi < 4; mi++)
                #pragma unroll
                for (int nj = 0; nj < 4; nj++) {
                    mma16816(acc[mi][nj], ah[mi], bh[nj]);
                    mma16816(acc[mi][nj], al[mi], bh[nj]);
                }
        }
        if (kt + 2 < KT) {
            load_stage(kt + 2, (kt + 2) % 3);
            CP_WAIT1();
        } else {
            CP_WAIT0();
        }
        __syncthreads();
    }

    #pragma unroll
    for (int mi = 0; mi < 4; mi++) {
        const int rbase = row0 + m0w + mi * 16 + (lane >> 2);
        #pragma unroll
        for (int half = 0; half < 2; half++) {
            const int m = rbase + half * 8;
            if (m >= M) continue;
            #pragma unroll
            for (int nj = 0; nj < 4; nj++) {
                const int n = col0 + n0w + nj * 8 + (lane & 3) * 2;
                float v0 = acc[mi][nj][half * 2 + 0] + bias[n];
                float v1 = acc[mi][nj][half * 2 + 1] + bias[n + 1];
                if (EPI == 1) { v0 = gelu_exact(v0); v1 = gelu_exact(v1); }
                if (EPI == 2) {
                    const float* rs = resid + (size_t)(m + m / 1568 + 1) * CC + n;
                    v0 += rs[0]; v1 += rs[1];
                }
                if (OUT == 0) {
                    float* cp = C + (size_t)m * N + n;
                    if (EPI == 3) {
                        float2 old = *(const float2*)cp;
                        v0 += old.x; v1 += old.y;
                    }
                    float2 o = {v0, v1};
                    *(float2*)cp = o;
                } else {
                    __half h0, l0, h1, l1;
                    f2hl(v0, h0, l0);
                    f2hl(v1, h1, l1);
                    *(__half2*)(Ch + (size_t)m * N + n) = __halves2half2(h0, h1);
                    *(__half2*)(Cl + (size_t)m * N + n) = __halves2half2(l0, l1);
                }
            }
        }
    }
}

// ---------------------------------------------------------------------------
// FUSED spatial scores + softmax. Per (row-block, z): computes S = Q*K^T*0.125
// for 128 rows x all 224 (padded) cols via HMMA (3 chains), row-softmax in
// registers (quad shuffles), writes P hi/lo to KP-padded layout (tail = 0).
// 8 warps; each warp owns 16 rows x 224 cols (28 n-tiles).
// smem: 2 k-step stages x (A 128x80x2 + B 224x80x2) = 2 x 56320 = 112640 B.
// ---------------------------------------------------------------------------
#define FSTG     56320u
#define FOFF_AH  0u
#define FOFF_AL  10240u
#define FOFF_BH  20480u
#define FOFF_BL  38400u
#define FSC_SMEM (2 * FSTG)

__global__ void __launch_bounds__(256)
attn_scores_softmax(const __half* __restrict__ qh, const __half* __restrict__ ql,
                    __half* __restrict__ ph, __half* __restrict__ pl)
{
    extern __shared__ char smem[];
    const uint32_t sb = smem_u32(smem);

    const int z = blockIdx.y;
    const int s = z / NH, h = z % NH;
    const size_t base  = (size_t)(s * SL) * C3 + h * HD;
    const size_t pbase = (size_t)z * SL * KP;

    const int tid  = threadIdx.x;
    const int wid  = tid >> 5;
    const int lane = tid & 31;
    const int row0 = blockIdx.x * 128;

    // load both k-steps (K=64) into the two stages
    #pragma unroll
    for (int kt = 0; kt < 2; kt++) {
        const int kw = kt * 32;
        const uint32_t dstb = sb + kt * FSTG;
        // A (Q): 2 arrays x 128 rows x 4 chunks = 1024
        #pragma unroll
        for (int q = 0; q < 4; q++) {
            int cid = q * 256 + tid;
            int arr = cid >> 9;
            int idx = cid & 511;
            int row = idx >> 2, ch = idx & 3;
            int gr  = min(row0 + row, SL - 1);
            const __half* src = (arr ? ql : qh) + base + (size_t)gr * C3 + kw + ch * 8;
            cpasync16(dstb + (arr ? FOFF_AL : FOFF_AH) + row * 80u + ch * 16u, src);
        }
        // B (K): 2 arrays x 224 rows x 4 chunks = 1792
        #pragma unroll
        for (int q = 0; q < 7; q++) {
            int cid = q * 256 + tid;
            int arr = cid >> 10;          // 0..1791: arr = cid/896? NO -- handle below
            (void)arr;
            int idx2 = cid;
            int arr2 = (idx2 >= 896) ? 1 : 0;
            int idx  = arr2 ? idx2 - 896 : idx2;
            int row = idx >> 2, ch = idx & 3;
            int gr  = min(row, SL - 1);
            const __half* src = (arr2 ? ql : qh) + base + (size_t)gr * C3 + CC + kw + ch * 8;
            cpasync16(dstb + (arr2 ? FOFF_BL : FOFF_BH) + row * 80u + ch * 16u, src);
        }
        CP_COMMIT();
    }
    CP_WAIT0();
    __syncthreads();

    const int m0w = wid * 16;
    const uint32_t a_off = (uint32_t)(m0w + (lane & 15)) * 80u + (uint32_t)((lane >> 4) << 4);
    const uint32_t b_off = (uint32_t)((lane & 7) + ((lane >> 4) << 3)) * 80u
                         + (uint32_t)(((lane >> 3) & 1) << 4);

    float acc[28][4];
    #pragma unroll
    for (int t = 0; t < 28; t++)
        #pragma unroll
        for (int c = 0; c < 4; c++) acc[t][c] = 0.0f;

    #pragma unroll
    for (int kt = 0; kt < 2; kt++) {
        const uint32_t bb = sb + kt * FSTG;
        #pragma unroll
        for (int s2 = 0; s2 < 2; s2++) {
            uint32_t ah[4], al[4];
            ldm4(ah, bb + FOFF_AH + a_off + s2 * 32u);
            ldm4(al, bb + FOFF_AL + a_off + s2 * 32u);
            #pragma unroll
            for (int njq = 0; njq < 14; njq++) {
                uint32_t th[4], tl[4];
                ldm4(th, bb + FOFF_BH + b_off + njq * 1280u + s2 * 32u);
                ldm4(tl, bb + FOFF_BL + b_off + njq * 1280u + s2 * 32u);
                uint32_t bh0[2] = {th[0], th[1]}, bh1[2] = {th[2], th[3]};
                uint32_t bl0[2] = {tl[0], tl[1]}, bl1[2] = {tl[2], tl[3]};
                mma16816(acc[njq*2],   ah, bh0);
                mma16816(acc[njq*2],   ah, bl0);
                mma16816(acc[njq*2],   al, bh0);
                mma16816(acc[njq*2+1], ah, bh1);
                mma16816(acc[njq*2+1], ah, bl1);
                mma16816(acc[njq*2+1], al, bh1);
            }
        }
    }

    // ---- softmax per row (two halves), quad-level reduction ----
    const int ncol0 = (lane & 3) * 2;
    #pragma unroll
    for (int half = 0; half < 2; half++) {
        const int row = row0 + m0w + (lane >> 2) + half * 8;
        // scale + mask, find max
        float mx = -1e30f;
        #pragma unroll
        for (int t = 0; t < 28; t++) {
            int n = t * 8 + ncol0;
            float v0 = acc[t][half*2+0] * 0.125f;
            float v1 = acc[t][half*2+1] * 0.125f;
            acc[t][half*2+0] = (n < SL)     ? v0 : -1e30f;
            acc[t][half*2+1] = (n + 1 < SL) ? v1 : -1e30f;
            mx = fmaxf(mx, acc[t][half*2+0]);
            mx = fmaxf(mx, acc[t][half*2+1]);
        }
        mx = fmaxf(mx, __shfl_xor_sync(0xffffffffu, mx, 1));
        mx = fmaxf(mx, __shfl_xor_sync(0xffffffffu, mx, 2));
        // exp + sum
        float sum = 0.0f;
        #pragma unroll
        for (int t = 0; t < 28; t++) {
            float e0 = expf(acc[t][half*2+0] - mx);
            float e1 = expf(acc[t][half*2+1] - mx);
            int n = t * 8 + ncol0;
            e0 = (n < SL)     ? e0 : 0.0f;
            e1 = (n + 1 < SL) ? e1 : 0.0f;
            acc[t][half*2+0] = e0;
            acc[t][half*2+1] = e1;
            sum += e0 + e1;
        }
        sum += __shfl_xor_sync(0xffffffffu, sum, 1);
        sum += __shfl_xor_sync(0xffffffffu, sum, 2);
        float inv = 1.0f / sum;
        // write P hi/lo (padding cols already 0)
        if (row < SL) {
            size_t ob = pbase + (size_t)row * KP;
            #pragma unroll
            for (int t = 0; t < 28; t++) {
                int n = t * 8 + ncol0;
                __half h0, l0, h1, l1;
                f2hl(acc[t][half*2+0] * inv, h0, l0);
                f2hl(acc[t][half*2+1] * inv, h1, l1);
                *(__half2*)(ph + ob + n) = __halves2half2(h0, h1);
                *(__half2*)(pl + ob + n) = __halves2half2(l0, l1);
            }
        }
    }
}

// ---------------------------------------------------------------------------
// Batched PV via HMMA (Round-8, passing).
// ---------------------------------------------------------------------------
#define PSTG    30720u
#define POFF_AH 0u
#define POFF_AL 10240u
#define POFF_BH 20480u
#define POFF_BL 25600u
#define PV_SMEM (2 * PSTG)

__global__ void __launch_bounds__(256)
attn_pv_mma(const __half* __restrict__ ph, const __half* __restrict__ pl,
            const __half* __restrict__ vth, const __half* __restrict__ vtl,
            __half* __restrict__ oh, __half* __restrict__ ol)
{
    extern __shared__ char smem[];
    const uint32_t sb = smem_u32(smem);

    const int z = blockIdx.y;
    const int s = z / NH, h = z % NH;
    const size_t pbase = (size_t)z * SL * KP;
    const size_t vbase = (size_t)z * HD * KP;

    const int tid  = threadIdx.x;
    const int wid  = tid >> 5;
    const int lane = tid & 31;
    const int row0 = blockIdx.x * 128;

    float acc[2][4][4];
    #pragma unroll
    for (int a = 0; a < 2; a++)
        #pragma unroll
        for (int b = 0; b < 4; b++)
            #pragma unroll
            for (int c = 0; c < 4; c++) acc[a][b][c] = 0.0f;

    auto load_stage = [&](int kt, int buf) {
        const int kw = kt * 32;
        const uint32_t dstb = sb + buf * PSTG;
        #pragma unroll
        for (int q = 0; q < 4; q++) {
            int cid = q * 256 + tid;
            int arr = cid >> 9;
            int idx = cid & 511;
            int row = idx >> 2, ch = idx & 3;
            int gr  = min(row0 + row, SL - 1);
            const __half* src = (arr ? pl : ph) + pbase + (size_t)gr * KP + kw + ch * 8;
            cpasync16(dstb + (arr ? POFF_AL : POFF_AH) + row * 80u + ch * 16u, src);
        }
        #pragma unroll
        for (int q = 0; q < 2; q++) {
            int cid = q * 256 + tid;
            int arr = cid >> 8;
            int idx = cid & 255;
            int row = idx >> 2, ch = idx & 3;
            const __half* src = (arr ? vtl : vth) + vbase + (size_t)row * KP + kw + ch * 8;
            cpasync16(dstb + (arr ? POFF_BL : POFF_BH) + row * 80u + ch * 16u, src);
        }
        CP_COMMIT();
    };

    load_stage(0, 0);
    CP_WAIT0();
    __syncthreads();

    const int m0w = (wid & 3) * 32;
    const int n0w = (wid >> 2) * 32;
    const uint32_t a_off = (uint32_t)(m0w + (lane & 15)) * 80u + (uint32_t)((lane >> 4) << 4);
    const uint32_t b_off = (uint32_t)(n0w + (lane & 7) + ((lane >> 4) << 3)) * 80u
                         + (uint32_t)(((lane >> 3) & 1) << 4);

    for (int kt = 0; kt < KP / 32; kt++) {
        const int buf = kt & 1;
        if (kt + 1 < KP / 32) load_stage(kt + 1, buf ^ 1);

        const uint32_t bb = sb + buf * PSTG;
        #pragma unroll
        for (int s2 = 0; s2 < 2; s2++) {
            uint32_t ah[2][4], al[2][4], bh[4][2], bl[4][2];
            #pragma unroll
            for (int mi = 0; mi < 2; mi++) {
                ldm4(ah[mi], bb + POFF_AH + a_off + mi * 1280u + s2 * 32u);
                ldm4(al[mi], bb + POFF_AL + a_off + mi * 1280u + s2 * 32u);
            }
            #pragma unroll
            for (int nj = 0; nj < 2; nj++) {
                uint32_t t[4];
                ldm4(t, bb + POFF_BH + b_off + nj * 1280u + s2 * 32u);
                bh[nj*2][0] = t[0]; bh[nj*2][1] = t[1];
                bh[nj*2+1][0] = t[2]; bh[nj*2+1][1] = t[3];
                ldm4(t, bb + POFF_BL + b_off + nj * 1280u + s2 * 32u);
                bl[nj*2][0] = t[0]; bl[nj*2][1] = t[1];
                bl[nj*2+1][0] = t[2]; bl[nj*2+1][1] = t[3];
            }
            #pragma unroll
            for (int mi = 0; mi < 2; mi++)
                #pragma unroll
                for (int nj = 0; nj < 4; nj++) {
                    mma16816(acc[mi][nj], ah[mi], bh[nj]);
                    mma16816(acc[mi][nj], ah[mi], bl[nj]);
                    mma16816(acc[mi][nj], al[mi], bh[nj]);
                }
        }
        CP_WAIT0();
        __syncthreads();
    }

    #pragma unroll
    for (int mi = 0; mi < 2; mi++) {
        const int rbase = row0 + m0w + mi * 16 + (lane >> 2);
        #pragma unroll
        for (int half = 0; half < 2; half++) {
            const int m = rbase + half * 8;
            if (m >= SL) continue;
            size_t ob = (size_t)(s * SL + m) * CC + h * HD;
            #pragma unroll
            for (int nj = 0; nj < 4; nj++) {
                const int n = n0w + nj * 8 + (lane & 3) * 2;
                __half h0, l0, h1, l1;
                f2hl(acc[mi][nj][half * 2 + 0], h0, l0);
                f2hl(acc[mi][nj][half * 2 + 1], h1, l1);
                *(__half2*)(oh + ob + n) = __halves2half2(h0, h1);
                *(__half2*)(ol + ob + n) = __halves2half2(l0, l1);
            }
        }
    }
}

// ---------------------------------------------------------------------------
// V transpose: per z, Vt[d][t] = V[t][d], padded t->224 with zeros. hi+lo.
// ---------------------------------------------------------------------------
__global__ void transpose_v(const __half* __restrict__ qh, const __half* __restrict__ ql,
                            __half* __restrict__ vth, __half* __restrict__ vtl)
{
    int z = blockIdx.x;
    int s = z / NH, h = z % NH;
    size_t vbase = (size_t)(s * SL) * C3 + 2 * CC + h * HD;
    size_t obase = (size_t)z * HD * KP;
    __shared__ __half shh[32][66], shl[32][66];
    int tid = threadIdx.x;

    for (int t0 = 0; t0 < KP; t0 += 32) {
        #pragma unroll
        for (int i = 0; i < 8; i++) {
            int e = i * 256 + tid;
            int t = e >> 6, d = e & 63;
            int gt = t0 + t;
            if (gt < SL) {
                size_t gi = vbase + (size_t)gt * C3 + d;
                shh[t][d] = qh[gi];
                shl[t][d] = ql[gi];
            } else {
                shh[t][d] = __float2half(0.0f);
                shl[t][d] = __float2half(0.0f);
            }
        }
        __syncthreads();
        #pragma unroll
        for (int i = 0; i < 8; i++) {
            int e = i * 256 + tid;
            int d = e >> 5, t = e & 31;
            vth[obase + (size_t)d * KP + t0 + t] = shh[t][d];
            vtl[obase + (size_t)d * KP + t0 + t] = shl[t][d];
        }
        __syncthreads();
    }
}

// ---------------------------------------------------------------------------
// Fused weight conversion: all 7 weights -> single fp16, one launch.
// ---------------------------------------------------------------------------
struct WSegs {
    const float4* src[7];
    __half2*      dh[7];
    int           n4[7];
};

__global__ void conv_all(WSegs w, int total4)
{
    int i = blockIdx.x * blockDim.x + threadIdx.x;
    if (i >= total4) return;
    int rem = i;
    #pragma unroll
    for (int s = 0; s < 7; s++) {
        if (rem < w.n4[s]) {
            float4 v = w.src[s][rem];
            w.dh[s][rem * 2 + 0] = __halves2half2(__float2half_rn(v.x), __float2half_rn(v.y));
            w.dh[s][rem * 2 + 1] = __halves2half2(__float2half_rn(v.z), __float2half_rn(v.w));
            return;
        }
        rem -= w.n4[s];
    }
}

// ---------------------------------------------------------------------------
// LN core: values v0,v1,v2 per thread.
// ---------------------------------------------------------------------------
__device__ __forceinline__ void ln_core(float v0, float v1, float v2,
                                        const float* __restrict__ g,
                                        const float* __restrict__ bta,
                                        __half* __restrict__ oh,
                                        __half* __restrict__ ol, size_t ob)
{
    int tid = threadIdx.x;
    int lane = tid & 31, wid = tid >> 5;
    __shared__ float sh[32];
    float s = v0 + v1 + v2;
    #pragma unroll
    for (int o = 16; o; o >>= 1) s += __shfl_xor_sync(0xffffffffu, s, o);
    if (lane == 0) sh[wid] = s;
    __syncthreads();
    if (wid == 0) {
        float t2 = (lane < 8) ? sh[lane] : 0.0f;
        #pragma unroll
        for (int o = 4; o; o >>= 1) t2 += __shfl_xor_sync(0xffffffffu, t2, o);
        if (lane == 0) sh[0] = t2;
    }
    __syncthreads();
    float mean = sh[0] * (1.0f / 768.0f);
    __syncthreads();
    float d0 = v0 - mean, d1 = v1 - mean, d2 = v2 - mean;
    float s2 = d0 * d0 + d1 * d1 + d2 * d2;
    #pragma unroll
    for (int o = 16; o; o >>= 1) s2 += __shfl_xor_sync(0xffffffffu, s2, o);
    if (lane == 0) sh[wid] = s2;
    __syncthreads();
    if (wid == 0) {
        float t2 = (lane < 8) ? sh[lane] : 0.0f;
        #pragma unroll
        for (int o = 4; o; o >>= 1) t2 += __shfl_xor_sync(0xffffffffu, t2, o);
        if (lane == 0) sh[0] = t2;
    }
    __syncthreads();
    float inv = rsqrtf(sh[0] * (1.0f / 768.0f) + 1e-5f);
    #pragma unroll
    for (int p = 0; p < 3; p++) {
        float d = (p == 0) ? d0 : (p == 1) ? d1 : d2;
        int c = tid + p * 256;
        float v = d * inv * g[c] + bta[c];
        __half h, l;
        f2hl(v, h, l);
        oh[ob + c] = h;
        ol[ob + c] = l;
    }
}

// ---------------------------------------------------------------------------
// LayerNorm (modes 0/1 gather). One block/row. Writes hi/lo fp16.
// ---------------------------------------------------------------------------
__global__ void ln_kernel(const float* __restrict__ src0,
                          const float* __restrict__ xt,
                          const float* __restrict__ g,
                          const float* __restrict__ bta,
                          __half* __restrict__ oh,
                          __half* __restrict__ ol, int mode)
{
    int m = blockIdx.x;
    const float* src;
    if (mode == 0) {
        src = src0 + (size_t)(m + m / 1568 + 1) * CC;
    } else {
        int sb = m / SL, p = m % SL;
        int b = sb >> 3, t = sb & 7;
        if (p == 0) src = src0 + (size_t)b * NTOK * CC;
        else        src = xt + ((size_t)(b * HW + (p - 1)) * TT + t) * CC;
    }
    int tid = threadIdx.x;
    float v0 = src[tid], v1 = src[tid + 256], v2 = src[tid + 512];
    ln_core(v0, v1, v2, g, bta, oh, ol, (size_t)m * CC);
}

// ---------------------------------------------------------------------------
// Fused assemble + LN2.
// ---------------------------------------------------------------------------
__global__ void assemble_ln(const float* __restrict__ x, const float* __restrict__ xt,
                            const float* __restrict__ ps,
                            const float* __restrict__ g, const float* __restrict__ bta,
                            float* __restrict__ out,
                            __half* __restrict__ oh, __half* __restrict__ ol)
{
    int row = blockIdx.x;
    int b = row / NTOK, n = row % NTOK;
    size_t orow = (size_t)row * CC;
    int tid = threadIdx.x;
    float v[3];
    if (n == 0) {
        #pragma unroll
        for (int p = 0; p < 3; p++) {
            int c = tid + p * 256;
            float acc = 0.0f;
            #pragma unroll
            for (int t = 0; t < TT; t++)
                acc += ps[((size_t)(b * TT + t) * SL) * CC + c];
            v[p] = x[orow + c] + acc * 0.125f;
        }
    } else {
        int r = n - 1, hw = r >> 3, t = r & 7;
        size_t xtrow = ((size_t)b * 1568 + r) * CC;
        size_t psrow = ((size_t)((b * TT + t) * SL + 1 + hw)) * CC;
        #pragma unroll
        for (int p = 0; p < 3; p++) {
            int c = tid + p * 256;
            v[p] = xt[xtrow + c] + ps[psrow + c];
        }
    }
    #pragma unroll
    for (int p = 0; p < 3; p++)
        out[orow + tid + p * 256] = v[p];
    ln_core(v[0], v[1], v[2], g, bta, oh, ol, orow);
}

// ---------------------------------------------------------------------------
// Temporal attention: fused per (seq, head). Padded smem (conflict-free).
// ---------------------------------------------------------------------------
__global__ void temporal_attn(const float* __restrict__ qkv,
                              __half* __restrict__ oh,
                              __half* __restrict__ ol)
{
    int seq = blockIdx.x, h = blockIdx.y;
    __shared__ float q[TT][HD + 1], k[TT][HD + 1], v[TT][HD + 1], p[TT][TT];
    int tid = threadIdx.x;
    size_t base = (size_t)(seq * TT) * C3 + h * HD;
    #pragma unroll
    for (int t = 0; t < TT; t++) {
        q[t][tid] = qkv[base + (size_t)t * C3 + tid];
        k[t][tid] = qkv[base + (size_t)t * C3 + CC + tid];
        v[t][tid] = qkv[base + (size_t)t * C3 + 2 * CC + tid];
    }
    __syncthreads();
    int i = tid >> 3, j = tid & 7;
    float s = 0.0f;
    #pragma unroll
    for (int d = 0; d < HD; d++) s = fmaf(q[i][d], k[j][d], s);
    p[i][j] = s * 0.125f;
    __syncthreads();
    if (tid < TT) {
        float mx = -1e30f;
        #pragma unroll
        for (int jj = 0; jj < TT; jj++) mx = fmaxf(mx, p[tid][jj]);
        float sum = 0.0f;
        #pragma unroll
        for (int jj = 0; jj < TT; jj++) {
            float e = expf(p[tid][jj] - mx);
            p[tid][jj] = e; sum += e;
        }
        float invs = 1.0f / sum;
        #pragma unroll
        for (int jj = 0; jj < TT; jj++) p[tid][jj] *= invs;
    }
    __syncthreads();
    #pragma unroll
    for (int t = 0; t < TT; t++) {
        float o = 0.0f;
        #pragma unroll
        for (int jj = 0; jj < TT; jj++) o = fmaf(p[t][jj], v[jj][tid], o);
        __half hh, ll;
        f2hl(o, hh, ll);
        size_t oi = (size_t)(seq * TT + t) * CC + h * HD + tid;
        oh[oi] = hh;
        ol[oi] = ll;
    }
}

// ---------------------------------------------------------------------------
// Host launch
// ---------------------------------------------------------------------------
extern "C" void kernel_launch(void* const* d_in, const int* in_sizes, int n_in,
                              void* d_out, int out_size)
{
    const float* x        = (const float*)d_in[0];
    const float* ln_t_g   = (const float*)d_in[1];
    const float* ln_t_b   = (const float*)d_in[2];
    const float* t_qkv_w  = (const float*)d_in[3];
    const float* t_qkv_b  = (const float*)d_in[4];
    const float* t_proj_w = (const float*)d_in[5];
    const float* t_proj_b = (const float*)d_in[6];
    const float* t_fc_w   = (const float*)d_in[7];
    const float* t_fc_b   = (const float*)d_in[8];
    const float* ln1_g    = (const float*)d_in[9];
    const float* ln1_b    = (const float*)d_in[10];
    const float* s_qkv_w  = (const float*)d_in[11];
    const float* s_qkv_b  = (const float*)d_in[12];
    const float* s_proj_w = (const float*)d_in[13];
    const float* s_proj_b = (const float*)d_in[14];
    const float* ln2_g    = (const float*)d_in[15];
    const float* ln2_b    = (const float*)d_in[16];
    const float* fc1_w    = (const float*)d_in[17];
    const float* fc1_b    = (const float*)d_in[18];
    const float* fc2_w    = (const float*)d_in[19];
    const float* fc2_b    = (const float*)d_in[20];
    float* out = (float*)d_out;

    float *qkv, *xt, *proj;
    __half *lnh, *lnl, *ath, *atl, *pjh, *pjl, *f1h, *f1l;
    __half *qsh, *qsl, *ph, *pl, *vth, *vtl;
    cudaGetSymbolAddress((void**)&qkv,  g_qkv);
    cudaGetSymbolAddress((void**)&xt,   g_xt);
    cudaGetSymbolAddress((void**)&proj, g_proj);
    cudaGetSymbolAddress((void**)&lnh,  g_ln_h);
    cudaGetSymbolAddress((void**)&lnl,  g_ln_l);
    cudaGetSymbolAddress((void**)&ath,  g_at_h);
    cudaGetSymbolAddress((void**)&atl,  g_at_l);
    cudaGetSymbolAddress((void**)&pjh,  g_pj_h);
    cudaGetSymbolAddress((void**)&pjl,  g_pj_l);
    cudaGetSymbolAddress((void**)&f1h,  g_f1_h);
    cudaGetSymbolAddress((void**)&f1l,  g_f1_l);
    cudaGetSymbolAddress((void**)&qsh,  g_qs_h);
    cudaGetSymbolAddress((void**)&qsl,  g_qs_l);
    cudaGetSymbolAddress((void**)&ph,   g_p_h);
    cudaGetSymbolAddress((void**)&pl,   g_p_l);
    cudaGetSymbolAddress((void**)&vth,  g_vt_h);
    cudaGetSymbolAddress((void**)&vtl,  g_vt_l);

    __half *wtq, *wtp, *wtf, *wsq, *wsp, *wf1, *wf2;
    cudaGetSymbolAddress((void**)&wtq, g_wtq);
    cudaGetSymbolAddress((void**)&wtp, g_wtp);
    cudaGetSymbolAddress((void**)&wtf, g_wtf);
    cudaGetSymbolAddress((void**)&wsq, g_wsq);
    cudaGetSymbolAddress((void**)&wsp, g_wsp);
    cudaGetSymbolAddress((void**)&wf1, g_wf1);
    cudaGetSymbolAddress((void**)&wf2, g_wf2);

    cudaFuncSetAttribute(gemm_mma<0,0>, cudaFuncAttributeMaxDynamicSharedMemorySize, GEMM_SMEM);
    cudaFuncSetAttribute(gemm_mma<0,1>, cudaFuncAttributeMaxDynamicSharedMemorySize, GEMM_SMEM);
    cudaFuncSetAttribute(gemm_mma<1,1>, cudaFuncAttributeMaxDynamicSharedMemorySize, GEMM_SMEM);
    cudaFuncSetAttribute(gemm_mma<2,0>, cudaFuncAttributeMaxDynamicSharedMemorySize, GEMM_SMEM);
    cudaFuncSetAttribute(gemm_mma<3,0>, cudaFuncAttributeMaxDynamicSharedMemorySize, GEMM_SMEM);
    cudaFuncSetAttribute(attn_scores_softmax, cudaFuncAttributeMaxDynamicSharedMemorySize, FSC_SMEM);
    cudaFuncSetAttribute(attn_pv_mma, cudaFuncAttributeMaxDynamicSharedMemorySize, PV_SMEM);

    // 0. convert all weights in one launch (single fp16)
    {
        WSegs w;
        w.src[0] = (const float4*)t_qkv_w;  w.dh[0] = (__half2*)wtq; w.n4[0] = C3 * CC / 4;
        w.src[1] = (const float4*)t_proj_w; w.dh[1] = (__half2*)wtp; w.n4[1] = CC * CC / 4;
        w.src[2] = (const float4*)t_fc_w;   w.dh[2] = (__half2*)wtf; w.n4[2] = CC * CC / 4;
        w.src[3] = (const float4*)s_qkv_w;  w.dh[3] = (__half2*)wsq; w.n4[3] = C3 * CC / 4;
        w.src[4] = (const float4*)s_proj_w; w.dh[4] = (__half2*)wsp; w.n4[4] = CC * CC / 4;
        w.src[5] = (const float4*)fc1_w;    w.dh[5] = (__half2*)wf1; w.n4[5] = HIDDEN * CC / 4;
        w.src[6] = (const float4*)fc2_w;    w.dh[6] = (__half2*)wf2; w.n4[6] = CC * HIDDEN / 4;
        int total4 = 0;
        for (int i = 0; i < 7; i++) total4 += w.n4[i];
        conv_all<<<(total4 + 255) / 256, 256>>>(w, total4);
    }

    // 1. temporal LN (skip cls) -> hi/lo
    ln_kernel<<<MT, 256>>>(x, nullptr, ln_t_g, ln_t_b, lnh, lnl, 0);

    // 2. temporal qkv -> fp32
    gemm_mma<0,0><<<dim3(C3/128, (MT+127)/128), 256, GEMM_SMEM>>>(
        lnh, lnl, wtq, t_qkv_b, qkv, nullptr, nullptr, nullptr, MT, C3, CC);

    // 3. temporal attention -> hi/lo
    temporal_attn<<<dim3(BB * HW, NH), 64>>>(qkv, ath, atl);

    // 4. temporal proj -> hi/lo
    gemm_mma<0,1><<<dim3(CC/128, (MT+127)/128), 256, GEMM_SMEM>>>(
        ath, atl, wtp, t_proj_b, nullptr, pjh, pjl, nullptr, MT, CC, CC);

    // 5. t_fc + residual from x (skip-cls) -> fp32 xt
    gemm_mma<2,0><<<dim3(CC/128, (MT+127)/128), 256, GEMM_SMEM>>>(
        pjh, pjl, wtf, t_fc_b, xt, nullptr, nullptr, x, MT, CC, CC);

    // 6. spatial gather + LN1 -> hi/lo
    ln_kernel<<<MS, 256>>>(x, xt, ln1_g, ln1_b, lnh, lnl, 1);

    // 7. spatial qkv -> hi/lo fp16
    gemm_mma<0,1><<<dim3(C3/128, (MS+127)/128), 256, GEMM_SMEM>>>(
        lnh, lnl, wsq, s_qkv_b, nullptr, qsh, qsl, nullptr, MS, C3, CC);

    // 8-10. spatial attention (tensor cores, fused scores+softmax)
    attn_scores_softmax<<<dim3(2, ZB), 256, FSC_SMEM>>>(qsh, qsl, ph, pl);
    transpose_v<<<ZB, 256>>>(qsh, qsl, vth, vtl);
    attn_pv_mma<<<dim3(2, ZB), 256, PV_SMEM>>>(ph, pl, vth, vtl, ath, atl);

    // 11. spatial proj -> fp32
    gemm_mma<0,0><<<dim3(CC/128, (MS+127)/128), 256, GEMM_SMEM>>>(
        ath, atl, wsp, s_proj_b, proj, nullptr, nullptr, nullptr, MS, CC, CC);

    // 12+13. assemble x_new into d_out AND LN2 -> hi/lo (fused)
    assemble_ln<<<MX, 256>>>(x, xt, proj, ln2_g, ln2_b, out, lnh, lnl);

    // 14. fc1 + gelu -> hi/lo
    gemm_mma<1,1><<<dim3(HIDDEN/128, (MX+127)/128), 256, GEMM_SMEM>>>(
        lnh, lnl, wf1, fc1_b, nullptr, f1h, f1l, nullptr, MX, HIDDEN, CC);

    // 15. fc2 + in-place residual on d_out
    gemm_mma<3,0><<<dim3(CC/128, (MX+127)/128), 256, GEMM_SMEM>>>(
        f1h, f1l, wf2, fc2_b, out, nullptr, nullptr, nullptr, MX, CC, HIDDEN);
}

// round 11
// speedup vs baseline: 2.1149x; 1.3836x over previous
#include <cuda_runtime.h>
#include <cuda_fp16.h>
#include <math.h>
#include <stdint.h>

// ---------------------------------------------------------------------------
// Problem constants
// ---------------------------------------------------------------------------
#define CC     768
#define C3     2304
#define NH     12
#define HD     64
#define HIDDEN 3072
#define TT     8
#define HW     196
#define BB     4
#define NTOK   1569
#define MT     6272
#define MS     6304
#define MX     6276
#define SL     197
#define SB     32
#define ZB     (SB*NH)
#define SL2    (SL*SL)
#define KP     224          // padded K for P/Vt (7 * 32)

// ---------------------------------------------------------------------------
// Static device scratch
// ---------------------------------------------------------------------------
__device__ float g_qkv [(size_t)MT * C3];      // fp32 qkv (temporal attention)
__device__ float g_xt  [(size_t)MT * CC];
__device__ float g_proj[(size_t)MS * CC];

// activation hi/lo fp16
__device__ __half g_ln_h[(size_t)MS * CC];
__device__ __half g_ln_l[(size_t)MS * CC];
__device__ __half g_at_h[(size_t)MS * CC];
__device__ __half g_at_l[(size_t)MS * CC];
__device__ __half g_pj_h[(size_t)MT * CC];
__device__ __half g_pj_l[(size_t)MT * CC];
__device__ __half g_f1_h[(size_t)MX * HIDDEN];
__device__ __half g_f1_l[(size_t)MX * HIDDEN];

// spatial qkv hi/lo fp16
__device__ __half g_qs_h[(size_t)MS * C3];
__device__ __half g_qs_l[(size_t)MS * C3];
// softmax P hi/lo (K-padded to 224)
__device__ __half g_p_h[(size_t)ZB * SL * KP];
__device__ __half g_p_l[(size_t)ZB * SL * KP];
// V transposed hi/lo [z][64][224]
__device__ __half g_vt_h[(size_t)ZB * HD * KP];
__device__ __half g_vt_l[(size_t)ZB * HD * KP];

// weights: single fp16
__device__ __half g_wtq[(size_t)C3 * CC];
__device__ __half g_wtp[(size_t)CC * CC];
__device__ __half g_wtf[(size_t)CC * CC];
__device__ __half g_wsq[(size_t)C3 * CC];
__device__ __half g_wsp[(size_t)CC * CC];
__device__ __half g_wf1[(size_t)HIDDEN * CC];
__device__ __half g_wf2[(size_t)CC * HIDDEN];

// ---------------------------------------------------------------------------
// Helpers
// ---------------------------------------------------------------------------
__device__ __forceinline__ float gelu_exact(float v) {
    return 0.5f * v * (1.0f + erff(v * 0.7071067811865475f));
}

__device__ __forceinline__ void f2hl(float x, __half& h, __half& l) {
    h = __float2half_rn(x);
    l = __float2half_rn(x - __half2float(h));
}

__device__ __forceinline__ uint32_t smem_u32(const void* p) {
    uint32_t a;
    asm("{ .reg .u64 t; cvta.to.shared.u64 t, %1; cvt.u32.u64 %0, t; }" : "=r"(a) : "l"(p));
    return a;
}

__device__ __forceinline__ void cpasync16(uint32_t dst, const void* src) {
    asm volatile("cp.async.cg.shared.global [%0], [%1], 16;" :: "r"(dst), "l"(src));
}
#define CP_COMMIT() asm volatile("cp.async.commit_group;" ::: "memory")
#define CP_WAIT0()  asm volatile("cp.async.wait_group 0;" ::: "memory")
#define CP_WAIT1()  asm volatile("cp.async.wait_group 1;" ::: "memory")

__device__ __forceinline__ void ldm4(uint32_t* r, uint32_t addr) {
    asm volatile("ldmatrix.sync.aligned.m8n8.x4.shared.b16 {%0,%1,%2,%3}, [%4];"
                 : "=r"(r[0]), "=r"(r[1]), "=r"(r[2]), "=r"(r[3]) : "r"(addr));
}

__device__ __forceinline__ void mma16816(float* d, const uint32_t* a, const uint32_t* b) {
    asm volatile(
        "mma.sync.aligned.m16n8k16.row.col.f32.f16.f16.f32 "
        "{%0,%1,%2,%3}, {%4,%5,%6,%7}, {%8,%9}, {%0,%1,%2,%3};"
        : "+f"(d[0]), "+f"(d[1]), "+f"(d[2]), "+f"(d[3])
        : "r"(a[0]), "r"(a[1]), "r"(a[2]), "r"(a[3]), "r"(b[0]), "r"(b[1]));
}

// ---------------------------------------------------------------------------
// Single-chain fp16 HMMA NT GEMM: C = A(hi fp16) * B(fp16)^T + bias.
// CTA 128x128, 8 warps (64Mx32N), k-step 32, 3-stage cp.async (wait_group 1),
// 2 CTAs/SM. Attention-internal GEMMs keep multi-chain precision elsewhere.
//   EPI 0: +bias   1: gelu(+bias)   2: +bias+resid(skip-cls)   3: +bias+C
//   OUT 0: fp32 C  1: hi/lo fp16 arrays (Ch, Cl)
// smem/stage: A 128x80 + B 128x80 = 20480 B; x3 stages = 61440 B.
// ---------------------------------------------------------------------------
#define STG    20480u
#define OFF_A  0u
#define OFF_B  10240u
#define GEMM_SMEM (3 * STG)

template<int EPI, int OUT>
__global__ void __launch_bounds__(256, 2)
gemm_mma(const __half* __restrict__ Ahg,
         const __half* __restrict__ Bg,
         const float* __restrict__ bias,
         float* __restrict__ C,
         __half* __restrict__ Ch, __half* __restrict__ Cl,
         const float* __restrict__ resid,
         int M, int N, int K)
{
    extern __shared__ char smem[];
    const uint32_t sb = smem_u32(smem);

    const int tid  = threadIdx.x;
    const int wid  = tid >> 5;
    const int lane = tid & 31;
    const int row0 = blockIdx.y * 128;
    const int col0 = blockIdx.x * 128;
    const int KT   = K >> 5;

    float acc[4][4][4];
    #pragma unroll
    for (int a = 0; a < 4; a++)
        #pragma unroll
        for (int b = 0; b < 4; b++)
            #pragma unroll
            for (int c = 0; c < 4; c++) acc[a][b][c] = 0.0f;

    auto load_stage = [&](int kt, int buf) {
        const int kw = kt * 32;
        const uint32_t dstb = sb + buf * STG;
        #pragma unroll
        for (int q = 0; q < 2; q++) {
            int cid = q * 256 + tid;
            int row = cid >> 2, ch = cid & 3;
            int ar  = min(row0 + row, M - 1);
            cpasync16(dstb + OFF_A + row * 80u + ch * 16u,
                      Ahg + (size_t)ar * K + kw + ch * 8);
        }
        #pragma unroll
        for (int q = 0; q < 2; q++) {
            int cid = q * 256 + tid;
            int row = cid >> 2, ch = cid & 3;
            cpasync16(dstb + OFF_B + row * 80u + ch * 16u,
                      Bg + (size_t)(col0 + row) * K + kw + ch * 8);
        }
        CP_COMMIT();
    };

    load_stage(0, 0);
    load_stage(1, 1);           // KT >= 24 at every call site
    CP_WAIT1();
    __syncthreads();

    const int m0w = (wid & 1) * 64;
    const int n0w = (wid >> 1) * 32;
    const uint32_t a_off = (uint32_t)(m0w + (lane & 15)) * 80u + (uint32_t)((lane >> 4) << 4);
    const uint32_t b_off = (uint32_t)(n0w + (lane & 7) + ((lane >> 4) << 3)) * 80u
                         + (uint32_t)(((lane >> 3) & 1) << 4);

    for (int kt = 0; kt < KT; kt++) {
        const int buf = kt % 3;
        const uint32_t bb = sb + buf * STG;
        #pragma unroll
        for (int s = 0; s < 2; s++) {
            uint32_t ah[4][4], bh[4][2];
            #pragma unroll
            for (int mi = 0; mi < 4; mi++)
                ldm4(ah[mi], bb + OFF_A + a_off + mi * 1280u + s * 32u);
            #pragma unroll
            for (int nj = 0; nj < 2; nj++) {
                uint32_t t[4];
                ldm4(t, bb + OFF_B + b_off + nj * 1280u + s * 32u);
                bh[nj*2][0] = t[0]; bh[nj*2][1] = t[1];
                bh[nj*2+1][0] = t[2]; bh[nj*2+1][1] = t[3];
            }
            #pragma unroll
            for (int mi = 0; mi < 4; mi++)
                #pragma unroll
                for (int nj = 0; nj < 4; nj++)
                    mma16816(acc[mi][nj], ah[mi], bh[nj]);
        }
        if (kt + 2 < KT) {
            load_stage(kt + 2, (kt + 2) % 3);
            CP_WAIT1();
        } else {
            CP_WAIT0();
        }
        __syncthreads();
    }

    #pragma unroll
    for (int mi = 0; mi < 4; mi++) {
        const int rbase = row0 + m0w + mi * 16 + (lane >> 2);
        #pragma unroll
        for (int half = 0; half < 2; half++) {
            const int m = rbase + half * 8;
            if (m >= M) continue;
            #pragma unroll
            for (int nj = 0; nj < 4; nj++) {
                const int n = col0 + n0w + nj * 8 + (lane & 3) * 2;
                float v0 = acc[mi][nj][half * 2 + 0] + bias[n];
                float v1 = acc[mi][nj][half * 2 + 1] + bias[n + 1];
                if (EPI == 1) { v0 = gelu_exact(v0); v1 = gelu_exact(v1); }
                if (EPI == 2) {
                    const float* rs = resid + (size_t)(m + m / 1568 + 1) * CC + n;
                    v0 += rs[0]; v1 += rs[1];
                }
                if (OUT == 0) {
                    float* cp = C + (size_t)m * N + n;
                    if (EPI == 3) {
                        float2 old = *(const float2*)cp;
                        v0 += old.x; v1 += old.y;
                    }
                    float2 o = {v0, v1};
                    *(float2*)cp = o;
                } else {
                    __half h0, l0, h1, l1;
                    f2hl(v0, h0, l0);
                    f2hl(v1, h1, l1);
                    *(__half2*)(Ch + (size_t)m * N + n) = __halves2half2(h0, h1);
                    *(__half2*)(Cl + (size_t)m * N + n) = __halves2half2(l0, l1);
                }
            }
        }
    }
}

// ---------------------------------------------------------------------------
// FUSED spatial scores + softmax (Round-10, passing). 3-chain precision.
// ---------------------------------------------------------------------------
#define FSTG     56320u
#define FOFF_AH  0u
#define FOFF_AL  10240u
#define FOFF_BH  20480u
#define FOFF_BL  38400u
#define FSC_SMEM (2 * FSTG)

__global__ void __launch_bounds__(256)
attn_scores_softmax(const __half* __restrict__ qh, const __half* __restrict__ ql,
                    __half* __restrict__ ph, __half* __restrict__ pl)
{
    extern __shared__ char smem[];
    const uint32_t sb = smem_u32(smem);

    const int z = blockIdx.y;
    const int s = z / NH, h = z % NH;
    const size_t base  = (size_t)(s * SL) * C3 + h * HD;
    const size_t pbase = (size_t)z * SL * KP;

    const int tid  = threadIdx.x;
    const int wid  = tid >> 5;
    const int lane = tid & 31;
    const int row0 = blockIdx.x * 128;

    #pragma unroll
    for (int kt = 0; kt < 2; kt++) {
        const int kw = kt * 32;
        const uint32_t dstb = sb + kt * FSTG;
        #pragma unroll
        for (int q = 0; q < 4; q++) {
            int cid = q * 256 + tid;
            int arr = cid >> 9;
            int idx = cid & 511;
            int row = idx >> 2, ch = idx & 3;
            int gr  = min(row0 + row, SL - 1);
            const __half* src = (arr ? ql : qh) + base + (size_t)gr * C3 + kw + ch * 8;
            cpasync16(dstb + (arr ? FOFF_AL : FOFF_AH) + row * 80u + ch * 16u, src);
        }
        #pragma unroll
        for (int q = 0; q < 7; q++) {
            int cid = q * 256 + tid;
            int arr2 = (cid >= 896) ? 1 : 0;
            int idx  = arr2 ? cid - 896 : cid;
            int row = idx >> 2, ch = idx & 3;
            int gr  = min(row, SL - 1);
            const __half* src = (arr2 ? ql : qh) + base + (size_t)gr * C3 + CC + kw + ch * 8;
            cpasync16(dstb + (arr2 ? FOFF_BL : FOFF_BH) + row * 80u + ch * 16u, src);
        }
        CP_COMMIT();
    }
    CP_WAIT0();
    __syncthreads();

    const int m0w = wid * 16;
    const uint32_t a_off = (uint32_t)(m0w + (lane & 15)) * 80u + (uint32_t)((lane >> 4) << 4);
    const uint32_t b_off = (uint32_t)((lane & 7) + ((lane >> 4) << 3)) * 80u
                         + (uint32_t)(((lane >> 3) & 1) << 4);

    float acc[28][4];
    #pragma unroll
    for (int t = 0; t < 28; t++)
        #pragma unroll
        for (int c = 0; c < 4; c++) acc[t][c] = 0.0f;

    #pragma unroll
    for (int kt = 0; kt < 2; kt++) {
        const uint32_t bb = sb + kt * FSTG;
        #pragma unroll
        for (int s2 = 0; s2 < 2; s2++) {
            uint32_t ah[4], al[4];
            ldm4(ah, bb + FOFF_AH + a_off + s2 * 32u);
            ldm4(al, bb + FOFF_AL + a_off + s2 * 32u);
            #pragma unroll
            for (int njq = 0; njq < 14; njq++) {
                uint32_t th[4], tl[4];
                ldm4(th, bb + FOFF_BH + b_off + njq * 1280u + s2 * 32u);
                ldm4(tl, bb + FOFF_BL + b_off + njq * 1280u + s2 * 32u);
                uint32_t bh0[2] = {th[0], th[1]}, bh1[2] = {th[2], th[3]};
                uint32_t bl0[2] = {tl[0], tl[1]}, bl1[2] = {tl[2], tl[3]};
                mma16816(acc[njq*2],   ah, bh0);
                mma16816(acc[njq*2],   ah, bl0);
                mma16816(acc[njq*2],   al, bh0);
                mma16816(acc[njq*2+1], ah, bh1);
                mma16816(acc[njq*2+1], ah, bl1);
                mma16816(acc[njq*2+1], al, bh1);
            }
        }
    }

    const int ncol0 = (lane & 3) * 2;
    #pragma unroll
    for (int half = 0; half < 2; half++) {
        const int row = row0 + m0w + (lane >> 2) + half * 8;
        float mx = -1e30f;
        #pragma unroll
        for (int t = 0; t < 28; t++) {
            int n = t * 8 + ncol0;
            float v0 = acc[t][half*2+0] * 0.125f;
            float v1 = acc[t][half*2+1] * 0.125f;
            acc[t][half*2+0] = (n < SL)     ? v0 : -1e30f;
            acc[t][half*2+1] = (n + 1 < SL) ? v1 : -1e30f;
            mx = fmaxf(mx, acc[t][half*2+0]);
            mx = fmaxf(mx, acc[t][half*2+1]);
        }
        mx = fmaxf(mx, __shfl_xor_sync(0xffffffffu, mx, 1));
        mx = fmaxf(mx, __shfl_xor_sync(0xffffffffu, mx, 2));
        float sum = 0.0f;
        #pragma unroll
        for (int t = 0; t < 28; t++) {
            float e0 = expf(acc[t][half*2+0] - mx);
            float e1 = expf(acc[t][half*2+1] - mx);
            int n = t * 8 + ncol0;
            e0 = (n < SL)     ? e0 : 0.0f;
            e1 = (n + 1 < SL) ? e1 : 0.0f;
            acc[t][half*2+0] = e0;
            acc[t][half*2+1] = e1;
            sum += e0 + e1;
        }
        sum += __shfl_xor_sync(0xffffffffu, sum, 1);
        sum += __shfl_xor_sync(0xffffffffu, sum, 2);
        float inv = 1.0f / sum;
        if (row < SL) {
            size_t ob = pbase + (size_t)row * KP;
            #pragma unroll
            for (int t = 0; t < 28; t++) {
                int n = t * 8 + ncol0;
                __half h0, l0, h1, l1;
                f2hl(acc[t][half*2+0] * inv, h0, l0);
                f2hl(acc[t][half*2+1] * inv, h1, l1);
                *(__half2*)(ph + ob + n) = __halves2half2(h0, h1);
                *(__half2*)(pl + ob + n) = __halves2half2(l0, l1);
            }
        }
    }
}

// ---------------------------------------------------------------------------
// Batched PV via HMMA (Round-8, passing). 3-chain precision.
// ---------------------------------------------------------------------------
#define PSTG    30720u
#define POFF_AH 0u
#define POFF_AL 10240u
#define POFF_BH 20480u
#define POFF_BL 25600u
#define PV_SMEM (2 * PSTG)

__global__ void __launch_bounds__(256)
attn_pv_mma(const __half* __restrict__ ph, const __half* __restrict__ pl,
            const __half* __restrict__ vth, const __half* __restrict__ vtl,
            __half* __restrict__ oh, __half* __restrict__ ol)
{
    extern __shared__ char smem[];
    const uint32_t sb = smem_u32(smem);

    const int z = blockIdx.y;
    const int s = z / NH, h = z % NH;
    const size_t pbase = (size_t)z * SL * KP;
    const size_t vbase = (size_t)z * HD * KP;

    const int tid  = threadIdx.x;
    const int wid  = tid >> 5;
    const int lane = tid & 31;
    const int row0 = blockIdx.x * 128;

    float acc[2][4][4];
    #pragma unroll
    for (int a = 0; a < 2; a++)
        #pragma unroll
        for (int b = 0; b < 4; b++)
            #pragma unroll
            for (int c = 0; c < 4; c++) acc[a][b][c] = 0.0f;

    auto load_stage = [&](int kt, int buf) {
        const int kw = kt * 32;
        const uint32_t dstb = sb + buf * PSTG;
        #pragma unroll
        for (int q = 0; q < 4; q++) {
            int cid = q * 256 + tid;
            int arr = cid >> 9;
            int idx = cid & 511;
            int row = idx >> 2, ch = idx & 3;
            int gr  = min(row0 + row, SL - 1);
            const __half* src = (arr ? pl : ph) + pbase + (size_t)gr * KP + kw + ch * 8;
            cpasync16(dstb + (arr ? POFF_AL : POFF_AH) + row * 80u + ch * 16u, src);
        }
        #pragma unroll
        for (int q = 0; q < 2; q++) {
            int cid = q * 256 + tid;
            int arr = cid >> 8;
            int idx = cid & 255;
            int row = idx >> 2, ch = idx & 3;
            const __half* src = (arr ? vtl : vth) + vbase + (size_t)row * KP + kw + ch * 8;
            cpasync16(dstb + (arr ? POFF_BL : POFF_BH) + row * 80u + ch * 16u, src);
        }
        CP_COMMIT();
    };

    load_stage(0, 0);
    CP_WAIT0();
    __syncthreads();

    const int m0w = (wid & 3) * 32;
    const int n0w = (wid >> 2) * 32;
    const uint32_t a_off = (uint32_t)(m0w + (lane & 15)) * 80u + (uint32_t)((lane >> 4) << 4);
    const uint32_t b_off = (uint32_t)(n0w + (lane & 7) + ((lane >> 4) << 3)) * 80u
                         + (uint32_t)(((lane >> 3) & 1) << 4);

    for (int kt = 0; kt < KP / 32; kt++) {
        const int buf = kt & 1;
        if (kt + 1 < KP / 32) load_stage(kt + 1, buf ^ 1);

        const uint32_t bb = sb + buf * PSTG;
        #pragma unroll
        for (int s2 = 0; s2 < 2; s2++) {
            uint32_t ah[2][4], al[2][4], bh[4][2], bl[4][2];
            #pragma unroll
            for (int mi = 0; mi < 2; mi++) {
                ldm4(ah[mi], bb + POFF_AH + a_off + mi * 1280u + s2 * 32u);
                ldm4(al[mi], bb + POFF_AL + a_off + mi * 1280u + s2 * 32u);
            }
            #pragma unroll
            for (int nj = 0; nj < 2; nj++) {
                uint32_t t[4];
                ldm4(t, bb + POFF_BH + b_off + nj * 1280u + s2 * 32u);
                bh[nj*2][0] = t[0]; bh[nj*2][1] = t[1];
                bh[nj*2+1][0] = t[2]; bh[nj*2+1][1] = t[3];
                ldm4(t, bb + POFF_BL + b_off + nj * 1280u + s2 * 32u);
                bl[nj*2][0] = t[0]; bl[nj*2][1] = t[1];
                bl[nj*2+1][0] = t[2]; bl[nj*2+1][1] = t[3];
            }
            #pragma unroll
            for (int mi = 0; mi < 2; mi++)
                #pragma unroll
                for (int nj = 0; nj < 4; nj++) {
                    mma16816(acc[mi][nj], ah[mi], bh[nj]);
                    mma16816(acc[mi][nj], ah[mi], bl[nj]);
                    mma16816(acc[mi][nj], al[mi], bh[nj]);
                }
        }
        CP_WAIT0();
        __syncthreads();
    }

    #pragma unroll
    for (int mi = 0; mi < 2; mi++) {
        const int rbase = row0 + m0w + mi * 16 + (lane >> 2);
        #pragma unroll
        for (int half = 0; half < 2; half++) {
            const int m = rbase + half * 8;
            if (m >= SL) continue;
            size_t ob = (size_t)(s * SL + m) * CC + h * HD;
            #pragma unroll
            for (int nj = 0; nj < 4; nj++) {
                const int n = n0w + nj * 8 + (lane & 3) * 2;
                __half h0, l0, h1, l1;
                f2hl(acc[mi][nj][half * 2 + 0], h0, l0);
                f2hl(acc[mi][nj][half * 2 + 1], h1, l1);
                *(__half2*)(oh + ob + n) = __halves2half2(h0, h1);
                *(__half2*)(ol + ob + n) = __halves2half2(l0, l1);
            }
        }
    }
}

// ---------------------------------------------------------------------------
// V transpose: per z, Vt[d][t] = V[t][d], padded t->224 with zeros. hi+lo.
// ---------------------------------------------------------------------------
__global__ void transpose_v(const __half* __restrict__ qh, const __half* __restrict__ ql,
                            __half* __restrict__ vth, __half* __restrict__ vtl)
{
    int z = blockIdx.x;
    int s = z / NH, h = z % NH;
    size_t vbase = (size_t)(s * SL) * C3 + 2 * CC + h * HD;
    size_t obase = (size_t)z * HD * KP;
    __shared__ __half shh[32][66], shl[32][66];
    int tid = threadIdx.x;

    for (int t0 = 0; t0 < KP; t0 += 32) {
        #pragma unroll
        for (int i = 0; i < 8; i++) {
            int e = i * 256 + tid;
            int t = e >> 6, d = e & 63;
            int gt = t0 + t;
            if (gt < SL) {
                size_t gi = vbase + (size_t)gt * C3 + d;
                shh[t][d] = qh[gi];
                shl[t][d] = ql[gi];
            } else {
                shh[t][d] = __float2half(0.0f);
                shl[t][d] = __float2half(0.0f);
            }
        }
        __syncthreads();
        #pragma unroll
        for (int i = 0; i < 8; i++) {
            int e = i * 256 + tid;
            int d = e >> 5, t = e & 31;
            vth[obase + (size_t)d * KP + t0 + t] = shh[t][d];
            vtl[obase + (size_t)d * KP + t0 + t] = shl[t][d];
        }
        __syncthreads();
    }
}

// ---------------------------------------------------------------------------
// Fused weight conversion: all 7 weights -> single fp16, one launch.
// ---------------------------------------------------------------------------
struct WSegs {
    const float4* src[7];
    __half2*      dh[7];
    int           n4[7];
};

__global__ void conv_all(WSegs w, int total4)
{
    int i = blockIdx.x * blockDim.x + threadIdx.x;
    if (i >= total4) return;
    int rem = i;
    #pragma unroll
    for (int s = 0; s < 7; s++) {
        if (rem < w.n4[s]) {
            float4 v = w.src[s][rem];
            w.dh[s][rem * 2 + 0] = __halves2half2(__float2half_rn(v.x), __float2half_rn(v.y));
            w.dh[s][rem * 2 + 1] = __halves2half2(__float2half_rn(v.z), __float2half_rn(v.w));
            return;
        }
        rem -= w.n4[s];
    }
}

// ---------------------------------------------------------------------------
// LN core: values v0,v1,v2 per thread.
// ---------------------------------------------------------------------------
__device__ __forceinline__ void ln_core(float v0, float v1, float v2,
                                        const float* __restrict__ g,
                                        const float* __restrict__ bta,
                                        __half* __restrict__ oh,
                                        __half* __restrict__ ol, size_t ob)
{
    int tid = threadIdx.x;
    int lane = tid & 31, wid = tid >> 5;
    __shared__ float sh[32];
    float s = v0 + v1 + v2;
    #pragma unroll
    for (int o = 16; o; o >>= 1) s += __shfl_xor_sync(0xffffffffu, s, o);
    if (lane == 0) sh[wid] = s;
    __syncthreads();
    if (wid == 0) {
        float t2 = (lane < 8) ? sh[lane] : 0.0f;
        #pragma unroll
        for (int o = 4; o; o >>= 1) t2 += __shfl_xor_sync(0xffffffffu, t2, o);
        if (lane == 0) sh[0] = t2;
    }
    __syncthreads();
    float mean = sh[0] * (1.0f / 768.0f);
    __syncthreads();
    float d0 = v0 - mean, d1 = v1 - mean, d2 = v2 - mean;
    float s2 = d0 * d0 + d1 * d1 + d2 * d2;
    #pragma unroll
    for (int o = 16; o; o >>= 1) s2 += __shfl_xor_sync(0xffffffffu, s2, o);
    if (lane == 0) sh[wid] = s2;
    __syncthreads();
    if (wid == 0) {
        float t2 = (lane < 8) ? sh[lane] : 0.0f;
        #pragma unroll
        for (int o = 4; o; o >>= 1) t2 += __shfl_xor_sync(0xffffffffu, t2, o);
        if (lane == 0) sh[0] = t2;
    }
    __syncthreads();
    float inv = rsqrtf(sh[0] * (1.0f / 768.0f) + 1e-5f);
    #pragma unroll
    for (int p = 0; p < 3; p++) {
        float d = (p == 0) ? d0 : (p == 1) ? d1 : d2;
        int c = tid + p * 256;
        float v = d * inv * g[c] + bta[c];
        __half h, l;
        f2hl(v, h, l);
        oh[ob + c] = h;
        ol[ob + c] = l;
    }
}

// ---------------------------------------------------------------------------
// LayerNorm (modes 0/1 gather). One block/row. Writes hi/lo fp16.
// ---------------------------------------------------------------------------
__global__ void ln_kernel(const float* __restrict__ src0,
                          const float* __restrict__ xt,
                          const float* __restrict__ g,
                          const float* __restrict__ bta,
                          __half* __restrict__ oh,
                          __half* __restrict__ ol, int mode)
{
    int m = blockIdx.x;
    const float* src;
    if (mode == 0) {
        src = src0 + (size_t)(m + m / 1568 + 1) * CC;
    } else {
        int sb = m / SL, p = m % SL;
        int b = sb >> 3, t = sb & 7;
        if (p == 0) src = src0 + (size_t)b * NTOK * CC;
        else        src = xt + ((size_t)(b * HW + (p - 1)) * TT + t) * CC;
    }
    int tid = threadIdx.x;
    float v0 = src[tid], v1 = src[tid + 256], v2 = src[tid + 512];
    ln_core(v0, v1, v2, g, bta, oh, ol, (size_t)m * CC);
}

// ---------------------------------------------------------------------------
// Fused assemble + LN2.
// ---------------------------------------------------------------------------
__global__ void assemble_ln(const float* __restrict__ x, const float* __restrict__ xt,
                            const float* __restrict__ ps,
                            const float* __restrict__ g, const float* __restrict__ bta,
                            float* __restrict__ out,
                            __half* __restrict__ oh, __half* __restrict__ ol)
{
    int row = blockIdx.x;
    int b = row / NTOK, n = row % NTOK;
    size_t orow = (size_t)row * CC;
    int tid = threadIdx.x;
    float v[3];
    if (n == 0) {
        #pragma unroll
        for (int p = 0; p < 3; p++) {
            int c = tid + p * 256;
            float acc = 0.0f;
            #pragma unroll
            for (int t = 0; t < TT; t++)
                acc += ps[((size_t)(b * TT + t) * SL) * CC + c];
            v[p] = x[orow + c] + acc * 0.125f;
        }
    } else {
        int r = n - 1, hw = r >> 3, t = r & 7;
        size_t xtrow = ((size_t)b * 1568 + r) * CC;
        size_t psrow = ((size_t)((b * TT + t) * SL + 1 + hw)) * CC;
        #pragma unroll
        for (int p = 0; p < 3; p++) {
            int c = tid + p * 256;
            v[p] = xt[xtrow + c] + ps[psrow + c];
        }
    }
    #pragma unroll
    for (int p = 0; p < 3; p++)
        out[orow + tid + p * 256] = v[p];
    ln_core(v[0], v[1], v[2], g, bta, oh, ol, orow);
}

// ---------------------------------------------------------------------------
// Temporal attention: fused per (seq, head). Padded smem (conflict-free).
// ---------------------------------------------------------------------------
__global__ void temporal_attn(const float* __restrict__ qkv,
                              __half* __restrict__ oh,
                              __half* __restrict__ ol)
{
    int seq = blockIdx.x, h = blockIdx.y;
    __shared__ float q[TT][HD + 1], k[TT][HD + 1], v[TT][HD + 1], p[TT][TT];
    int tid = threadIdx.x;
    size_t base = (size_t)(seq * TT) * C3 + h * HD;
    #pragma unroll
    for (int t = 0; t < TT; t++) {
        q[t][tid] = qkv[base + (size_t)t * C3 + tid];
        k[t][tid] = qkv[base + (size_t)t * C3 + CC + tid];
        v[t][tid] = qkv[base + (size_t)t * C3 + 2 * CC + tid];
    }
    __syncthreads();
    int i = tid >> 3, j = tid & 7;
    float s = 0.0f;
    #pragma unroll
    for (int d = 0; d < HD; d++) s = fmaf(q[i][d], k[j][d], s);
    p[i][j] = s * 0.125f;
    __syncthreads();
    if (tid < TT) {
        float mx = -1e30f;
        #pragma unroll
        for (int jj = 0; jj < TT; jj++) mx = fmaxf(mx, p[tid][jj]);
        float sum = 0.0f;
        #pragma unroll
        for (int jj = 0; jj < TT; jj++) {
            float e = expf(p[tid][jj] - mx);
            p[tid][jj] = e; sum += e;
        }
        float invs = 1.0f / sum;
        #pragma unroll
        for (int jj = 0; jj < TT; jj++) p[tid][jj] *= invs;
    }
    __syncthreads();
    #pragma unroll
    for (int t = 0; t < TT; t++) {
        float o = 0.0f;
        #pragma unroll
        for (int jj = 0; jj < TT; jj++) o = fmaf(p[t][jj], v[jj][tid], o);
        __half hh, ll;
        f2hl(o, hh, ll);
        size_t oi = (size_t)(seq * TT + t) * CC + h * HD + tid;
        oh[oi] = hh;
        ol[oi] = ll;
    }
}

// ---------------------------------------------------------------------------
// Host launch
// ---------------------------------------------------------------------------
extern "C" void kernel_launch(void* const* d_in, const int* in_sizes, int n_in,
                              void* d_out, int out_size)
{
    const float* x        = (const float*)d_in[0];
    const float* ln_t_g   = (const float*)d_in[1];
    const float* ln_t_b   = (const float*)d_in[2];
    const float* t_qkv_w  = (const float*)d_in[3];
    const float* t_qkv_b  = (const float*)d_in[4];
    const float* t_proj_w = (const float*)d_in[5];
    const float* t_proj_b = (const float*)d_in[6];
    const float* t_fc_w   = (const float*)d_in[7];
    const float* t_fc_b   = (const float*)d_in[8];
    const float* ln1_g    = (const float*)d_in[9];
    const float* ln1_b    = (const float*)d_in[10];
    const float* s_qkv_w  = (const float*)d_in[11];
    const float* s_qkv_b  = (const float*)d_in[12];
    const float* s_proj_w = (const float*)d_in[13];
    const float* s_proj_b = (const float*)d_in[14];
    const float* ln2_g    = (const float*)d_in[15];
    const float* ln2_b    = (const float*)d_in[16];
    const float* fc1_w    = (const float*)d_in[17];
    const float* fc1_b    = (const float*)d_in[18];
    const float* fc2_w    = (const float*)d_in[19];
    const float* fc2_b    = (const float*)d_in[20];
    float* out = (float*)d_out;

    float *qkv, *xt, *proj;
    __half *lnh, *lnl, *ath, *atl, *pjh, *pjl, *f1h, *f1l;
    __half *qsh, *qsl, *ph, *pl, *vth, *vtl;
    cudaGetSymbolAddress((void**)&qkv,  g_qkv);
    cudaGetSymbolAddress((void**)&xt,   g_xt);
    cudaGetSymbolAddress((void**)&proj, g_proj);
    cudaGetSymbolAddress((void**)&lnh,  g_ln_h);
    cudaGetSymbolAddress((void**)&lnl,  g_ln_l);
    cudaGetSymbolAddress((void**)&ath,  g_at_h);
    cudaGetSymbolAddress((void**)&atl,  g_at_l);
    cudaGetSymbolAddress((void**)&pjh,  g_pj_h);
    cudaGetSymbolAddress((void**)&pjl,  g_pj_l);
    cudaGetSymbolAddress((void**)&f1h,  g_f1_h);
    cudaGetSymbolAddress((void**)&f1l,  g_f1_l);
    cudaGetSymbolAddress((void**)&qsh,  g_qs_h);
    cudaGetSymbolAddress((void**)&qsl,  g_qs_l);
    cudaGetSymbolAddress((void**)&ph,   g_p_h);
    cudaGetSymbolAddress((void**)&pl,   g_p_l);
    cudaGetSymbolAddress((void**)&vth,  g_vt_h);
    cudaGetSymbolAddress((void**)&vtl,  g_vt_l);

    __half *wtq, *wtp, *wtf, *wsq, *wsp, *wf1, *wf2;
    cudaGetSymbolAddress((void**)&wtq, g_wtq);
    cudaGetSymbolAddress((void**)&wtp, g_wtp);
    cudaGetSymbolAddress((void**)&wtf, g_wtf);
    cudaGetSymbolAddress((void**)&wsq, g_wsq);
    cudaGetSymbolAddress((void**)&wsp, g_wsp);
    cudaGetSymbolAddress((void**)&wf1, g_wf1);
    cudaGetSymbolAddress((void**)&wf2, g_wf2);

    cudaFuncSetAttribute(gemm_mma<0,0>, cudaFuncAttributeMaxDynamicSharedMemorySize, GEMM_SMEM);
    cudaFuncSetAttribute(gemm_mma<0,1>, cudaFuncAttributeMaxDynamicSharedMemorySize, GEMM_SMEM);
    cudaFuncSetAttribute(gemm_mma<1,1>, cudaFuncAttributeMaxDynamicSharedMemorySize, GEMM_SMEM);
    cudaFuncSetAttribute(gemm_mma<2,0>, cudaFuncAttributeMaxDynamicSharedMemorySize, GEMM_SMEM);
    cudaFuncSetAttribute(gemm_mma<3,0>, cudaFuncAttributeMaxDynamicSharedMemorySize, GEMM_SMEM);
    cudaFuncSetAttribute(attn_scores_softmax, cudaFuncAttributeMaxDynamicSharedMemorySize, FSC_SMEM);
    cudaFuncSetAttribute(attn_pv_mma, cudaFuncAttributeMaxDynamicSharedMemorySize, PV_SMEM);

    // 0. convert all weights in one launch (single fp16)
    {
        WSegs w;
        w.src[0] = (const float4*)t_qkv_w;  w.dh[0] = (__half2*)wtq; w.n4[0] = C3 * CC / 4;
        w.src[1] = (const float4*)t_proj_w; w.dh[1] = (__half2*)wtp; w.n4[1] = CC * CC / 4;
        w.src[2] = (const float4*)t_fc_w;   w.dh[2] = (__half2*)wtf; w.n4[2] = CC * CC / 4;
        w.src[3] = (const float4*)s_qkv_w;  w.dh[3] = (__half2*)wsq; w.n4[3] = C3 * CC / 4;
        w.src[4] = (const float4*)s_proj_w; w.dh[4] = (__half2*)wsp; w.n4[4] = CC * CC / 4;
        w.src[5] = (const float4*)fc1_w;    w.dh[5] = (__half2*)wf1; w.n4[5] = HIDDEN * CC / 4;
        w.src[6] = (const float4*)fc2_w;    w.dh[6] = (__half2*)wf2; w.n4[6] = CC * HIDDEN / 4;
        int total4 = 0;
        for (int i = 0; i < 7; i++) total4 += w.n4[i];
        conv_all<<<(total4 + 255) / 256, 256>>>(w, total4);
    }

    // 1. temporal LN (skip cls) -> hi/lo
    ln_kernel<<<MT, 256>>>(x, nullptr, ln_t_g, ln_t_b, lnh, lnl, 0);

    // 2. temporal qkv -> fp32 (1-chain: A = LN hi)
    gemm_mma<0,0><<<dim3(C3/128, (MT+127)/128), 256, GEMM_SMEM>>>(
        lnh, wtq, t_qkv_b, qkv, nullptr, nullptr, nullptr, MT, C3, CC);

    // 3. temporal attention -> hi/lo
    temporal_attn<<<dim3(BB * HW, NH), 64>>>(qkv, ath, atl);

    // 4. temporal proj -> hi/lo
    gemm_mma<0,1><<<dim3(CC/128, (MT+127)/128), 256, GEMM_SMEM>>>(
        ath, wtp, t_proj_b, nullptr, pjh, pjl, nullptr, MT, CC, CC);

    // 5. t_fc + residual from x (skip-cls) -> fp32 xt
    gemm_mma<2,0><<<dim3(CC/128, (MT+127)/128), 256, GEMM_SMEM>>>(
        pjh, wtf, t_fc_b, xt, nullptr, nullptr, x, MT, CC, CC);

    // 6. spatial gather + LN1 -> hi/lo
    ln_kernel<<<MS, 256>>>(x, xt, ln1_g, ln1_b, lnh, lnl, 1);

    // 7. spatial qkv -> hi/lo fp16 (attention internals need hi/lo)
    gemm_mma<0,1><<<dim3(C3/128, (MS+127)/128), 256, GEMM_SMEM>>>(
        lnh, wsq, s_qkv_b, nullptr, qsh, qsl, nullptr, MS, C3, CC);

    // 8-10. spatial attention (tensor cores, fused scores+softmax, 3-chain)
    attn_scores_softmax<<<dim3(2, ZB), 256, FSC_SMEM>>>(qsh, qsl, ph, pl);
    transpose_v<<<ZB, 256>>>(qsh, qsl, vth, vtl);
    attn_pv_mma<<<dim3(2, ZB), 256, PV_SMEM>>>(ph, pl, vth, vtl, ath, atl);

    // 11. spatial proj -> fp32
    gemm_mma<0,0><<<dim3(CC/128, (MS+127)/128), 256, GEMM_SMEM>>>(
        ath, wsp, s_proj_b, proj, nullptr, nullptr, nullptr, MS, CC, CC);

    // 12+13. assemble x_new into d_out AND LN2 -> hi/lo (fused)
    assemble_ln<<<MX, 256>>>(x, xt, proj, ln2_g, ln2_b, out, lnh, lnl);

    // 14. fc1 + gelu -> hi/lo
    gemm_mma<1,1><<<dim3(HIDDEN/128, (MX+127)/128), 256, GEMM_SMEM>>>(
        lnh, wf1, fc1_b, nullptr, f1h, f1l, nullptr, MX, HIDDEN, CC);

    // 15. fc2 + in-place residual on d_out
    gemm_mma<3,0><<<dim3(CC/128, (MX+127)/128), 256, GEMM_SMEM>>>(
        f1h, wf2, fc2_b, out, nullptr, nullptr, nullptr, MX, CC, HIDDEN);
}

// round 12
// speedup vs baseline: 2.5683x; 1.2144x over previous
#include <cuda_runtime.h>
#include <cuda_fp16.h>
#include <math.h>
#include <stdint.h>

// ---------------------------------------------------------------------------
// Problem constants
// ---------------------------------------------------------------------------
#define CC     768
#define C3     2304
#define NH     12
#define HD     64
#define HIDDEN 3072
#define TT     8
#define HW     196
#define BB     4
#define NTOK   1569
#define MT     6272
#define MS     6304
#define MX     6276
#define SL     197
#define SB     32
#define ZB     (SB*NH)
#define SL2    (SL*SL)
#define KP     224          // padded K for P/Vt (7 * 32)

// ---------------------------------------------------------------------------
// Static device scratch
// ---------------------------------------------------------------------------
__device__ float g_qkv [(size_t)MT * C3];      // fp32 qkv (temporal attention)
__device__ float g_xt  [(size_t)MT * CC];
__device__ float g_proj[(size_t)MS * CC];

// fp16 activations (hi only — big GEMMs are 1-chain)
__device__ __half g_ln_h[(size_t)MS * CC];
__device__ __half g_at_h[(size_t)MS * CC];
__device__ __half g_pj_h[(size_t)MT * CC];
__device__ __half g_f1_h[(size_t)MX * HIDDEN];
__device__ __half g_qs_h[(size_t)MS * C3];
__device__ __half g_p_h [(size_t)ZB * SL * KP];
__device__ __half g_vt_h[(size_t)ZB * HD * KP];

// weights: single fp16
__device__ __half g_wtq[(size_t)C3 * CC];
__device__ __half g_wtp[(size_t)CC * CC];
__device__ __half g_wtf[(size_t)CC * CC];
__device__ __half g_wsq[(size_t)C3 * CC];
__device__ __half g_wsp[(size_t)CC * CC];
__device__ __half g_wf1[(size_t)HIDDEN * CC];
__device__ __half g_wf2[(size_t)CC * HIDDEN];

// ---------------------------------------------------------------------------
// Helpers
// ---------------------------------------------------------------------------
__device__ __forceinline__ float gelu_exact(float v) {
    return 0.5f * v * (1.0f + erff(v * 0.7071067811865475f));
}

__device__ __forceinline__ uint32_t smem_u32(const void* p) {
    uint32_t a;
    asm("{ .reg .u64 t; cvta.to.shared.u64 t, %1; cvt.u32.u64 %0, t; }" : "=r"(a) : "l"(p));
    return a;
}

__device__ __forceinline__ void cpasync16(uint32_t dst, const void* src) {
    asm volatile("cp.async.cg.shared.global [%0], [%1], 16;" :: "r"(dst), "l"(src));
}
#define CP_COMMIT() asm volatile("cp.async.commit_group;" ::: "memory")
#define CP_WAIT0()  asm volatile("cp.async.wait_group 0;" ::: "memory")
#define CP_WAIT1()  asm volatile("cp.async.wait_group 1;" ::: "memory")

__device__ __forceinline__ void ldm4(uint32_t* r, uint32_t addr) {
    asm volatile("ldmatrix.sync.aligned.m8n8.x4.shared.b16 {%0,%1,%2,%3}, [%4];"
                 : "=r"(r[0]), "=r"(r[1]), "=r"(r[2]), "=r"(r[3]) : "r"(addr));
}

__device__ __forceinline__ void mma16816(float* d, const uint32_t* a, const uint32_t* b) {
    asm volatile(
        "mma.sync.aligned.m16n8k16.row.col.f32.f16.f16.f32 "
        "{%0,%1,%2,%3}, {%4,%5,%6,%7}, {%8,%9}, {%0,%1,%2,%3};"
        : "+f"(d[0]), "+f"(d[1]), "+f"(d[2]), "+f"(d[3])
        : "r"(a[0]), "r"(a[1]), "r"(a[2]), "r"(a[3]), "r"(b[0]), "r"(b[1]));
}

// ---------------------------------------------------------------------------
// Single-chain fp16 HMMA NT GEMM: C = A(fp16) * B(fp16)^T + bias.
// CTA 128x128, 8 warps (64Mx32N), k-step 32, 3-stage cp.async (wait_group 1),
// 2 CTAs/SM.
//   EPI 0: +bias   1: gelu(+bias)   2: +bias+resid(skip-cls)   3: +bias+C
//   OUT 0: fp32 C  1: fp16 (Ch)
// ---------------------------------------------------------------------------
#define STG    20480u
#define OFF_A  0u
#define OFF_B  10240u
#define GEMM_SMEM (3 * STG)

template<int EPI, int OUT>
__global__ void __launch_bounds__(256, 2)
gemm_mma(const __half* __restrict__ Ahg,
         const __half* __restrict__ Bg,
         const float* __restrict__ bias,
         float* __restrict__ C,
         __half* __restrict__ Ch,
         const float* __restrict__ resid,
         int M, int N, int K)
{
    extern __shared__ char smem[];
    const uint32_t sb = smem_u32(smem);

    const int tid  = threadIdx.x;
    const int wid  = tid >> 5;
    const int lane = tid & 31;
    const int row0 = blockIdx.y * 128;
    const int col0 = blockIdx.x * 128;
    const int KT   = K >> 5;

    float acc[4][4][4];
    #pragma unroll
    for (int a = 0; a < 4; a++)
        #pragma unroll
        for (int b = 0; b < 4; b++)
            #pragma unroll
            for (int c = 0; c < 4; c++) acc[a][b][c] = 0.0f;

    auto load_stage = [&](int kt, int buf) {
        const int kw = kt * 32;
        const uint32_t dstb = sb + buf * STG;
        #pragma unroll
        for (int q = 0; q < 2; q++) {
            int cid = q * 256 + tid;
            int row = cid >> 2, ch = cid & 3;
            int ar  = min(row0 + row, M - 1);
            cpasync16(dstb + OFF_A + row * 80u + ch * 16u,
                      Ahg + (size_t)ar * K + kw + ch * 8);
        }
        #pragma unroll
        for (int q = 0; q < 2; q++) {
            int cid = q * 256 + tid;
            int row = cid >> 2, ch = cid & 3;
            cpasync16(dstb + OFF_B + row * 80u + ch * 16u,
                      Bg + (size_t)(col0 + row) * K + kw + ch * 8);
        }
        CP_COMMIT();
    };

    load_stage(0, 0);
    load_stage(1, 1);
    CP_WAIT1();
    __syncthreads();

    const int m0w = (wid & 1) * 64;
    const int n0w = (wid >> 1) * 32;
    const uint32_t a_off = (uint32_t)(m0w + (lane & 15)) * 80u + (uint32_t)((lane >> 4) << 4);
    const uint32_t b_off = (uint32_t)(n0w + (lane & 7) + ((lane >> 4) << 3)) * 80u
                         + (uint32_t)(((lane >> 3) & 1) << 4);

    for (int kt = 0; kt < KT; kt++) {
        const int buf = kt % 3;
        const uint32_t bb = sb + buf * STG;
        #pragma unroll
        for (int s = 0; s < 2; s++) {
            uint32_t ah[4][4], bh[4][2];
            #pragma unroll
            for (int mi = 0; mi < 4; mi++)
                ldm4(ah[mi], bb + OFF_A + a_off + mi * 1280u + s * 32u);
            #pragma unroll
            for (int nj = 0; nj < 2; nj++) {
                uint32_t t[4];
                ldm4(t, bb + OFF_B + b_off + nj * 1280u + s * 32u);
                bh[nj*2][0] = t[0]; bh[nj*2][1] = t[1];
                bh[nj*2+1][0] = t[2]; bh[nj*2+1][1] = t[3];
            }
            #pragma unroll
            for (int mi = 0; mi < 4; mi++)
                #pragma unroll
                for (int nj = 0; nj < 4; nj++)
                    mma16816(acc[mi][nj], ah[mi], bh[nj]);
        }
        if (kt + 2 < KT) {
            load_stage(kt + 2, (kt + 2) % 3);
            CP_WAIT1();
        } else {
            CP_WAIT0();
        }
        __syncthreads();
    }

    #pragma unroll
    for (int mi = 0; mi < 4; mi++) {
        const int rbase = row0 + m0w + mi * 16 + (lane >> 2);
        #pragma unroll
        for (int half = 0; half < 2; half++) {
            const int m = rbase + half * 8;
            if (m >= M) continue;
            #pragma unroll
            for (int nj = 0; nj < 4; nj++) {
                const int n = col0 + n0w + nj * 8 + (lane & 3) * 2;
                float v0 = acc[mi][nj][half * 2 + 0] + bias[n];
                float v1 = acc[mi][nj][half * 2 + 1] + bias[n + 1];
                if (EPI == 1) { v0 = gelu_exact(v0); v1 = gelu_exact(v1); }
                if (EPI == 2) {
                    const float* rs = resid + (size_t)(m + m / 1568 + 1) * CC + n;
                    v0 += rs[0]; v1 += rs[1];
                }
                if (OUT == 0) {
                    float* cp = C + (size_t)m * N + n;
                    if (EPI == 3) {
                        float2 old = *(const float2*)cp;
                        v0 += old.x; v1 += old.y;
                    }
                    float2 o = {v0, v1};
                    *(float2*)cp = o;
                } else {
                    *(__half2*)(Ch + (size_t)m * N + n) =
                        __halves2half2(__float2half_rn(v0), __float2half_rn(v1));
                }
            }
        }
    }
}

// ---------------------------------------------------------------------------
// FUSED spatial scores + softmax (1-chain fp16). Per (row-block, z):
// S = Q*K^T*0.125 for 128 rows x 224 padded cols via HMMA, row softmax
// in registers (quad shuffles), writes P fp16, tail zeroed.
// smem: 2 k-stages x (A 128x80 + B 224x80) = 2 x 28160 = 56320 B.
// ---------------------------------------------------------------------------
#define FSTG     28160u
#define FOFF_A   0u
#define FOFF_B   10240u
#define FSC_SMEM (2 * FSTG)

__global__ void __launch_bounds__(256)
attn_scores_softmax(const __half* __restrict__ qh, __half* __restrict__ ph)
{
    extern __shared__ char smem[];
    const uint32_t sb = smem_u32(smem);

    const int z = blockIdx.y;
    const int s = z / NH, h = z % NH;
    const size_t base  = (size_t)(s * SL) * C3 + h * HD;
    const size_t pbase = (size_t)z * SL * KP;

    const int tid  = threadIdx.x;
    const int wid  = tid >> 5;
    const int lane = tid & 31;
    const int row0 = blockIdx.x * 128;

    #pragma unroll
    for (int kt = 0; kt < 2; kt++) {
        const int kw = kt * 32;
        const uint32_t dstb = sb + kt * FSTG;
        // A (Q): 128 rows x 4 chunks = 512
        #pragma unroll
        for (int q = 0; q < 2; q++) {
            int cid = q * 256 + tid;
            int row = cid >> 2, ch = cid & 3;
            int gr  = min(row0 + row, SL - 1);
            cpasync16(dstb + FOFF_A + row * 80u + ch * 16u,
                      qh + base + (size_t)gr * C3 + kw + ch * 8);
        }
        // B (K): 224 rows x 4 chunks = 896
        #pragma unroll
        for (int q = 0; q < 4; q++) {
            int cid = q * 256 + tid;
            if (cid < 896) {
                int row = cid >> 2, ch = cid & 3;
                int gr  = min(row, SL - 1);
                cpasync16(dstb + FOFF_B + row * 80u + ch * 16u,
                          qh + base + (size_t)gr * C3 + CC + kw + ch * 8);
            }
        }
        CP_COMMIT();
    }
    CP_WAIT0();
    __syncthreads();

    const int m0w = wid * 16;
    const uint32_t a_off = (uint32_t)(m0w + (lane & 15)) * 80u + (uint32_t)((lane >> 4) << 4);
    const uint32_t b_off = (uint32_t)((lane & 7) + ((lane >> 4) << 3)) * 80u
                         + (uint32_t)(((lane >> 3) & 1) << 4);

    float acc[28][4];
    #pragma unroll
    for (int t = 0; t < 28; t++)
        #pragma unroll
        for (int c = 0; c < 4; c++) acc[t][c] = 0.0f;

    #pragma unroll
    for (int kt = 0; kt < 2; kt++) {
        const uint32_t bb = sb + kt * FSTG;
        #pragma unroll
        for (int s2 = 0; s2 < 2; s2++) {
            uint32_t ah[4];
            ldm4(ah, bb + FOFF_A + a_off + s2 * 32u);
            #pragma unroll
            for (int njq = 0; njq < 14; njq++) {
                uint32_t th[4];
                ldm4(th, bb + FOFF_B + b_off + njq * 1280u + s2 * 32u);
                uint32_t b0[2] = {th[0], th[1]}, b1[2] = {th[2], th[3]};
                mma16816(acc[njq*2],   ah, b0);
                mma16816(acc[njq*2+1], ah, b1);
            }
        }
    }

    const int ncol0 = (lane & 3) * 2;
    #pragma unroll
    for (int half = 0; half < 2; half++) {
        const int row = row0 + m0w + (lane >> 2) + half * 8;
        float mx = -1e30f;
        #pragma unroll
        for (int t = 0; t < 28; t++) {
            int n = t * 8 + ncol0;
            float v0 = acc[t][half*2+0] * 0.125f;
            float v1 = acc[t][half*2+1] * 0.125f;
            acc[t][half*2+0] = (n < SL)     ? v0 : -1e30f;
            acc[t][half*2+1] = (n + 1 < SL) ? v1 : -1e30f;
            mx = fmaxf(mx, acc[t][half*2+0]);
            mx = fmaxf(mx, acc[t][half*2+1]);
        }
        mx = fmaxf(mx, __shfl_xor_sync(0xffffffffu, mx, 1));
        mx = fmaxf(mx, __shfl_xor_sync(0xffffffffu, mx, 2));
        float sum = 0.0f;
        #pragma unroll
        for (int t = 0; t < 28; t++) {
            float e0 = expf(acc[t][half*2+0] - mx);
            float e1 = expf(acc[t][half*2+1] - mx);
            int n = t * 8 + ncol0;
            e0 = (n < SL)     ? e0 : 0.0f;
            e1 = (n + 1 < SL) ? e1 : 0.0f;
            acc[t][half*2+0] = e0;
            acc[t][half*2+1] = e1;
            sum += e0 + e1;
        }
        sum += __shfl_xor_sync(0xffffffffu, sum, 1);
        sum += __shfl_xor_sync(0xffffffffu, sum, 2);
        float inv = 1.0f / sum;
        if (row < SL) {
            size_t ob = pbase + (size_t)row * KP;
            #pragma unroll
            for (int t = 0; t < 28; t++) {
                int n = t * 8 + ncol0;
                *(__half2*)(ph + ob + n) = __halves2half2(
                    __float2half_rn(acc[t][half*2+0] * inv),
                    __float2half_rn(acc[t][half*2+1] * inv));
            }
        }
    }
}

// ---------------------------------------------------------------------------
// Batched PV via HMMA (1-chain fp16). Per z: O = P(197x224) * Vt(64x224)^T.
// CTA 128(M)x64(N), 8 warps 32x32, double-buffered.
// smem/stage: A 128x80 + B 64x80 = 15360 B.
// ---------------------------------------------------------------------------
#define PSTG    15360u
#define POFF_A  0u
#define POFF_B  10240u
#define PV_SMEM (2 * PSTG)

__global__ void __launch_bounds__(256)
attn_pv_mma(const __half* __restrict__ ph,
            const __half* __restrict__ vth,
            __half* __restrict__ oh)
{
    extern __shared__ char smem[];
    const uint32_t sb = smem_u32(smem);

    const int z = blockIdx.y;
    const int s = z / NH, h = z % NH;
    const size_t pbase = (size_t)z * SL * KP;
    const size_t vbase = (size_t)z * HD * KP;

    const int tid  = threadIdx.x;
    const int wid  = tid >> 5;
    const int lane = tid & 31;
    const int row0 = blockIdx.x * 128;

    float acc[2][4][4];
    #pragma unroll
    for (int a = 0; a < 2; a++)
        #pragma unroll
        for (int b = 0; b < 4; b++)
            #pragma unroll
            for (int c = 0; c < 4; c++) acc[a][b][c] = 0.0f;

    auto load_stage = [&](int kt, int buf) {
        const int kw = kt * 32;
        const uint32_t dstb = sb + buf * PSTG;
        #pragma unroll
        for (int q = 0; q < 2; q++) {
            int cid = q * 256 + tid;
            int row = cid >> 2, ch = cid & 3;
            int gr  = min(row0 + row, SL - 1);
            cpasync16(dstb + POFF_A + row * 80u + ch * 16u,
                      ph + pbase + (size_t)gr * KP + kw + ch * 8);
        }
        {
            int row = tid >> 2, ch = tid & 3;   // 256 = 64 rows x 4 chunks
            cpasync16(dstb + POFF_B + row * 80u + ch * 16u,
                      vth + vbase + (size_t)row * KP + kw + ch * 8);
        }
        CP_COMMIT();
    };

    load_stage(0, 0);
    CP_WAIT0();
    __syncthreads();

    const int m0w = (wid & 3) * 32;
    const int n0w = (wid >> 2) * 32;
    const uint32_t a_off = (uint32_t)(m0w + (lane & 15)) * 80u + (uint32_t)((lane >> 4) << 4);
    const uint32_t b_off = (uint32_t)(n0w + (lane & 7) + ((lane >> 4) << 3)) * 80u
                         + (uint32_t)(((lane >> 3) & 1) << 4);

    for (int kt = 0; kt < KP / 32; kt++) {
        const int buf = kt & 1;
        if (kt + 1 < KP / 32) load_stage(kt + 1, buf ^ 1);

        const uint32_t bb = sb + buf * PSTG;
        #pragma unroll
        for (int s2 = 0; s2 < 2; s2++) {
            uint32_t ah[2][4], bh[4][2];
            #pragma unroll
            for (int mi = 0; mi < 2; mi++)
                ldm4(ah[mi], bb + POFF_A + a_off + mi * 1280u + s2 * 32u);
            #pragma unroll
            for (int nj = 0; nj < 2; nj++) {
                uint32_t t[4];
                ldm4(t, bb + POFF_B + b_off + nj * 1280u + s2 * 32u);
                bh[nj*2][0] = t[0]; bh[nj*2][1] = t[1];
                bh[nj*2+1][0] = t[2]; bh[nj*2+1][1] = t[3];
            }
            #pragma unroll
            for (int mi = 0; mi < 2; mi++)
                #pragma unroll
                for (int nj = 0; nj < 4; nj++)
                    mma16816(acc[mi][nj], ah[mi], bh[nj]);
        }
        CP_WAIT0();
        __syncthreads();
    }

    #pragma unroll
    for (int mi = 0; mi < 2; mi++) {
        const int rbase = row0 + m0w + mi * 16 + (lane >> 2);
        #pragma unroll
        for (int half = 0; half < 2; half++) {
            const int m = rbase + half * 8;
            if (m >= SL) continue;
            size_t ob = (size_t)(s * SL + m) * CC + h * HD;
            #pragma unroll
            for (int nj = 0; nj < 4; nj++) {
                const int n = n0w + nj * 8 + (lane & 3) * 2;
                *(__half2*)(oh + ob + n) = __halves2half2(
                    __float2half_rn(acc[mi][nj][half * 2 + 0]),
                    __float2half_rn(acc[mi][nj][half * 2 + 1]));
            }
        }
    }
}

// ---------------------------------------------------------------------------
// V transpose: per z, Vt[d][t] = V[t][d], padded t->224 with zeros.
// ---------------------------------------------------------------------------
__global__ void transpose_v(const __half* __restrict__ qh, __half* __restrict__ vth)
{
    int z = blockIdx.x;
    int s = z / NH, h = z % NH;
    size_t vbase = (size_t)(s * SL) * C3 + 2 * CC + h * HD;
    size_t obase = (size_t)z * HD * KP;
    __shared__ __half shh[32][66];
    int tid = threadIdx.x;

    for (int t0 = 0; t0 < KP; t0 += 32) {
        #pragma unroll
        for (int i = 0; i < 8; i++) {
            int e = i * 256 + tid;
            int t = e >> 6, d = e & 63;
            int gt = t0 + t;
            shh[t][d] = (gt < SL) ? qh[vbase + (size_t)gt * C3 + d]
                                  : __float2half(0.0f);
        }
        __syncthreads();
        #pragma unroll
        for (int i = 0; i < 8; i++) {
            int e = i * 256 + tid;
            int d = e >> 5, t = e & 31;
            vth[obase + (size_t)d * KP + t0 + t] = shh[t][d];
        }
        __syncthreads();
    }
}

// ---------------------------------------------------------------------------
// Fused weight conversion: all 7 weights -> single fp16, one launch.
// ---------------------------------------------------------------------------
struct WSegs {
    const float4* src[7];
    __half2*      dh[7];
    int           n4[7];
};

__global__ void conv_all(WSegs w, int total4)
{
    int i = blockIdx.x * blockDim.x + threadIdx.x;
    if (i >= total4) return;
    int rem = i;
    #pragma unroll
    for (int s = 0; s < 7; s++) {
        if (rem < w.n4[s]) {
            float4 v = w.src[s][rem];
            w.dh[s][rem * 2 + 0] = __halves2half2(__float2half_rn(v.x), __float2half_rn(v.y));
            w.dh[s][rem * 2 + 1] = __halves2half2(__float2half_rn(v.z), __float2half_rn(v.w));
            return;
        }
        rem -= w.n4[s];
    }
}

// ---------------------------------------------------------------------------
// LN core: values v0,v1,v2 per thread. Writes fp16.
// ---------------------------------------------------------------------------
__device__ __forceinline__ void ln_core(float v0, float v1, float v2,
                                        const float* __restrict__ g,
                                        const float* __restrict__ bta,
                                        __half* __restrict__ oh, size_t ob)
{
    int tid = threadIdx.x;
    int lane = tid & 31, wid = tid >> 5;
    __shared__ float sh[32];
    float s = v0 + v1 + v2;
    #pragma unroll
    for (int o = 16; o; o >>= 1) s += __shfl_xor_sync(0xffffffffu, s, o);
    if (lane == 0) sh[wid] = s;
    __syncthreads();
    if (wid == 0) {
        float t2 = (lane < 8) ? sh[lane] : 0.0f;
        #pragma unroll
        for (int o = 4; o; o >>= 1) t2 += __shfl_xor_sync(0xffffffffu, t2, o);
        if (lane == 0) sh[0] = t2;
    }
    __syncthreads();
    float mean = sh[0] * (1.0f / 768.0f);
    __syncthreads();
    float d0 = v0 - mean, d1 = v1 - mean, d2 = v2 - mean;
    float s2 = d0 * d0 + d1 * d1 + d2 * d2;
    #pragma unroll
    for (int o = 16; o; o >>= 1) s2 += __shfl_xor_sync(0xffffffffu, s2, o);
    if (lane == 0) sh[wid] = s2;
    __syncthreads();
    if (wid == 0) {
        float t2 = (lane < 8) ? sh[lane] : 0.0f;
        #pragma unroll
        for (int o = 4; o; o >>= 1) t2 += __shfl_xor_sync(0xffffffffu, t2, o);
        if (lane == 0) sh[0] = t2;
    }
    __syncthreads();
    float inv = rsqrtf(sh[0] * (1.0f / 768.0f) + 1e-5f);
    #pragma unroll
    for (int p = 0; p < 3; p++) {
        float d = (p == 0) ? d0 : (p == 1) ? d1 : d2;
        int c = tid + p * 256;
        oh[ob + c] = __float2half_rn(d * inv * g[c] + bta[c]);
    }
}

// ---------------------------------------------------------------------------
// LayerNorm (modes 0/1 gather). One block/row. Writes fp16.
// ---------------------------------------------------------------------------
__global__ void ln_kernel(const float* __restrict__ src0,
                          const float* __restrict__ xt,
                          const float* __restrict__ g,
                          const float* __restrict__ bta,
                          __half* __restrict__ oh, int mode)
{
    int m = blockIdx.x;
    const float* src;
    if (mode == 0) {
        src = src0 + (size_t)(m + m / 1568 + 1) * CC;
    } else {
        int sb = m / SL, p = m % SL;
        int b = sb >> 3, t = sb & 7;
        if (p == 0) src = src0 + (size_t)b * NTOK * CC;
        else        src = xt + ((size_t)(b * HW + (p - 1)) * TT + t) * CC;
    }
    int tid = threadIdx.x;
    float v0 = src[tid], v1 = src[tid + 256], v2 = src[tid + 512];
    ln_core(v0, v1, v2, g, bta, oh, (size_t)m * CC);
}

// ---------------------------------------------------------------------------
// Fused assemble + LN2.
// ---------------------------------------------------------------------------
__global__ void assemble_ln(const float* __restrict__ x, const float* __restrict__ xt,
                            const float* __restrict__ ps,
                            const float* __restrict__ g, const float* __restrict__ bta,
                            float* __restrict__ out,
                            __half* __restrict__ oh)
{
    int row = blockIdx.x;
    int b = row / NTOK, n = row % NTOK;
    size_t orow = (size_t)row * CC;
    int tid = threadIdx.x;
    float v[3];
    if (n == 0) {
        #pragma unroll
        for (int p = 0; p < 3; p++) {
            int c = tid + p * 256;
            float acc = 0.0f;
            #pragma unroll
            for (int t = 0; t < TT; t++)
                acc += ps[((size_t)(b * TT + t) * SL) * CC + c];
            v[p] = x[orow + c] + acc * 0.125f;
        }
    } else {
        int r = n - 1, hw = r >> 3, t = r & 7;
        size_t xtrow = ((size_t)b * 1568 + r) * CC;
        size_t psrow = ((size_t)((b * TT + t) * SL + 1 + hw)) * CC;
        #pragma unroll
        for (int p = 0; p < 3; p++) {
            int c = tid + p * 256;
            v[p] = xt[xtrow + c] + ps[psrow + c];
        }
    }
    #pragma unroll
    for (int p = 0; p < 3; p++)
        out[orow + tid + p * 256] = v[p];
    ln_core(v[0], v[1], v[2], g, bta, oh, orow);
}

// ---------------------------------------------------------------------------
// Temporal attention: fused per (seq, head), float4 loads, fp16 hi output.
// ---------------------------------------------------------------------------
__global__ void temporal_attn(const float* __restrict__ qkv,
                              __half* __restrict__ oh)
{
    int seq = blockIdx.x, h = blockIdx.y;
    __shared__ float q[TT][68], k[TT][68], v[TT][68];
    __shared__ float p[TT][TT];
    int tid = threadIdx.x;
    size_t base = (size_t)(seq * TT) * C3 + h * HD;

    #pragma unroll
    for (int arr = 0; arr < 3; arr++) {
        float (*dst)[68] = (arr == 0) ? q : (arr == 1) ? k : v;
        #pragma unroll
        for (int it = 0; it < 2; it++) {
            int e = it * 64 + tid;          // 0..127 -> 8 t x 16 d4
            int t = e >> 4, d4 = (e & 15) << 2;
            float4 val = *(const float4*)(qkv + base + (size_t)t * C3 + arr * CC + d4);
            dst[t][d4]     = val.x;
            dst[t][d4 + 1] = val.y;
            dst[t][d4 + 2] = val.z;
            dst[t][d4 + 3] = val.w;
        }
    }
    __syncthreads();
    int i = tid >> 3, j = tid & 7;
    float s = 0.0f;
    #pragma unroll
    for (int d = 0; d < HD; d++) s = fmaf(q[i][d], k[j][d], s);
    p[i][j] = s * 0.125f;
    __syncthreads();
    if (tid < TT) {
        float mx = -1e30f;
        #pragma unroll
        for (int jj = 0; jj < TT; jj++) mx = fmaxf(mx, p[tid][jj]);
        float sum = 0.0f;
        #pragma unroll
        for (int jj = 0; jj < TT; jj++) {
            float e = expf(p[tid][jj] - mx);
            p[tid][jj] = e; sum += e;
        }
        float invs = 1.0f / sum;
        #pragma unroll
        for (int jj = 0; jj < TT; jj++) p[tid][jj] *= invs;
    }
    __syncthreads();
    #pragma unroll
    for (int t = 0; t < TT; t++) {
        float o = 0.0f;
        #pragma unroll
        for (int jj = 0; jj < TT; jj++) o = fmaf(p[t][jj], v[jj][tid], o);
        oh[(size_t)(seq * TT + t) * CC + h * HD + tid] = __float2half_rn(o);
    }
}

// ---------------------------------------------------------------------------
// Host launch
// ---------------------------------------------------------------------------
extern "C" void kernel_launch(void* const* d_in, const int* in_sizes, int n_in,
                              void* d_out, int out_size)
{
    const float* x        = (const float*)d_in[0];
    const float* ln_t_g   = (const float*)d_in[1];
    const float* ln_t_b   = (const float*)d_in[2];
    const float* t_qkv_w  = (const float*)d_in[3];
    const float* t_qkv_b  = (const float*)d_in[4];
    const float* t_proj_w = (const float*)d_in[5];
    const float* t_proj_b = (const float*)d_in[6];
    const float* t_fc_w   = (const float*)d_in[7];
    const float* t_fc_b   = (const float*)d_in[8];
    const float* ln1_g    = (const float*)d_in[9];
    const float* ln1_b    = (const float*)d_in[10];
    const float* s_qkv_w  = (const float*)d_in[11];
    const float* s_qkv_b  = (const float*)d_in[12];
    const float* s_proj_w = (const float*)d_in[13];
    const float* s_proj_b = (const float*)d_in[14];
    const float* ln2_g    = (const float*)d_in[15];
    const float* ln2_b    = (const float*)d_in[16];
    const float* fc1_w    = (const float*)d_in[17];
    const float* fc1_b    = (const float*)d_in[18];
    const float* fc2_w    = (const float*)d_in[19];
    const float* fc2_b    = (const float*)d_in[20];
    float* out = (float*)d_out;

    float *qkv, *xt, *proj;
    __half *lnh, *ath, *pjh, *f1h, *qsh, *ph, *vth;
    cudaGetSymbolAddress((void**)&qkv,  g_qkv);
    cudaGetSymbolAddress((void**)&xt,   g_xt);
    cudaGetSymbolAddress((void**)&proj, g_proj);
    cudaGetSymbolAddress((void**)&lnh,  g_ln_h);
    cudaGetSymbolAddress((void**)&ath,  g_at_h);
    cudaGetSymbolAddress((void**)&pjh,  g_pj_h);
    cudaGetSymbolAddress((void**)&f1h,  g_f1_h);
    cudaGetSymbolAddress((void**)&qsh,  g_qs_h);
    cudaGetSymbolAddress((void**)&ph,   g_p_h);
    cudaGetSymbolAddress((void**)&vth,  g_vt_h);

    __half *wtq, *wtp, *wtf, *wsq, *wsp, *wf1, *wf2;
    cudaGetSymbolAddress((void**)&wtq, g_wtq);
    cudaGetSymbolAddress((void**)&wtp, g_wtp);
    cudaGetSymbolAddress((void**)&wtf, g_wtf);
    cudaGetSymbolAddress((void**)&wsq, g_wsq);
    cudaGetSymbolAddress((void**)&wsp, g_wsp);
    cudaGetSymbolAddress((void**)&wf1, g_wf1);
    cudaGetSymbolAddress((void**)&wf2, g_wf2);

    cudaFuncSetAttribute(gemm_mma<0,0>, cudaFuncAttributeMaxDynamicSharedMemorySize, GEMM_SMEM);
    cudaFuncSetAttribute(gemm_mma<0,1>, cudaFuncAttributeMaxDynamicSharedMemorySize, GEMM_SMEM);
    cudaFuncSetAttribute(gemm_mma<1,1>, cudaFuncAttributeMaxDynamicSharedMemorySize, GEMM_SMEM);
    cudaFuncSetAttribute(gemm_mma<2,0>, cudaFuncAttributeMaxDynamicSharedMemorySize, GEMM_SMEM);
    cudaFuncSetAttribute(gemm_mma<3,0>, cudaFuncAttributeMaxDynamicSharedMemorySize, GEMM_SMEM);
    cudaFuncSetAttribute(attn_scores_softmax, cudaFuncAttributeMaxDynamicSharedMemorySize, FSC_SMEM);
    cudaFuncSetAttribute(attn_pv_mma, cudaFuncAttributeMaxDynamicSharedMemorySize, PV_SMEM);

    // 0. convert all weights in one launch (single fp16)
    {
        WSegs w;
        w.src[0] = (const float4*)t_qkv_w;  w.dh[0] = (__half2*)wtq; w.n4[0] = C3 * CC / 4;
        w.src[1] = (const float4*)t_proj_w; w.dh[1] = (__half2*)wtp; w.n4[1] = CC * CC / 4;
        w.src[2] = (const float4*)t_fc_w;   w.dh[2] = (__half2*)wtf; w.n4[2] = CC * CC / 4;
        w.src[3] = (const float4*)s_qkv_w;  w.dh[3] = (__half2*)wsq; w.n4[3] = C3 * CC / 4;
        w.src[4] = (const float4*)s_proj_w; w.dh[4] = (__half2*)wsp; w.n4[4] = CC * CC / 4;
        w.src[5] = (const float4*)fc1_w;    w.dh[5] = (__half2*)wf1; w.n4[5] = HIDDEN * CC / 4;
        w.src[6] = (const float4*)fc2_w;    w.dh[6] = (__half2*)wf2; w.n4[6] = CC * HIDDEN / 4;
        int total4 = 0;
        for (int i = 0; i < 7; i++) total4 += w.n4[i];
        conv_all<<<(total4 + 255) / 256, 256>>>(w, total4);
    }

    // 1. temporal LN (skip cls) -> fp16
    ln_kernel<<<MT, 256>>>(x, nullptr, ln_t_g, ln_t_b, lnh, 0);

    // 2. temporal qkv -> fp32
    gemm_mma<0,0><<<dim3(C3/128, (MT+127)/128), 256, GEMM_SMEM>>>(
        lnh, wtq, t_qkv_b, qkv, nullptr, nullptr, MT, C3, CC);

    // 3. temporal attention -> fp16
    temporal_attn<<<dim3(BB * HW, NH), 64>>>(qkv, ath);

    // 4. temporal proj -> fp16
    gemm_mma<0,1><<<dim3(CC/128, (MT+127)/128), 256, GEMM_SMEM>>>(
        ath, wtp, t_proj_b, nullptr, pjh, nullptr, MT, CC, CC);

    // 5. t_fc + residual from x (skip-cls) -> fp32 xt
    gemm_mma<2,0><<<dim3(CC/128, (MT+127)/128), 256, GEMM_SMEM>>>(
        pjh, wtf, t_fc_b, xt, nullptr, x, MT, CC, CC);

    // 6. spatial gather + LN1 -> fp16
    ln_kernel<<<MS, 256>>>(x, xt, ln1_g, ln1_b, lnh, 1);

    // 7. spatial qkv -> fp16
    gemm_mma<0,1><<<dim3(C3/128, (MS+127)/128), 256, GEMM_SMEM>>>(
        lnh, wsq, s_qkv_b, nullptr, qsh, nullptr, MS, C3, CC);

    // 8-10. spatial attention (tensor cores, 1-chain fp16)
    attn_scores_softmax<<<dim3(2, ZB), 256, FSC_SMEM>>>(qsh, ph);
    transpose_v<<<ZB, 256>>>(qsh, vth);
    attn_pv_mma<<<dim3(2, ZB), 256, PV_SMEM>>>(ph, vth, ath);

    // 11. spatial proj -> fp32
    gemm_mma<0,0><<<dim3(CC/128, (MS+127)/128), 256, GEMM_SMEM>>>(
        ath, wsp, s_proj_b, proj, nullptr, nullptr, MS, CC, CC);

    // 12+13. assemble x_new into d_out AND LN2 -> fp16 (fused)
    assemble_ln<<<MX, 256>>>(x, xt, proj, ln2_g, ln2_b, out, lnh);

    // 14. fc1 + gelu -> fp16
    gemm_mma<1,1><<<dim3(HIDDEN/128, (MX+127)/128), 256, GEMM_SMEM>>>(
        lnh, wf1, fc1_b, nullptr, f1h, nullptr, MX, HIDDEN, CC);

    // 15. fc2 + in-place residual on d_out
    gemm_mma<3,0><<<dim3(CC/128, (MX+127)/128), 256, GEMM_SMEM>>>(
        f1h, wf2, fc2_b, out, nullptr, nullptr, MX, CC, HIDDEN);
}